// round 1
// baseline (speedup 1.0000x reference)
#include <cuda_runtime.h>

typedef unsigned long long ull;

#define EPS 1e-5f

// ---------------- scratch (device globals; no cudaMalloc allowed) ----------------
__device__ float g_Wall[768 * 512];     // folded weights: rows 0-127 q, 128-255 k, 256-767 v
__device__ float g_ball[768];           // folded biases
__device__ float g_pos[128 * 1024];     // pos[h*32+d][n]
__device__ float g_qk[16 * 256 * 1024]; // [b][o][n], o<128: q (h*32+d), o in [128,256): k
__device__ float g_vt[16 * 4 * 1024 * 128]; // [b][h][n][c]

// ---------------- f32x2 packed math helpers (Blackwell FFMA2) ----------------
__device__ __forceinline__ ull pack2(float x, float y) {
    ull r; asm("mov.b64 %0, {%1, %2};" : "=l"(r) : "f"(x), "f"(y)); return r;
}
__device__ __forceinline__ float2 unpack2(ull v) {
    float2 r; asm("mov.b64 {%0, %1}, %2;" : "=f"(r.x), "=f"(r.y) : "l"(v)); return r;
}
__device__ __forceinline__ void ffma2(ull& d, ull a, ull b) {
    asm("fma.rn.f32x2 %0, %1, %2, %0;" : "+l"(d) : "l"(a), "l"(b));
}
__device__ __forceinline__ void fmul2(ull& d, ull a) {
    asm("mul.rn.f32x2 %0, %0, %1;" : "+l"(d) : "l"(a));
}

// ---------------- 1) fold BN into conv weights ----------------
__global__ void fold_kernel(
    const float* __restrict__ Wq, const float* __restrict__ bq,
    const float* __restrict__ qg, const float* __restrict__ qb,
    const float* __restrict__ qm, const float* __restrict__ qvv,
    const float* __restrict__ Wk, const float* __restrict__ bk,
    const float* __restrict__ kg, const float* __restrict__ kb,
    const float* __restrict__ km, const float* __restrict__ kvv,
    const float* __restrict__ Wv, const float* __restrict__ bv,
    const float* __restrict__ vg, const float* __restrict__ vb,
    const float* __restrict__ vm, const float* __restrict__ vvv)
{
    int o = blockIdx.x;  // 0..767
    const float* src;
    float s, bias;
    if (o < 128) {
        s = qg[o] * rsqrtf(qvv[o] + EPS);
        bias = (bq[o] - qm[o]) * s + qb[o];
        src = Wq + o * 512;
    } else if (o < 256) {
        int oo = o - 128;
        s = kg[oo] * rsqrtf(kvv[oo] + EPS);
        bias = (bk[oo] - km[oo]) * s + kb[oo];
        src = Wk + oo * 512;
    } else {
        int oo = o - 256;
        s = vg[oo] * rsqrtf(vvv[oo] + EPS);
        bias = (bv[oo] - vm[oo]) * s + vb[oo];
        src = Wv + oo * 512;
    }
    for (int c = threadIdx.x; c < 512; c += blockDim.x)
        g_Wall[o * 512 + c] = src[c] * s;
    if (threadIdx.x == 0) g_ball[o] = bias;
}

// ---------------- 2) pos[h,d,n] = rel_h[h,d,hh] + rel_w[h,d,w], n = w*32+hh ----------------
__global__ void pos_kernel(const float* __restrict__ rel_h, const float* __restrict__ rel_w) {
    int idx = blockIdx.x * blockDim.x + threadIdx.x;
    if (idx >= 128 * 1024) return;
    int hd = idx >> 10;
    int n = idx & 1023;
    int w = n >> 5, hh = n & 31;
    g_pos[idx] = rel_h[hd * 32 + hh] + rel_w[hd * 32 + w];
}

// ---------------- 3) fused QKV projection GEMM: [768,512] x [512,1024] per batch ----------------
__global__ __launch_bounds__(256) void proj_kernel(const float* __restrict__ x) {
    __shared__ float sW[32 * 68]; // [k][r] transposed W tile, pad 4
    __shared__ float sX[32 * 68]; // [k][n] x tile, pad 4
    int b = blockIdx.z;
    int row0 = blockIdx.y * 64;
    int col0 = blockIdx.x * 64;
    int tid = threadIdx.x;
    int ty = tid >> 4, tx = tid & 15;
    int r0 = ty * 4, c0 = tx * 4;
    const float* xb = x + (size_t)b * 512 * 1024;

    ull acc[4][2];
    #pragma unroll
    for (int i = 0; i < 4; i++) { acc[i][0] = 0ull; acc[i][1] = 0ull; }

    for (int kk = 0; kk < 512; kk += 32) {
        #pragma unroll
        for (int it = 0; it < 2; it++) {
            int i = tid + it * 256;          // 0..511 float4s of W
            int r = i >> 3, k4 = i & 7;
            float4 w4 = *(const float4*)&g_Wall[(row0 + r) * 512 + kk + k4 * 4];
            sW[(k4 * 4 + 0) * 68 + r] = w4.x;
            sW[(k4 * 4 + 1) * 68 + r] = w4.y;
            sW[(k4 * 4 + 2) * 68 + r] = w4.z;
            sW[(k4 * 4 + 3) * 68 + r] = w4.w;
        }
        #pragma unroll
        for (int it = 0; it < 2; it++) {
            int i = tid + it * 256;          // 0..511 float4s of x
            int k = i >> 4, n4 = i & 15;
            *(float4*)&sX[k * 68 + n4 * 4] =
                *(const float4*)&xb[(size_t)(kk + k) * 1024 + col0 + n4 * 4];
        }
        __syncthreads();
        #pragma unroll
        for (int k = 0; k < 32; k++) {
            float4 a = *(const float4*)&sW[k * 68 + r0];
            ulonglong2 bb = *(const ulonglong2*)&sX[k * 68 + c0];
            ull a0 = pack2(a.x, a.x);
            ull a1 = pack2(a.y, a.y);
            ull a2 = pack2(a.z, a.z);
            ull a3 = pack2(a.w, a.w);
            ffma2(acc[0][0], a0, bb.x); ffma2(acc[0][1], a0, bb.y);
            ffma2(acc[1][0], a1, bb.x); ffma2(acc[1][1], a1, bb.y);
            ffma2(acc[2][0], a2, bb.x); ffma2(acc[2][1], a2, bb.y);
            ffma2(acc[3][0], a3, bb.x); ffma2(acc[3][1], a3, bb.y);
        }
        __syncthreads();
    }

    #pragma unroll
    for (int i = 0; i < 4; i++) {
        int o = row0 + r0 + i;
        float bias = g_ball[o];
        float2 p01 = unpack2(acc[i][0]);
        float2 p23 = unpack2(acc[i][1]);
        float v0 = p01.x + bias, v1 = p01.y + bias, v2 = p23.x + bias, v3 = p23.y + bias;
        int n = col0 + c0;
        if (o < 256) {
            float4 out4 = make_float4(v0, v1, v2, v3);
            *(float4*)&g_qk[((size_t)b * 256 + o) * 1024 + n] = out4;
        } else {
            int c = o - 256;
            int h = c >> 7, cc = c & 127;
            float* dst = &g_vt[(((size_t)b * 4 + h) * 1024 + n) * 128 + cc];
            dst[0] = v0; dst[128] = v1; dst[256] = v2; dst[384] = v3;
        }
    }
}

// ---------------- 4) fused flash attention + residual ----------------
// grid: (m_tiles=16, h=4, b=16), 256 threads
// smem: sQ[64][68] (d-major, rows 0-31 q, 32-63 pos)
//       sK[64][68] (d-major, rows 0-31 k, 32-63 q)
//       sS[64][68] (row = local query m, col = local key n)
//       sV[64][132] (row = local key n, col = c)
//       rowmax/rowsum/rowscale[64]
#define ATTN_SMEM_FLOATS (3 * 64 * 68 + 64 * 132 + 192)

__global__ __launch_bounds__(256, 2) void attn_kernel(const float* __restrict__ x,
                                                      float* __restrict__ out)
{
    extern __shared__ float sm[];
    float* sQ = sm;
    float* sK = sm + 64 * 68;
    float* sS = sm + 2 * 64 * 68;
    float* sV = sm + 3 * 64 * 68;
    float* rowmax = sV + 64 * 132;
    float* rowsum = rowmax + 64;
    float* rowscale = rowsum + 64;

    int mt = blockIdx.x, h = blockIdx.y, b = blockIdx.z;
    int tid = threadIdx.x;
    int ty = tid >> 4, tx = tid & 15;
    int m0 = ty * 4;               // local query row base
    int mg = mt * 64;              // global query base
    size_t qkbase = (size_t)b * 256 * 1024;

    // load Q' tile: sQ[d'][m]
    #pragma unroll
    for (int it = 0; it < 4; it++) {
        int i = tid + it * 256;    // 0..1023 float4s
        int r = i >> 4, c4 = i & 15;
        const float* src = (r < 32)
            ? &g_qk[qkbase + (size_t)(h * 32 + r) * 1024 + mg + c4 * 4]
            : &g_pos[(size_t)(h * 32 + (r - 32)) * 1024 + mg + c4 * 4];
        *(float4*)&sQ[r * 68 + c4 * 4] = *(const float4*)src;
    }
    if (tid < 64) { rowmax[tid] = -1e30f; rowsum[tid] = 0.f; }

    ull acc[4][4];   // [m row i][c-pair k], c = h*128 + tx*8 + {2k, 2k+1}
    #pragma unroll
    for (int i = 0; i < 4; i++)
        #pragma unroll
        for (int k = 0; k < 4; k++) acc[i][k] = 0ull;

    const float* vbase = &g_vt[(((size_t)b * 4 + h) * 1024) * 128];

    for (int nt = 0; nt < 16; nt++) {
        __syncthreads();   // previous tile's reads of sK/sS/sV complete
        int ng = nt * 64;
        // load K' tile: sK[d'][n]
        #pragma unroll
        for (int it = 0; it < 4; it++) {
            int i = tid + it * 256;
            int r = i >> 4, c4 = i & 15;
            const float* src = (r < 32)
                ? &g_qk[qkbase + (size_t)(128 + h * 32 + r) * 1024 + ng + c4 * 4]
                : &g_qk[qkbase + (size_t)(h * 32 + (r - 32)) * 1024 + ng + c4 * 4];
            *(float4*)&sK[r * 68 + c4 * 4] = *(const float4*)src;
        }
        // load V tile: sV[n][c]
        #pragma unroll
        for (int it = 0; it < 8; it++) {
            int i = tid + it * 256;   // 0..2047 float4s
            int n = i >> 5, c4 = i & 31;
            *(float4*)&sV[n * 132 + c4 * 4] =
                *(const float4*)&vbase[(size_t)(ng + n) * 128 + c4 * 4];
        }
        __syncthreads();

        // ---- S = Q'^T K' (64x64) ----
        ull sacc[4][2];
        #pragma unroll
        for (int i = 0; i < 4; i++) { sacc[i][0] = 0ull; sacc[i][1] = 0ull; }
        #pragma unroll 16
        for (int d = 0; d < 64; d++) {
            float4 a = *(const float4*)&sQ[d * 68 + m0];
            ulonglong2 bb = *(const ulonglong2*)&sK[d * 68 + (tx << 2)];
            ull a0 = pack2(a.x, a.x);
            ull a1 = pack2(a.y, a.y);
            ull a2 = pack2(a.z, a.z);
            ull a3 = pack2(a.w, a.w);
            ffma2(sacc[0][0], a0, bb.x); ffma2(sacc[0][1], a0, bb.y);
            ffma2(sacc[1][0], a1, bb.x); ffma2(sacc[1][1], a1, bb.y);
            ffma2(sacc[2][0], a2, bb.x); ffma2(sacc[2][1], a2, bb.y);
            ffma2(sacc[3][0], a3, bb.x); ffma2(sacc[3][1], a3, bb.y);
        }
        #pragma unroll
        for (int i = 0; i < 4; i++) {
            float2 lo = unpack2(sacc[i][0]);
            float2 hi = unpack2(sacc[i][1]);
            *(float4*)&sS[(m0 + i) * 68 + (tx << 2)] = make_float4(lo.x, lo.y, hi.x, hi.y);
        }
        __syncthreads();

        // ---- online softmax over this key tile ----
        {
            int row = tid >> 2;   // 0..63
            int qq = tid & 3;
            float* srow = &sS[row * 68 + qq * 16];
            float mx = -1e30f;
            #pragma unroll
            for (int t = 0; t < 16; t++) mx = fmaxf(mx, srow[t]);
            mx = fmaxf(mx, __shfl_xor_sync(0xffffffffu, mx, 1));
            mx = fmaxf(mx, __shfl_xor_sync(0xffffffffu, mx, 2));
            float mold = rowmax[row];
            float mnew = fmaxf(mold, mx);
            float ssum = 0.f;
            #pragma unroll
            for (int t = 0; t < 16; t++) {
                float p = __expf(srow[t] - mnew);
                srow[t] = p;
                ssum += p;
            }
            ssum += __shfl_xor_sync(0xffffffffu, ssum, 1);
            ssum += __shfl_xor_sync(0xffffffffu, ssum, 2);
            if (qq == 0) {
                float sc = __expf(mold - mnew);
                rowscale[row] = sc;
                rowsum[row] = rowsum[row] * sc + ssum;
                rowmax[row] = mnew;
            }
        }
        __syncthreads();

        // ---- rescale accumulators, then acc += P * V ----
        #pragma unroll
        for (int i = 0; i < 4; i++) {
            float sc = rowscale[m0 + i];
            ull sd = pack2(sc, sc);
            fmul2(acc[i][0], sd); fmul2(acc[i][1], sd);
            fmul2(acc[i][2], sd); fmul2(acc[i][3], sd);
        }
        #pragma unroll 2
        for (int n4 = 0; n4 < 16; n4++) {
            float parr[4][4];
            #pragma unroll
            for (int i = 0; i < 4; i++) {
                float4 t = *(const float4*)&sS[(m0 + i) * 68 + (n4 << 2)];
                parr[i][0] = t.x; parr[i][1] = t.y; parr[i][2] = t.z; parr[i][3] = t.w;
            }
            #pragma unroll
            for (int nn = 0; nn < 4; nn++) {
                const float* vrow = &sV[(n4 * 4 + nn) * 132 + (tx << 3)];
                ulonglong2 va = *(const ulonglong2*)vrow;
                ulonglong2 vb = *(const ulonglong2*)(vrow + 4);
                #pragma unroll
                for (int i = 0; i < 4; i++) {
                    ull pd = pack2(parr[i][nn], parr[i][nn]);
                    ffma2(acc[i][0], pd, va.x);
                    ffma2(acc[i][1], pd, va.y);
                    ffma2(acc[i][2], pd, vb.x);
                    ffma2(acc[i][3], pd, vb.y);
                }
            }
        }
    }

    // ---- normalize, add residual, write out ----
    float inv[4];
    #pragma unroll
    for (int i = 0; i < 4; i++) inv[i] = 1.0f / rowsum[m0 + i];
    int cbase = h * 128 + (tx << 3);
    #pragma unroll
    for (int k = 0; k < 4; k++) {
        float2 p0 = unpack2(acc[0][k]);
        float2 p1 = unpack2(acc[1][k]);
        float2 p2 = unpack2(acc[2][k]);
        float2 p3 = unpack2(acc[3][k]);
        size_t a0 = ((size_t)b * 512 + cbase + 2 * k) * 1024 + mg + m0;
        float4 xv = *(const float4*)&x[a0];
        float4 ov;
        ov.x = p0.x * inv[0] + xv.x;
        ov.y = p1.x * inv[1] + xv.y;
        ov.z = p2.x * inv[2] + xv.z;
        ov.w = p3.x * inv[3] + xv.w;
        *(float4*)&out[a0] = ov;
        size_t a1 = a0 + 1024;
        xv = *(const float4*)&x[a1];
        ov.x = p0.y * inv[0] + xv.x;
        ov.y = p1.y * inv[1] + xv.y;
        ov.z = p2.y * inv[2] + xv.z;
        ov.w = p3.y * inv[3] + xv.w;
        *(float4*)&out[a1] = ov;
    }
}

// ---------------- launch ----------------
extern "C" void kernel_launch(void* const* d_in, const int* in_sizes, int n_in,
                              void* d_out, int out_size)
{
    const float* x     = (const float*)d_in[0];
    const float* Wq    = (const float*)d_in[1];
    const float* bq    = (const float*)d_in[2];
    const float* qg    = (const float*)d_in[3];
    const float* qb    = (const float*)d_in[4];
    const float* qm    = (const float*)d_in[5];
    const float* qv    = (const float*)d_in[6];
    const float* Wk    = (const float*)d_in[7];
    const float* bk    = (const float*)d_in[8];
    const float* kg    = (const float*)d_in[9];
    const float* kb    = (const float*)d_in[10];
    const float* km    = (const float*)d_in[11];
    const float* kv    = (const float*)d_in[12];
    const float* Wv    = (const float*)d_in[13];
    const float* bv    = (const float*)d_in[14];
    const float* vg    = (const float*)d_in[15];
    const float* vb    = (const float*)d_in[16];
    const float* vm    = (const float*)d_in[17];
    const float* vvar  = (const float*)d_in[18];
    const float* rel_h = (const float*)d_in[19];
    const float* rel_w = (const float*)d_in[20];
    float* out = (float*)d_out;

    cudaFuncSetAttribute(attn_kernel, cudaFuncAttributeMaxDynamicSharedMemorySize,
                         ATTN_SMEM_FLOATS * (int)sizeof(float));

    fold_kernel<<<768, 256>>>(Wq, bq, qg, qb, qm, qv,
                              Wk, bk, kg, kb, km, kv,
                              Wv, bv, vg, vb, vm, vvar);
    pos_kernel<<<512, 256>>>(rel_h, rel_w);
    proj_kernel<<<dim3(16, 12, 16), 256>>>(x);
    attn_kernel<<<dim3(16, 4, 16), 256, ATTN_SMEM_FLOATS * sizeof(float)>>>(x, out);
}

// round 2
// speedup vs baseline: 1.5138x; 1.5138x over previous
#include <cuda_runtime.h>

typedef unsigned long long ull;
typedef unsigned int uint32;

#define EPS 1e-5f

// ---------------- scratch (device globals; no cudaMalloc allowed) ----------------
__device__ float g_Wall[768 * 512];     // folded weights: rows 0-127 q, 128-255 k, 256-767 v
__device__ float g_ball[768];           // folded biases
__device__ float g_pos[128 * 1024];     // pos[h*32+d][n]
__device__ float g_qk[16 * 256 * 1024]; // [b][o][n], o<128: q (h*32+d), o in [128,256): k
__device__ float g_vt[16 * 4 * 1024 * 128]; // [b][h][n][c]

// ---------------- f32x2 packed math helpers (proj kernel) ----------------
__device__ __forceinline__ ull pack2(float x, float y) {
    ull r; asm("mov.b64 %0, {%1, %2};" : "=l"(r) : "f"(x), "f"(y)); return r;
}
__device__ __forceinline__ float2 unpack2(ull v) {
    float2 r; asm("mov.b64 {%0, %1}, %2;" : "=f"(r.x), "=f"(r.y) : "l"(v)); return r;
}
__device__ __forceinline__ void ffma2(ull& d, ull a, ull b) {
    asm("fma.rn.f32x2 %0, %1, %2, %0;" : "+l"(d) : "l"(a), "l"(b));
}

// ---------------- tf32 helpers ----------------
__device__ __forceinline__ uint32 f2tf(float x) {
    uint32 r; asm("cvt.rna.tf32.f32 %0, %1;" : "=r"(r) : "f"(x)); return r;
}
__device__ __forceinline__ float tf2f(uint32 x) { return __uint_as_float(x); }

__device__ __forceinline__ void mma_tf32(float* c, const uint32* a, uint32 b0, uint32 b1) {
    asm volatile("mma.sync.aligned.m16n8k8.row.col.f32.tf32.tf32.f32 "
        "{%0,%1,%2,%3}, {%4,%5,%6,%7}, {%8,%9}, {%0,%1,%2,%3};"
        : "+f"(c[0]), "+f"(c[1]), "+f"(c[2]), "+f"(c[3])
        : "r"(a[0]), "r"(a[1]), "r"(a[2]), "r"(a[3]), "r"(b0), "r"(b1));
}

// ---------------- 1) fold BN into conv weights ----------------
__global__ void fold_kernel(
    const float* __restrict__ Wq, const float* __restrict__ bq,
    const float* __restrict__ qg, const float* __restrict__ qb,
    const float* __restrict__ qm, const float* __restrict__ qvv,
    const float* __restrict__ Wk, const float* __restrict__ bk,
    const float* __restrict__ kg, const float* __restrict__ kb,
    const float* __restrict__ km, const float* __restrict__ kvv,
    const float* __restrict__ Wv, const float* __restrict__ bv,
    const float* __restrict__ vg, const float* __restrict__ vb,
    const float* __restrict__ vm, const float* __restrict__ vvv)
{
    int o = blockIdx.x;  // 0..767
    const float* src;
    float s, bias;
    if (o < 128) {
        s = qg[o] * rsqrtf(qvv[o] + EPS);
        bias = (bq[o] - qm[o]) * s + qb[o];
        src = Wq + o * 512;
    } else if (o < 256) {
        int oo = o - 128;
        s = kg[oo] * rsqrtf(kvv[oo] + EPS);
        bias = (bk[oo] - km[oo]) * s + kb[oo];
        src = Wk + oo * 512;
    } else {
        int oo = o - 256;
        s = vg[oo] * rsqrtf(vvv[oo] + EPS);
        bias = (bv[oo] - vm[oo]) * s + vb[oo];
        src = Wv + oo * 512;
    }
    for (int c = threadIdx.x; c < 512; c += blockDim.x)
        g_Wall[o * 512 + c] = src[c] * s;
    if (threadIdx.x == 0) g_ball[o] = bias;
}

// ---------------- 2) pos[h,d,n] = rel_h[h,d,hh] + rel_w[h,d,w], n = w*32+hh ----------------
__global__ void pos_kernel(const float* __restrict__ rel_h, const float* __restrict__ rel_w) {
    int idx = blockIdx.x * blockDim.x + threadIdx.x;
    if (idx >= 128 * 1024) return;
    int hd = idx >> 10;
    int n = idx & 1023;
    int w = n >> 5, hh = n & 31;
    g_pos[idx] = rel_h[hd * 32 + hh] + rel_w[hd * 32 + w];
}

// ---------------- 3) fused QKV projection GEMM: [768,512] x [512,1024] per batch ----------------
__global__ __launch_bounds__(256) void proj_kernel(const float* __restrict__ x) {
    __shared__ float sW[32 * 68];
    __shared__ float sX[32 * 68];
    int b = blockIdx.z;
    int row0 = blockIdx.y * 64;
    int col0 = blockIdx.x * 64;
    int tid = threadIdx.x;
    int ty = tid >> 4, tx = tid & 15;
    int r0 = ty * 4, c0 = tx * 4;
    const float* xb = x + (size_t)b * 512 * 1024;

    ull acc[4][2];
    #pragma unroll
    for (int i = 0; i < 4; i++) { acc[i][0] = 0ull; acc[i][1] = 0ull; }

    for (int kk = 0; kk < 512; kk += 32) {
        #pragma unroll
        for (int it = 0; it < 2; it++) {
            int i = tid + it * 256;
            int r = i >> 3, k4 = i & 7;
            float4 w4 = *(const float4*)&g_Wall[(row0 + r) * 512 + kk + k4 * 4];
            sW[(k4 * 4 + 0) * 68 + r] = w4.x;
            sW[(k4 * 4 + 1) * 68 + r] = w4.y;
            sW[(k4 * 4 + 2) * 68 + r] = w4.z;
            sW[(k4 * 4 + 3) * 68 + r] = w4.w;
        }
        #pragma unroll
        for (int it = 0; it < 2; it++) {
            int i = tid + it * 256;
            int k = i >> 4, n4 = i & 15;
            *(float4*)&sX[k * 68 + n4 * 4] =
                *(const float4*)&xb[(size_t)(kk + k) * 1024 + col0 + n4 * 4];
        }
        __syncthreads();
        #pragma unroll
        for (int k = 0; k < 32; k++) {
            float4 a = *(const float4*)&sW[k * 68 + r0];
            ulonglong2 bb = *(const ulonglong2*)&sX[k * 68 + c0];
            ull a0 = pack2(a.x, a.x);
            ull a1 = pack2(a.y, a.y);
            ull a2 = pack2(a.z, a.z);
            ull a3 = pack2(a.w, a.w);
            ffma2(acc[0][0], a0, bb.x); ffma2(acc[0][1], a0, bb.y);
            ffma2(acc[1][0], a1, bb.x); ffma2(acc[1][1], a1, bb.y);
            ffma2(acc[2][0], a2, bb.x); ffma2(acc[2][1], a2, bb.y);
            ffma2(acc[3][0], a3, bb.x); ffma2(acc[3][1], a3, bb.y);
        }
        __syncthreads();
    }

    #pragma unroll
    for (int i = 0; i < 4; i++) {
        int o = row0 + r0 + i;
        float bias = g_ball[o];
        float2 p01 = unpack2(acc[i][0]);
        float2 p23 = unpack2(acc[i][1]);
        float v0 = p01.x + bias, v1 = p01.y + bias, v2 = p23.x + bias, v3 = p23.y + bias;
        int n = col0 + c0;
        if (o < 256) {
            float4 out4 = make_float4(v0, v1, v2, v3);
            *(float4*)&g_qk[((size_t)b * 256 + o) * 1024 + n] = out4;
        } else {
            int c = o - 256;
            int h = c >> 7, cc = c & 127;
            float* dst = &g_vt[(((size_t)b * 4 + h) * 1024 + n) * 128 + cc];
            dst[0] = v0; dst[128] = v1; dst[256] = v2; dst[384] = v3;
        }
    }
}

// ---------------- 4) flash attention via mma.sync tf32 (3xTF32 for QK) ----------------
// grid (16 m-tiles, 4 h, 16 b), 256 threads = 8 warps.
// warp w: m-group mw = w>>1 (16 rows), n-half / c-half nh = w&1.
// smem layout (floats):
#define OFF_KB   0                    // [64 d][72]   K' big
#define OFF_KS   4608                 // [64 d][72]   K' small
#define OFF_V    9216                 // [64 n][136]  V (tf32-rounded); reused as [64 m][136] out staging
#define OFF_P    17920                // [64 m][76]   P (tf32); also Q' staging at start
#define OFF_PMAX 22784                // [2][64]
#define OFF_PSUM 22912                // [2][64]
#define OFF_RMAX 23040                // [64]
#define OFF_RSUM 23104                // [64]
#define OFF_RSCL 23168                // [64]
#define OFF_MNEW 23232                // [64]
#define ATTN_SMEM_FLOATS 23296

__global__ __launch_bounds__(256, 1) void attn_kernel(const float* __restrict__ x,
                                                      float* __restrict__ out)
{
    extern __shared__ float sm[];
    float* sKb = sm + OFF_KB;
    float* sKs = sm + OFF_KS;
    float* sV  = sm + OFF_V;
    float* sP  = sm + OFF_P;
    float* pmax = sm + OFF_PMAX;
    float* psum = sm + OFF_PSUM;
    float* rowmax = sm + OFF_RMAX;
    float* rowsum = sm + OFF_RSUM;
    float* rowscale = sm + OFF_RSCL;
    float* smnew = sm + OFF_MNEW;

    int mt = blockIdx.x, h = blockIdx.y, b = blockIdx.z;
    int tid = threadIdx.x;
    int w = tid >> 5, lane = tid & 31;
    int g = lane >> 2, kk = lane & 3;
    int mw = w >> 1, nh = w & 1;
    int mg = mt * 64;
    int rl = mw * 16 + g;     // low row of this thread's fragments
    int rh = rl + 8;
    size_t qkbase = (size_t)b * 256 * 1024;

    // ---- stage Q' tile into sP as [m][76] (transpose from d-major) ----
    #pragma unroll
    for (int it = 0; it < 4; it++) {
        int i = tid + it * 256;            // 1024 float4 units: 64 d x 16 m4
        int d = i >> 4, m4 = (i & 15) * 4;
        const float* src = (d < 32)
            ? &g_qk[qkbase + (size_t)(h * 32 + d) * 1024 + mg + m4]
            : &g_pos[(size_t)(h * 32 + (d - 32)) * 1024 + mg + m4];
        float4 v = *(const float4*)src;
        sP[(m4 + 0) * 76 + d] = v.x;
        sP[(m4 + 1) * 76 + d] = v.y;
        sP[(m4 + 2) * 76 + d] = v.z;
        sP[(m4 + 3) * 76 + d] = v.w;
    }
    if (tid < 64) { rowmax[tid] = -1e30f; rowsum[tid] = 0.f; }
    __syncthreads();

    // ---- extract Q' A-fragments (big + small) into registers ----
    uint32 Qb[32], Qs[32];
    #pragma unroll
    for (int ks = 0; ks < 8; ks++) {
        int col = 8 * ks + kk;
        float v0 = sP[rl * 76 + col];
        float v1 = sP[rh * 76 + col];
        float v2 = sP[rl * 76 + col + 4];
        float v3 = sP[rh * 76 + col + 4];
        Qb[4 * ks + 0] = f2tf(v0); Qs[4 * ks + 0] = f2tf(v0 - tf2f(Qb[4 * ks + 0]));
        Qb[4 * ks + 1] = f2tf(v1); Qs[4 * ks + 1] = f2tf(v1 - tf2f(Qb[4 * ks + 1]));
        Qb[4 * ks + 2] = f2tf(v2); Qs[4 * ks + 2] = f2tf(v2 - tf2f(Qb[4 * ks + 2]));
        Qb[4 * ks + 3] = f2tf(v3); Qs[4 * ks + 3] = f2tf(v3 - tf2f(Qb[4 * ks + 3]));
    }

    float O[8][4];
    #pragma unroll
    for (int cf = 0; cf < 8; cf++)
        #pragma unroll
        for (int j = 0; j < 4; j++) O[cf][j] = 0.f;

    const float* vbase = &g_vt[(((size_t)b * 4 + h) * 1024) * 128];

    for (int nt = 0; nt < 16; nt++) {
        __syncthreads();   // previous tile's consumers done with sKb/sKs/sV/sP
        int ng = nt * 64;

        // ---- load K' tile, pre-split into big/small tf32 ----
        #pragma unroll
        for (int it = 0; it < 4; it++) {
            int i = tid + it * 256;
            int d = i >> 4, n4 = (i & 15) * 4;
            const float* src = (d < 32)
                ? &g_qk[qkbase + (size_t)(128 + h * 32 + d) * 1024 + ng + n4]
                : &g_qk[qkbase + (size_t)(h * 32 + (d - 32)) * 1024 + ng + n4];
            float4 v = *(const float4*)src;
            float4 vb, vs;
            vb.x = tf2f(f2tf(v.x)); vs.x = tf2f(f2tf(v.x - vb.x));
            vb.y = tf2f(f2tf(v.y)); vs.y = tf2f(f2tf(v.y - vb.y));
            vb.z = tf2f(f2tf(v.z)); vs.z = tf2f(f2tf(v.z - vb.z));
            vb.w = tf2f(f2tf(v.w)); vs.w = tf2f(f2tf(v.w - vb.w));
            *(float4*)&sKb[d * 72 + n4] = vb;
            *(float4*)&sKs[d * 72 + n4] = vs;
        }
        // ---- load V tile (tf32-rounded) ----
        #pragma unroll
        for (int it = 0; it < 8; it++) {
            int i = tid + it * 256;
            int n = i >> 5, c4 = (i & 31) * 4;
            float4 v = *(const float4*)&vbase[(size_t)(ng + n) * 128 + c4];
            v.x = tf2f(f2tf(v.x)); v.y = tf2f(f2tf(v.y));
            v.z = tf2f(f2tf(v.z)); v.w = tf2f(f2tf(v.w));
            *(float4*)&sV[n * 136 + c4] = v;
        }
        __syncthreads();

        // ---- S = Q'^T K'  (3xTF32) ----
        float S[4][4];
        #pragma unroll
        for (int f = 0; f < 4; f++)
            #pragma unroll
            for (int j = 0; j < 4; j++) S[f][j] = 0.f;

        #pragma unroll
        for (int ks = 0; ks < 8; ks++) {
            int kr0 = (8 * ks + kk) * 72;
            int kr1 = kr0 + 4 * 72;
            #pragma unroll
            for (int f = 0; f < 4; f++) {
                int nc = nh * 32 + 8 * f + g;
                uint32 bb0 = __float_as_uint(sKb[kr0 + nc]);
                uint32 bb1 = __float_as_uint(sKb[kr1 + nc]);
                uint32 bs0 = __float_as_uint(sKs[kr0 + nc]);
                uint32 bs1 = __float_as_uint(sKs[kr1 + nc]);
                mma_tf32(S[f], &Qb[4 * ks], bb0, bb1);
                mma_tf32(S[f], &Qs[4 * ks], bb0, bb1);
                mma_tf32(S[f], &Qb[4 * ks], bs0, bs1);
            }
        }

        // ---- partial row max (quad reduce) ----
        float mlo = -1e30f, mhi = -1e30f;
        #pragma unroll
        for (int f = 0; f < 4; f++) {
            mlo = fmaxf(mlo, fmaxf(S[f][0], S[f][1]));
            mhi = fmaxf(mhi, fmaxf(S[f][2], S[f][3]));
        }
        mlo = fmaxf(mlo, __shfl_xor_sync(0xffffffffu, mlo, 1));
        mlo = fmaxf(mlo, __shfl_xor_sync(0xffffffffu, mlo, 2));
        mhi = fmaxf(mhi, __shfl_xor_sync(0xffffffffu, mhi, 1));
        mhi = fmaxf(mhi, __shfl_xor_sync(0xffffffffu, mhi, 2));
        if (kk == 0) {
            pmax[nh * 64 + rl] = mlo;
            pmax[nh * 64 + rh] = mhi;
        }
        __syncthreads();
        if (tid < 64) {
            float mo = rowmax[tid];
            float mn = fmaxf(mo, fmaxf(pmax[tid], pmax[64 + tid]));
            rowmax[tid] = mn;
            smnew[tid] = mn;
            rowscale[tid] = __expf(mo - mn);
        }
        __syncthreads();

        // ---- exp, partial sums, store P (tf32) ----
        float mnl = smnew[rl], mnh = smnew[rh];
        float slo = 0.f, shi = 0.f;
        #pragma unroll
        for (int f = 0; f < 4; f++) {
            float p0 = __expf(S[f][0] - mnl);
            float p1 = __expf(S[f][1] - mnl);
            float p2 = __expf(S[f][2] - mnh);
            float p3 = __expf(S[f][3] - mnh);
            slo += p0 + p1;
            shi += p2 + p3;
            int col = nh * 32 + 8 * f + 2 * kk;
            float2 lo = make_float2(tf2f(f2tf(p0)), tf2f(f2tf(p1)));
            float2 hi = make_float2(tf2f(f2tf(p2)), tf2f(f2tf(p3)));
            *(float2*)&sP[rl * 76 + col] = lo;
            *(float2*)&sP[rh * 76 + col] = hi;
        }
        slo += __shfl_xor_sync(0xffffffffu, slo, 1);
        slo += __shfl_xor_sync(0xffffffffu, slo, 2);
        shi += __shfl_xor_sync(0xffffffffu, shi, 1);
        shi += __shfl_xor_sync(0xffffffffu, shi, 2);
        if (kk == 0) {
            psum[nh * 64 + rl] = slo;
            psum[nh * 64 + rh] = shi;
        }
        __syncthreads();
        if (tid < 64)
            rowsum[tid] = rowsum[tid] * rowscale[tid] + psum[tid] + psum[64 + tid];

        // ---- rescale accumulators, then O += P * V ----
        float scl = rowscale[rl], sch = rowscale[rh];
        #pragma unroll
        for (int cf = 0; cf < 8; cf++) {
            O[cf][0] *= scl; O[cf][1] *= scl;
            O[cf][2] *= sch; O[cf][3] *= sch;
        }
        #pragma unroll
        for (int ks = 0; ks < 8; ks++) {
            uint32 a[4];
            int col = 8 * ks + kk;
            a[0] = __float_as_uint(sP[rl * 76 + col]);
            a[1] = __float_as_uint(sP[rh * 76 + col]);
            a[2] = __float_as_uint(sP[rl * 76 + col + 4]);
            a[3] = __float_as_uint(sP[rh * 76 + col + 4]);
            int vr0 = (8 * ks + kk) * 136;
            int vr1 = vr0 + 4 * 136;
            #pragma unroll
            for (int cf = 0; cf < 8; cf++) {
                int cc = nh * 64 + 8 * cf + g;
                uint32 b0 = __float_as_uint(sV[vr0 + cc]);
                uint32 b1 = __float_as_uint(sV[vr1 + cc]);
                mma_tf32(O[cf], a, b0, b1);
            }
        }
    }

    // ---- normalize and stage output [m][c] in sV ----
    __syncthreads();
    float il = 1.0f / rowsum[rl];
    float ih = 1.0f / rowsum[rh];
    #pragma unroll
    for (int cf = 0; cf < 8; cf++) {
        int col = nh * 64 + 8 * cf + 2 * kk;
        *(float2*)&sV[rl * 136 + col] = make_float2(O[cf][0] * il, O[cf][1] * il);
        *(float2*)&sV[rh * 136 + col] = make_float2(O[cf][2] * ih, O[cf][3] * ih);
    }
    __syncthreads();

    // ---- coalesced write: out = staged + x ----
    {
        int m = tid & 63;
        int c0 = (tid >> 6) * 32;
        #pragma unroll 4
        for (int k = 0; k < 32; k++) {
            int c = c0 + k;
            float v = sV[m * 136 + c];
            size_t a = ((size_t)b * 512 + h * 128 + c) * 1024 + mg + m;
            out[a] = v + x[a];
        }
    }
}

// ---------------- launch ----------------
extern "C" void kernel_launch(void* const* d_in, const int* in_sizes, int n_in,
                              void* d_out, int out_size)
{
    const float* x     = (const float*)d_in[0];
    const float* Wq    = (const float*)d_in[1];
    const float* bq    = (const float*)d_in[2];
    const float* qg    = (const float*)d_in[3];
    const float* qb    = (const float*)d_in[4];
    const float* qm    = (const float*)d_in[5];
    const float* qv    = (const float*)d_in[6];
    const float* Wk    = (const float*)d_in[7];
    const float* bk    = (const float*)d_in[8];
    const float* kg    = (const float*)d_in[9];
    const float* kb    = (const float*)d_in[10];
    const float* km    = (const float*)d_in[11];
    const float* kv    = (const float*)d_in[12];
    const float* Wv    = (const float*)d_in[13];
    const float* bv    = (const float*)d_in[14];
    const float* vg    = (const float*)d_in[15];
    const float* vb    = (const float*)d_in[16];
    const float* vm    = (const float*)d_in[17];
    const float* vvar  = (const float*)d_in[18];
    const float* rel_h = (const float*)d_in[19];
    const float* rel_w = (const float*)d_in[20];
    float* out = (float*)d_out;

    cudaFuncSetAttribute(attn_kernel, cudaFuncAttributeMaxDynamicSharedMemorySize,
                         ATTN_SMEM_FLOATS * (int)sizeof(float));

    fold_kernel<<<768, 256>>>(Wq, bq, qg, qb, qm, qv,
                              Wk, bk, kg, kb, km, kv,
                              Wv, bv, vg, vb, vm, vvar);
    pos_kernel<<<512, 256>>>(rel_h, rel_w);
    proj_kernel<<<dim3(16, 12, 16), 256>>>(x);
    attn_kernel<<<dim3(16, 4, 16), 256, ATTN_SMEM_FLOATS * sizeof(float)>>>(x, out);
}

// round 3
// speedup vs baseline: 1.9890x; 1.3139x over previous
#include <cuda_runtime.h>

typedef unsigned int uint32;

#define EPS 1e-5f

// ---------------- scratch (device globals; no cudaMalloc allowed) ----------------
__device__ float g_Wall[768 * 512];     // folded weights: rows 0-127 q, 128-255 k, 256-767 v
__device__ float g_ball[768];           // folded biases
__device__ float g_pos[128 * 1024];     // pos[h*32+d][n]
__device__ float g_qk[16 * 256 * 1024]; // [b][o][n], o<128: q (h*32+d), o in [128,256): k
__device__ float g_vt[16 * 4 * 1024 * 128]; // [b][h][n][c]

// ---------------- tf32 helpers ----------------
__device__ __forceinline__ uint32 f2tf(float x) {
    uint32 r; asm("cvt.rna.tf32.f32 %0, %1;" : "=r"(r) : "f"(x)); return r;
}
__device__ __forceinline__ float tf2f(uint32 x) { return __uint_as_float(x); }

__device__ __forceinline__ void mma_tf32(float* c, const uint32* a, uint32 b0, uint32 b1) {
    asm volatile("mma.sync.aligned.m16n8k8.row.col.f32.tf32.tf32.f32 "
        "{%0,%1,%2,%3}, {%4,%5,%6,%7}, {%8,%9}, {%0,%1,%2,%3};"
        : "+f"(c[0]), "+f"(c[1]), "+f"(c[2]), "+f"(c[3])
        : "r"(a[0]), "r"(a[1]), "r"(a[2]), "r"(a[3]), "r"(b0), "r"(b1));
}

__device__ __forceinline__ void split_tf32(float v, float& big, float& small) {
    big = tf2f(f2tf(v));
    small = tf2f(f2tf(v - big));
}

// ---------------- 1) fold BN into conv weights ----------------
__global__ void fold_kernel(
    const float* __restrict__ Wq, const float* __restrict__ bq,
    const float* __restrict__ qg, const float* __restrict__ qb,
    const float* __restrict__ qm, const float* __restrict__ qvv,
    const float* __restrict__ Wk, const float* __restrict__ bk,
    const float* __restrict__ kg, const float* __restrict__ kb,
    const float* __restrict__ km, const float* __restrict__ kvv,
    const float* __restrict__ Wv, const float* __restrict__ bv,
    const float* __restrict__ vg, const float* __restrict__ vb,
    const float* __restrict__ vm, const float* __restrict__ vvv)
{
    int o = blockIdx.x;  // 0..767
    const float* src;
    float s, bias;
    if (o < 128) {
        s = qg[o] * rsqrtf(qvv[o] + EPS);
        bias = (bq[o] - qm[o]) * s + qb[o];
        src = Wq + o * 512;
    } else if (o < 256) {
        int oo = o - 128;
        s = kg[oo] * rsqrtf(kvv[oo] + EPS);
        bias = (bk[oo] - km[oo]) * s + kb[oo];
        src = Wk + oo * 512;
    } else {
        int oo = o - 256;
        s = vg[oo] * rsqrtf(vvv[oo] + EPS);
        bias = (bv[oo] - vm[oo]) * s + vb[oo];
        src = Wv + oo * 512;
    }
    for (int c = threadIdx.x; c < 512; c += blockDim.x)
        g_Wall[o * 512 + c] = src[c] * s;
    if (threadIdx.x == 0) g_ball[o] = bias;
}

// ---------------- 2) pos[h,d,n] = rel_h[h,d,hh] + rel_w[h,d,w], n = w*32+hh ----------------
__global__ void pos_kernel(const float* __restrict__ rel_h, const float* __restrict__ rel_w) {
    int idx = blockIdx.x * blockDim.x + threadIdx.x;
    if (idx >= 128 * 1024) return;
    int hd = idx >> 10;
    int n = idx & 1023;
    int w = n >> 5, hh = n & 31;
    g_pos[idx] = rel_h[hd * 32 + hh] + rel_w[hd * 32 + w];
}

// ---------------- 3) QKV projection via mma tf32 (3xTF32) ----------------
// block tile 128(o) x 128(n), K=512 in steps of 32. 256 threads = 8 warps (4m x 2n).
// smem: sWb/sWs [128 m][36]  (A: [m][k], frag loads bank (4g+kk) conflict-free)
//       sXb/sXs [32 k][136]  (B: [k][n], frag loads bank (8kk+g) conflict-free)
#define PW 36
#define PX 136
#define POFF_WS (128 * 36)
#define POFF_XB (2 * 128 * 36)
#define POFF_XS (POFF_XB + 32 * 136)
#define PROJ_SMEM_FLOATS (POFF_XS + 32 * 136)   // 17920 floats = 71680 B

__device__ __forceinline__ void proj_store2(int b, int o, int n, float v0, float v1) {
    if (o < 256) {
        *(float2*)&g_qk[((size_t)b * 256 + o) * 1024 + n] = make_float2(v0, v1);
    } else {
        int c = o - 256;
        int h = c >> 7, cc = c & 127;
        float* d = &g_vt[(((size_t)b * 4 + h) * 1024 + n) * 128 + cc];
        d[0] = v0; d[128] = v1;
    }
}

__global__ __launch_bounds__(256) void proj_kernel(const float* __restrict__ x) {
    extern __shared__ float ps[];
    float* sWb = ps;
    float* sWs = ps + POFF_WS;
    float* sXb = ps + POFF_XB;
    float* sXs = ps + POFF_XS;
    int b = blockIdx.z, row0 = blockIdx.y * 128, col0 = blockIdx.x * 128;
    int tid = threadIdx.x, w = tid >> 5, lane = tid & 31;
    int g = lane >> 2, kk = lane & 3;
    int wm = w >> 1, wn = w & 1;
    const float* xb = x + (size_t)b * 512 * 1024;

    float acc[2][8][4];
    #pragma unroll
    for (int mi = 0; mi < 2; mi++)
        #pragma unroll
        for (int nf = 0; nf < 8; nf++)
            #pragma unroll
            for (int j = 0; j < 4; j++) acc[mi][nf][j] = 0.f;

    for (int kt = 0; kt < 512; kt += 32) {
        __syncthreads();
        // W tile 128m x 32k -> [m][k] split
        #pragma unroll
        for (int it = 0; it < 4; it++) {
            int i = tid + it * 256;
            int m = i >> 3, k4 = (i & 7) * 4;
            float4 wv = *(const float4*)&g_Wall[(size_t)(row0 + m) * 512 + kt + k4];
            float4 hb, hs;
            split_tf32(wv.x, hb.x, hs.x);
            split_tf32(wv.y, hb.y, hs.y);
            split_tf32(wv.z, hb.z, hs.z);
            split_tf32(wv.w, hb.w, hs.w);
            *(float4*)&sWb[m * PW + k4] = hb;
            *(float4*)&sWs[m * PW + k4] = hs;
        }
        // X tile 32k x 128n -> [k][n] split
        #pragma unroll
        for (int it = 0; it < 4; it++) {
            int i = tid + it * 256;
            int k = i >> 5, n4 = (i & 31) * 4;
            float4 xv = *(const float4*)&xb[(size_t)(kt + k) * 1024 + col0 + n4];
            float4 hb, hs;
            split_tf32(xv.x, hb.x, hs.x);
            split_tf32(xv.y, hb.y, hs.y);
            split_tf32(xv.z, hb.z, hs.z);
            split_tf32(xv.w, hb.w, hs.w);
            *(float4*)&sXb[k * PX + n4] = hb;
            *(float4*)&sXs[k * PX + n4] = hs;
        }
        __syncthreads();

        #pragma unroll
        for (int ks = 0; ks < 4; ks++) {
            uint32 Ab[2][4], As[2][4];
            #pragma unroll
            for (int mi = 0; mi < 2; mi++) {
                int r = wm * 32 + mi * 16 + g;
                int c = ks * 8 + kk;
                Ab[mi][0] = __float_as_uint(sWb[r * PW + c]);
                Ab[mi][1] = __float_as_uint(sWb[(r + 8) * PW + c]);
                Ab[mi][2] = __float_as_uint(sWb[r * PW + c + 4]);
                Ab[mi][3] = __float_as_uint(sWb[(r + 8) * PW + c + 4]);
                As[mi][0] = __float_as_uint(sWs[r * PW + c]);
                As[mi][1] = __float_as_uint(sWs[(r + 8) * PW + c]);
                As[mi][2] = __float_as_uint(sWs[r * PW + c + 4]);
                As[mi][3] = __float_as_uint(sWs[(r + 8) * PW + c + 4]);
            }
            #pragma unroll
            for (int nf = 0; nf < 8; nf++) {
                int nc = wn * 64 + 8 * nf + g;
                int kr = (ks * 8 + kk) * PX;
                uint32 bb0 = __float_as_uint(sXb[kr + nc]);
                uint32 bb1 = __float_as_uint(sXb[kr + 4 * PX + nc]);
                uint32 bs0 = __float_as_uint(sXs[kr + nc]);
                uint32 bs1 = __float_as_uint(sXs[kr + 4 * PX + nc]);
                #pragma unroll
                for (int mi = 0; mi < 2; mi++) {
                    mma_tf32(acc[mi][nf], Ab[mi], bb0, bb1);
                    mma_tf32(acc[mi][nf], As[mi], bb0, bb1);
                    mma_tf32(acc[mi][nf], Ab[mi], bs0, bs1);
                }
            }
        }
    }

    // epilogue: bias + scatter to g_qk / g_vt
    #pragma unroll
    for (int mi = 0; mi < 2; mi++) {
        int o0 = row0 + wm * 32 + mi * 16 + g;
        int o1 = o0 + 8;
        float b0v = g_ball[o0], b1v = g_ball[o1];
        #pragma unroll
        for (int nf = 0; nf < 8; nf++) {
            int n = col0 + wn * 64 + 8 * nf + 2 * kk;
            proj_store2(b, o0, n, acc[mi][nf][0] + b0v, acc[mi][nf][1] + b0v);
            proj_store2(b, o1, n, acc[mi][nf][2] + b1v, acc[mi][nf][3] + b1v);
        }
    }
}

// ---------------- 4) flash attention: warp-autonomous softmax + double buffer ----------------
// 256 threads = 8 warps; warp w owns rows 16w..16w+15 of a 128-query tile, all 64 key cols.
// smem floats: buf0 @0, buf1 @17920; each buf: Kb[64][72] +0, Ks +4608, V[64][136] +9216.
// sP per warp @35840 + w*1216 : [16][76]. Q staging uses buf1.V area ([128][68]).
#define ABUF 17920
#define AOFF_SQ (ABUF + 9216)
#define AOFF_SP (2 * ABUF)
#define ATTN_SMEM_FLOATS (2 * ABUF + 8 * 16 * 76)   // 45568 floats = 182272 B

__device__ __forceinline__ void attn_load_tile(float* buf, int nt, size_t qkbase,
                                               const float* vbase, int h, int tid)
{
    int ng = nt * 64;
    float* sKb = buf;
    float* sKs = buf + 4608;
    float* sV  = buf + 9216;
    #pragma unroll
    for (int it = 0; it < 4; it++) {
        int i = tid + it * 256;
        int d = i >> 4, n4 = (i & 15) * 4;
        const float* src = (d < 32)
            ? &g_qk[qkbase + (size_t)(128 + h * 32 + d) * 1024 + ng + n4]
            : &g_qk[qkbase + (size_t)(h * 32 + (d - 32)) * 1024 + ng + n4];
        float4 v = *(const float4*)src;
        float4 vb, vs;
        split_tf32(v.x, vb.x, vs.x);
        split_tf32(v.y, vb.y, vs.y);
        split_tf32(v.z, vb.z, vs.z);
        split_tf32(v.w, vb.w, vs.w);
        *(float4*)&sKb[d * 72 + n4] = vb;
        *(float4*)&sKs[d * 72 + n4] = vs;
    }
    #pragma unroll
    for (int it = 0; it < 8; it++) {
        int i = tid + it * 256;
        int n = i >> 5, c4 = (i & 31) * 4;
        float4 v = *(const float4*)&vbase[(size_t)(ng + n) * 128 + c4];
        v.x = tf2f(f2tf(v.x)); v.y = tf2f(f2tf(v.y));
        v.z = tf2f(f2tf(v.z)); v.w = tf2f(f2tf(v.w));
        *(float4*)&sV[n * 136 + c4] = v;
    }
}

__global__ __launch_bounds__(256, 1) void attn_kernel(const float* __restrict__ x,
                                                      float* __restrict__ out)
{
    extern __shared__ float sm[];
    int mt = blockIdx.x, h = blockIdx.y, b = blockIdx.z;
    int tid = threadIdx.x, w = tid >> 5, lane = tid & 31;
    int g = lane >> 2, kk = lane & 3;
    int mg = mt * 128;
    int rl = 16 * w + g, rh = rl + 8;
    size_t qkbase = (size_t)b * 256 * 1024;
    const float* vbase = &g_vt[(((size_t)b * 4 + h) * 1024) * 128];
    float* sQ = sm + AOFF_SQ;
    float* sP = sm + AOFF_SP + w * 1216;

    // ---- stage Q' [128 m][68] (transpose from d-major), plus load tile 0 ----
    #pragma unroll
    for (int it = 0; it < 8; it++) {
        int i = tid + it * 256;   // 2048 float4 units: 64 d x 32 m4
        int d = i >> 5, m4 = (i & 31) * 4;
        const float* src = (d < 32)
            ? &g_qk[qkbase + (size_t)(h * 32 + d) * 1024 + mg + m4]
            : &g_pos[(size_t)(h * 32 + (d - 32)) * 1024 + mg + m4];
        float4 v = *(const float4*)src;
        sQ[(m4 + 0) * 68 + d] = v.x;
        sQ[(m4 + 1) * 68 + d] = v.y;
        sQ[(m4 + 2) * 68 + d] = v.z;
        sQ[(m4 + 3) * 68 + d] = v.w;
    }
    attn_load_tile(sm, 0, qkbase, vbase, h, tid);
    __syncthreads();

    // ---- extract Q' A-fragments (big + small) into registers ----
    uint32 Qb[32], Qs[32];
    #pragma unroll
    for (int ks = 0; ks < 8; ks++) {
        int c = 8 * ks + kk;
        float v0 = sQ[rl * 68 + c];
        float v1 = sQ[rh * 68 + c];
        float v2 = sQ[rl * 68 + c + 4];
        float v3 = sQ[rh * 68 + c + 4];
        Qb[4 * ks + 0] = f2tf(v0); Qs[4 * ks + 0] = f2tf(v0 - tf2f(Qb[4 * ks + 0]));
        Qb[4 * ks + 1] = f2tf(v1); Qs[4 * ks + 1] = f2tf(v1 - tf2f(Qb[4 * ks + 1]));
        Qb[4 * ks + 2] = f2tf(v2); Qs[4 * ks + 2] = f2tf(v2 - tf2f(Qb[4 * ks + 2]));
        Qb[4 * ks + 3] = f2tf(v3); Qs[4 * ks + 3] = f2tf(v3 - tf2f(Qb[4 * ks + 3]));
    }
    float m_l = -1e30f, m_h = -1e30f, l_l = 0.f, l_h = 0.f;
    float O[16][4];
    #pragma unroll
    for (int cf = 0; cf < 16; cf++)
        #pragma unroll
        for (int j = 0; j < 4; j++) O[cf][j] = 0.f;
    __syncthreads();   // all warps done reading sQ (tile-1 prefetch overwrites it)

    for (int nt = 0; nt < 16; nt++) {
        float* cur = sm + (nt & 1) * ABUF;
        if (nt < 15)
            attn_load_tile(sm + ((nt + 1) & 1) * ABUF, nt + 1, qkbase, vbase, h, tid);
        float* cKb = cur;
        float* cKs = cur + 4608;
        float* cV  = cur + 9216;

        // ---- S = Q'^T K' (3xTF32), warp: 16 rows x 64 cols ----
        float S[8][4];
        #pragma unroll
        for (int f = 0; f < 8; f++)
            #pragma unroll
            for (int j = 0; j < 4; j++) S[f][j] = 0.f;
        #pragma unroll
        for (int ks = 0; ks < 8; ks++) {
            int kr0 = (8 * ks + kk) * 72, kr1 = kr0 + 288;
            #pragma unroll
            for (int f = 0; f < 8; f++) {
                int nc = 8 * f + g;
                uint32 bb0 = __float_as_uint(cKb[kr0 + nc]);
                uint32 bb1 = __float_as_uint(cKb[kr1 + nc]);
                uint32 bs0 = __float_as_uint(cKs[kr0 + nc]);
                uint32 bs1 = __float_as_uint(cKs[kr1 + nc]);
                mma_tf32(S[f], &Qb[4 * ks], bb0, bb1);
                mma_tf32(S[f], &Qs[4 * ks], bb0, bb1);
                mma_tf32(S[f], &Qb[4 * ks], bs0, bs1);
            }
        }

        // ---- warp-local online softmax (quad shuffles only) ----
        float mlo = -1e30f, mhi = -1e30f;
        #pragma unroll
        for (int f = 0; f < 8; f++) {
            mlo = fmaxf(mlo, fmaxf(S[f][0], S[f][1]));
            mhi = fmaxf(mhi, fmaxf(S[f][2], S[f][3]));
        }
        mlo = fmaxf(mlo, __shfl_xor_sync(0xffffffffu, mlo, 1));
        mlo = fmaxf(mlo, __shfl_xor_sync(0xffffffffu, mlo, 2));
        mhi = fmaxf(mhi, __shfl_xor_sync(0xffffffffu, mhi, 1));
        mhi = fmaxf(mhi, __shfl_xor_sync(0xffffffffu, mhi, 2));
        float mnl = fmaxf(m_l, mlo), mnh = fmaxf(m_h, mhi);
        float scl = __expf(m_l - mnl), sch = __expf(m_h - mnh);
        m_l = mnl; m_h = mnh;
        float slo = 0.f, shi = 0.f;
        #pragma unroll
        for (int f = 0; f < 8; f++) {
            float p0 = __expf(S[f][0] - mnl);
            float p1 = __expf(S[f][1] - mnl);
            float p2 = __expf(S[f][2] - mnh);
            float p3 = __expf(S[f][3] - mnh);
            slo += p0 + p1;
            shi += p2 + p3;
            int col = 8 * f + 2 * kk;
            *(float2*)&sP[g * 76 + col] = make_float2(tf2f(f2tf(p0)), tf2f(f2tf(p1)));
            *(float2*)&sP[(g + 8) * 76 + col] = make_float2(tf2f(f2tf(p2)), tf2f(f2tf(p3)));
        }
        slo += __shfl_xor_sync(0xffffffffu, slo, 1);
        slo += __shfl_xor_sync(0xffffffffu, slo, 2);
        shi += __shfl_xor_sync(0xffffffffu, shi, 1);
        shi += __shfl_xor_sync(0xffffffffu, shi, 2);
        l_l = l_l * scl + slo;
        l_h = l_h * sch + shi;
        __syncwarp();

        // ---- rescale O, then O += P * V ----
        #pragma unroll
        for (int cf = 0; cf < 16; cf++) {
            O[cf][0] *= scl; O[cf][1] *= scl;
            O[cf][2] *= sch; O[cf][3] *= sch;
        }
        #pragma unroll
        for (int ks = 0; ks < 8; ks++) {
            uint32 a[4];
            int col = 8 * ks + kk;
            a[0] = __float_as_uint(sP[g * 76 + col]);
            a[1] = __float_as_uint(sP[(g + 8) * 76 + col]);
            a[2] = __float_as_uint(sP[g * 76 + col + 4]);
            a[3] = __float_as_uint(sP[(g + 8) * 76 + col + 4]);
            int vr0 = (8 * ks + kk) * 136, vr1 = vr0 + 544;
            #pragma unroll
            for (int cf = 0; cf < 16; cf++) {
                int cc = 8 * cf + g;
                uint32 b0 = __float_as_uint(cV[vr0 + cc]);
                uint32 b1 = __float_as_uint(cV[vr1 + cc]);
                mma_tf32(O[cf], a, b0, b1);
            }
        }
        __syncthreads();
    }

    // ---- normalize, stage [m][132], coalesced out = O + x ----
    float il = 1.0f / l_l, ih = 1.0f / l_h;
    float* sO = sm;   // reuse buf0 (last reads were from buf1 or barrier-protected)
    #pragma unroll
    for (int cf = 0; cf < 16; cf++) {
        int col = 8 * cf + 2 * kk;
        *(float2*)&sO[rl * 132 + col] = make_float2(O[cf][0] * il, O[cf][1] * il);
        *(float2*)&sO[rh * 132 + col] = make_float2(O[cf][2] * ih, O[cf][3] * ih);
    }
    __syncthreads();
    {
        int m = tid & 127;
        int c0 = (tid >> 7) * 64;
        #pragma unroll 4
        for (int k2 = 0; k2 < 64; k2++) {
            int c = c0 + k2;
            size_t a = ((size_t)b * 512 + h * 128 + c) * 1024 + mg + m;
            out[a] = sO[m * 132 + c] + x[a];
        }
    }
}

// ---------------- launch ----------------
extern "C" void kernel_launch(void* const* d_in, const int* in_sizes, int n_in,
                              void* d_out, int out_size)
{
    const float* x     = (const float*)d_in[0];
    const float* Wq    = (const float*)d_in[1];
    const float* bq    = (const float*)d_in[2];
    const float* qg    = (const float*)d_in[3];
    const float* qb    = (const float*)d_in[4];
    const float* qm    = (const float*)d_in[5];
    const float* qv    = (const float*)d_in[6];
    const float* Wk    = (const float*)d_in[7];
    const float* bk    = (const float*)d_in[8];
    const float* kg    = (const float*)d_in[9];
    const float* kb    = (const float*)d_in[10];
    const float* km    = (const float*)d_in[11];
    const float* kv    = (const float*)d_in[12];
    const float* Wv    = (const float*)d_in[13];
    const float* bv    = (const float*)d_in[14];
    const float* vg    = (const float*)d_in[15];
    const float* vb    = (const float*)d_in[16];
    const float* vm    = (const float*)d_in[17];
    const float* vvar  = (const float*)d_in[18];
    const float* rel_h = (const float*)d_in[19];
    const float* rel_w = (const float*)d_in[20];
    float* out = (float*)d_out;

    cudaFuncSetAttribute(attn_kernel, cudaFuncAttributeMaxDynamicSharedMemorySize,
                         ATTN_SMEM_FLOATS * (int)sizeof(float));
    cudaFuncSetAttribute(proj_kernel, cudaFuncAttributeMaxDynamicSharedMemorySize,
                         PROJ_SMEM_FLOATS * (int)sizeof(float));

    fold_kernel<<<768, 256>>>(Wq, bq, qg, qb, qm, qv,
                              Wk, bk, kg, kb, km, kv,
                              Wv, bv, vg, vb, vm, vvar);
    pos_kernel<<<512, 256>>>(rel_h, rel_w);
    proj_kernel<<<dim3(8, 6, 16), 256, PROJ_SMEM_FLOATS * sizeof(float)>>>(x);
    attn_kernel<<<dim3(8, 4, 16), 256, ATTN_SMEM_FLOATS * sizeof(float)>>>(x, out);
}

// round 4
// speedup vs baseline: 2.1248x; 1.0683x over previous
#include <cuda_runtime.h>

typedef unsigned int uint32;

#define EPS 1e-5f
#define TILE_F 17408   // floats per fragment-ready (K,V) tile image (8448 K + 8448 V + pad)

// ---------------- scratch (device globals; no cudaMalloc allowed) ----------------
__device__ float g_Wall[768 * 512];     // folded weights: rows 0-127 q, 128-255 k, 256-767 v
__device__ float g_ball[768];           // folded biases
__device__ float g_pos[128 * 1024];     // pos[h*32+d][n]
__device__ float g_qk[16 * 256 * 1024]; // [b][o][n], o<128: q (h*32+d), o in [128,256): k
__device__ float g_vt[16 * 4 * 1024 * 128]; // [b][h][n][c]
__device__ __align__(16) float g_tile[16 * 4 * 16 * TILE_F]; // fragment-ready K'/V tiles

// ---------------- tf32 helpers ----------------
__device__ __forceinline__ uint32 f2tf(float x) {
    uint32 r; asm("cvt.rna.tf32.f32 %0, %1;" : "=r"(r) : "f"(x)); return r;
}
__device__ __forceinline__ float tf2f(uint32 x) { return __uint_as_float(x); }

__device__ __forceinline__ void mma_tf32(float* c, const uint32* a, uint32 b0, uint32 b1) {
    asm volatile("mma.sync.aligned.m16n8k8.row.col.f32.tf32.tf32.f32 "
        "{%0,%1,%2,%3}, {%4,%5,%6,%7}, {%8,%9}, {%0,%1,%2,%3};"
        : "+f"(c[0]), "+f"(c[1]), "+f"(c[2]), "+f"(c[3])
        : "r"(a[0]), "r"(a[1]), "r"(a[2]), "r"(a[3]), "r"(b0), "r"(b1));
}

__device__ __forceinline__ void split_tf32(float v, float& big, float& small) {
    big = tf2f(f2tf(v));
    small = tf2f(f2tf(v - big));
}

// ---------------- cp.async helpers ----------------
__device__ __forceinline__ void cp_tile(float* smem_dst, const float* gsrc, int tid) {
    uint32 s = (uint32)__cvta_generic_to_shared(smem_dst);
    #pragma unroll
    for (int it = 0; it < 17; it++) {
        int i = tid + it * 256;          // 4352 float4s = 17408 floats
        asm volatile("cp.async.cg.shared.global [%0], [%1], 16;\n"
                     :: "r"(s + i * 16), "l"(gsrc + i * 4));
    }
}
#define CP_COMMIT() asm volatile("cp.async.commit_group;\n" ::: "memory")
#define CP_WAIT0()  asm volatile("cp.async.wait_group 0;\n" ::: "memory")

// ---------------- 1) fold BN into conv weights ----------------
__global__ void fold_kernel(
    const float* __restrict__ Wq, const float* __restrict__ bq,
    const float* __restrict__ qg, const float* __restrict__ qb,
    const float* __restrict__ qm, const float* __restrict__ qvv,
    const float* __restrict__ Wk, const float* __restrict__ bk,
    const float* __restrict__ kg, const float* __restrict__ kb,
    const float* __restrict__ km, const float* __restrict__ kvv,
    const float* __restrict__ Wv, const float* __restrict__ bv,
    const float* __restrict__ vg, const float* __restrict__ vb,
    const float* __restrict__ vm, const float* __restrict__ vvv)
{
    int o = blockIdx.x;  // 0..767
    const float* src;
    float s, bias;
    if (o < 128) {
        s = qg[o] * rsqrtf(qvv[o] + EPS);
        bias = (bq[o] - qm[o]) * s + qb[o];
        src = Wq + o * 512;
    } else if (o < 256) {
        int oo = o - 128;
        s = kg[oo] * rsqrtf(kvv[oo] + EPS);
        bias = (bk[oo] - km[oo]) * s + kb[oo];
        src = Wk + oo * 512;
    } else {
        int oo = o - 256;
        s = vg[oo] * rsqrtf(vvv[oo] + EPS);
        bias = (bv[oo] - vm[oo]) * s + vb[oo];
        src = Wv + oo * 512;
    }
    for (int c = threadIdx.x; c < 512; c += blockDim.x)
        g_Wall[o * 512 + c] = src[c] * s;
    if (threadIdx.x == 0) g_ball[o] = bias;
}

// ---------------- 2) pos[h,d,n] = rel_h[h,d,hh] + rel_w[h,d,w] ----------------
__global__ void pos_kernel(const float* __restrict__ rel_h, const float* __restrict__ rel_w) {
    int idx = blockIdx.x * blockDim.x + threadIdx.x;
    if (idx >= 128 * 1024) return;
    int hd = idx >> 10;
    int n = idx & 1023;
    int w = n >> 5, hh = n & 31;
    g_pos[idx] = rel_h[hd * 32 + hh] + rel_w[hd * 32 + w];
}

// ---------------- 3) QKV projection via mma tf32 ----------------
// block tile 128(o) x 128(n); QK blocks (y<2): 3xTF32; V blocks (y>=2): 2-term.
#define PW 36
#define PX 136
#define PROJ_SMEM_FLOATS 17920   // sWb 4608 | sWs 4608 | sXb 4352 | sXs 4352

__global__ __launch_bounds__(256) void proj_kernel(const float* __restrict__ x) {
    extern __shared__ float ps[];
    float* sWb = ps;
    float* sWs = ps + 4608;
    float* sXb = ps + 9216;
    float* sXs = ps + 13568;
    int b = blockIdx.z, row0 = blockIdx.y * 128, col0 = blockIdx.x * 128;
    bool isV = (row0 >= 256);
    int tid = threadIdx.x, w = tid >> 5, lane = tid & 31;
    int g = lane >> 2, kk = lane & 3;
    int wm = w >> 1, wn = w & 1;
    const float* xb = x + (size_t)b * 512 * 1024;

    float acc[2][8][4];
    #pragma unroll
    for (int mi = 0; mi < 2; mi++)
        #pragma unroll
        for (int nf = 0; nf < 8; nf++)
            #pragma unroll
            for (int j = 0; j < 4; j++) acc[mi][nf][j] = 0.f;

    float4 wreg[4], xreg[4];
    #pragma unroll
    for (int it = 0; it < 4; it++) {
        int i = tid + it * 256;
        wreg[it] = *(const float4*)&g_Wall[(size_t)(row0 + (i >> 3)) * 512 + ((i & 7) << 2)];
        xreg[it] = *(const float4*)&xb[(size_t)(i >> 5) * 1024 + col0 + ((i & 31) << 2)];
    }

    for (int kt = 0; kt < 16; kt++) {
        __syncthreads();
        #pragma unroll
        for (int it = 0; it < 4; it++) {
            int i = tid + it * 256;
            int m = i >> 3, k4 = (i & 7) << 2;
            float4 hb, hs;
            split_tf32(wreg[it].x, hb.x, hs.x);
            split_tf32(wreg[it].y, hb.y, hs.y);
            split_tf32(wreg[it].z, hb.z, hs.z);
            split_tf32(wreg[it].w, hb.w, hs.w);
            *(float4*)&sWb[m * PW + k4] = hb;
            *(float4*)&sWs[m * PW + k4] = hs;
        }
        if (!isV) {
            #pragma unroll
            for (int it = 0; it < 4; it++) {
                int i = tid + it * 256;
                int k = i >> 5, n4 = (i & 31) << 2;
                float4 hb, hs;
                split_tf32(xreg[it].x, hb.x, hs.x);
                split_tf32(xreg[it].y, hb.y, hs.y);
                split_tf32(xreg[it].z, hb.z, hs.z);
                split_tf32(xreg[it].w, hb.w, hs.w);
                *(float4*)&sXb[k * PX + n4] = hb;
                *(float4*)&sXs[k * PX + n4] = hs;
            }
        } else {
            #pragma unroll
            for (int it = 0; it < 4; it++) {
                int i = tid + it * 256;
                int k = i >> 5, n4 = (i & 31) << 2;
                float4 hb;
                hb.x = tf2f(f2tf(xreg[it].x));
                hb.y = tf2f(f2tf(xreg[it].y));
                hb.z = tf2f(f2tf(xreg[it].z));
                hb.w = tf2f(f2tf(xreg[it].w));
                *(float4*)&sXb[k * PX + n4] = hb;
            }
        }
        __syncthreads();
        if (kt < 15) {
            #pragma unroll
            for (int it = 0; it < 4; it++) {
                int i = tid + it * 256;
                wreg[it] = *(const float4*)&g_Wall[(size_t)(row0 + (i >> 3)) * 512 + (kt + 1) * 32 + ((i & 7) << 2)];
                xreg[it] = *(const float4*)&xb[(size_t)((kt + 1) * 32 + (i >> 5)) * 1024 + col0 + ((i & 31) << 2)];
            }
        }

        #pragma unroll
        for (int ks = 0; ks < 4; ks++) {
            uint32 Ab[2][4], As[2][4];
            #pragma unroll
            for (int mi = 0; mi < 2; mi++) {
                int r = wm * 32 + mi * 16 + g;
                int c = ks * 8 + kk;
                Ab[mi][0] = __float_as_uint(sWb[r * PW + c]);
                Ab[mi][1] = __float_as_uint(sWb[(r + 8) * PW + c]);
                Ab[mi][2] = __float_as_uint(sWb[r * PW + c + 4]);
                Ab[mi][3] = __float_as_uint(sWb[(r + 8) * PW + c + 4]);
                As[mi][0] = __float_as_uint(sWs[r * PW + c]);
                As[mi][1] = __float_as_uint(sWs[(r + 8) * PW + c]);
                As[mi][2] = __float_as_uint(sWs[r * PW + c + 4]);
                As[mi][3] = __float_as_uint(sWs[(r + 8) * PW + c + 4]);
            }
            if (!isV) {
                #pragma unroll
                for (int nf = 0; nf < 8; nf++) {
                    int nc = wn * 64 + 8 * nf + g;
                    int kr = (ks * 8 + kk) * PX;
                    uint32 bb0 = __float_as_uint(sXb[kr + nc]);
                    uint32 bb1 = __float_as_uint(sXb[kr + 4 * PX + nc]);
                    uint32 bs0 = __float_as_uint(sXs[kr + nc]);
                    uint32 bs1 = __float_as_uint(sXs[kr + 4 * PX + nc]);
                    #pragma unroll
                    for (int mi = 0; mi < 2; mi++) {
                        mma_tf32(acc[mi][nf], Ab[mi], bb0, bb1);
                        mma_tf32(acc[mi][nf], As[mi], bb0, bb1);
                        mma_tf32(acc[mi][nf], Ab[mi], bs0, bs1);
                    }
                }
            } else {
                #pragma unroll
                for (int nf = 0; nf < 8; nf++) {
                    int nc = wn * 64 + 8 * nf + g;
                    int kr = (ks * 8 + kk) * PX;
                    uint32 bb0 = __float_as_uint(sXb[kr + nc]);
                    uint32 bb1 = __float_as_uint(sXb[kr + 4 * PX + nc]);
                    #pragma unroll
                    for (int mi = 0; mi < 2; mi++) {
                        mma_tf32(acc[mi][nf], Ab[mi], bb0, bb1);
                        mma_tf32(acc[mi][nf], As[mi], bb0, bb1);
                    }
                }
            }
        }
    }

    if (!isV) {
        // direct coalesced-ish stores to g_qk [o][n]
        #pragma unroll
        for (int mi = 0; mi < 2; mi++) {
            int o0 = row0 + wm * 32 + mi * 16 + g;
            int o1 = o0 + 8;
            float b0v = g_ball[o0], b1v = g_ball[o1];
            #pragma unroll
            for (int nf = 0; nf < 8; nf++) {
                int n = col0 + wn * 64 + 8 * nf + 2 * kk;
                *(float2*)&g_qk[((size_t)b * 256 + o0) * 1024 + n] =
                    make_float2(acc[mi][nf][0] + b0v, acc[mi][nf][1] + b0v);
                *(float2*)&g_qk[((size_t)b * 256 + o1) * 1024 + n] =
                    make_float2(acc[mi][nf][2] + b1v, acc[mi][nf][3] + b1v);
            }
        }
    } else {
        // transpose through smem, coalesced stores to g_vt [n][c]
        __syncthreads();
        float* sOut = ps;   // 128 n x 132
        #pragma unroll
        for (int mi = 0; mi < 2; mi++) {
            int o0 = row0 + wm * 32 + mi * 16 + g;
            int ol = wm * 32 + mi * 16 + g;
            float b0v = g_ball[o0], b1v = g_ball[o0 + 8];
            #pragma unroll
            for (int nf = 0; nf < 8; nf++) {
                int n = wn * 64 + 8 * nf + 2 * kk;
                sOut[n * 132 + ol] = acc[mi][nf][0] + b0v;
                sOut[(n + 1) * 132 + ol] = acc[mi][nf][1] + b0v;
                sOut[n * 132 + ol + 8] = acc[mi][nf][2] + b1v;
                sOut[(n + 1) * 132 + ol + 8] = acc[mi][nf][3] + b1v;
            }
        }
        __syncthreads();
        int hh = (row0 - 256) >> 7;
        float* dst = g_vt + (size_t)(b * 4 + hh) * 131072;
        #pragma unroll
        for (int it = 0; it < 16; it++) {
            int i = tid + it * 256;
            int n = i >> 5, c4 = (i & 31) << 2;
            *(float4*)&dst[(size_t)(col0 + n) * 128 + c4] = *(float4*)&sOut[n * 132 + c4];
        }
    }
}

// ---------------- 3.5) prep: fragment-ready K'/V tile images ----------------
// K image: float4 (Kb[r], Kb[r+4], Ks[r], Ks[r+4]) at [dp][n], dp=4ks+kk (r=8ks+kk), stride 66
// V image: float2 (V[r], V[r+4]) at [dp][c], stride 132. Both tf32-RN-rounded.
__global__ __launch_bounds__(256) void prep_kernel() {
    int nt = blockIdx.x, h = blockIdx.y, b = blockIdx.z;
    int tid = threadIdx.x;
    int ng = nt * 64;
    size_t qkbase = (size_t)b * 256 * 1024;
    float* dst = g_tile + (size_t)((b * 4 + h) * 16 + nt) * TILE_F;

    #pragma unroll
    for (int it = 0; it < 8; it++) {
        int i = tid + it * 256;
        int dp = i >> 6, n = i & 63;
        int r = ((dp >> 2) << 3) + (dp & 3);
        float v0, v1;
        {
            int d = r;
            v0 = (d < 32) ? g_qk[qkbase + (size_t)(128 + h * 32 + d) * 1024 + ng + n]
                          : g_qk[qkbase + (size_t)(h * 32 + d - 32) * 1024 + ng + n];
        }
        {
            int d = r + 4;
            v1 = (d < 32) ? g_qk[qkbase + (size_t)(128 + h * 32 + d) * 1024 + ng + n]
                          : g_qk[qkbase + (size_t)(h * 32 + d - 32) * 1024 + ng + n];
        }
        float b0, s0, b1, s1;
        split_tf32(v0, b0, s0);
        split_tf32(v1, b1, s1);
        ((float4*)dst)[dp * 66 + n] = make_float4(b0, b1, s0, s1);
    }

    const float* vb = g_vt + (size_t)(b * 4 + h) * 131072;
    float* dv = dst + 8448;
    #pragma unroll
    for (int it = 0; it < 16; it++) {
        int i = tid + it * 256;
        int dp = i >> 7, c = i & 127;
        int r = ((dp >> 2) << 3) + (dp & 3);
        float v0 = tf2f(f2tf(vb[(size_t)(ng + r) * 128 + c]));
        float v1 = tf2f(f2tf(vb[(size_t)(ng + r + 4) * 128 + c]));
        ((float2*)dv)[dp * 132 + c] = make_float2(v0, v1);
    }
}

// ---------------- 4) flash attention: cp.async tiles + fragment-ready smem ----------------
// smem: buf0 @0 (17408), buf1 @17408; sP/sQ-staging @34816 (8 warps x 1216)
#define AOFF_SP (2 * TILE_F)
#define ATTN_SMEM_FLOATS (2 * TILE_F + 8 * 16 * 76)   // 44544 floats = 178176 B

__global__ __launch_bounds__(256, 1) void attn_kernel(const float* __restrict__ x,
                                                      float* __restrict__ out)
{
    extern __shared__ float sm[];
    int mt = blockIdx.x, h = blockIdx.y, b = blockIdx.z;
    int tid = threadIdx.x, w = tid >> 5, lane = tid & 31;
    int g = lane >> 2, kk = lane & 3;
    int mg = mt * 128;
    int rl = 16 * w + g, rh = rl + 8;
    size_t qkbase = (size_t)b * 256 * 1024;
    const float* tbase = g_tile + (size_t)((b * 4 + h) * 16) * TILE_F;
    float* sP = sm + AOFF_SP + w * 1216;

    // prologue: start tile-0 copy, stage Q' (transposed) into the sP area
    cp_tile(sm, tbase, tid);
    CP_COMMIT();

    float* sQ = sm + AOFF_SP;
    #pragma unroll
    for (int it = 0; it < 8; it++) {
        int i = tid + it * 256;   // 2048 float4 units: 64 d x 32 m4
        int d = i >> 5, m4 = (i & 31) << 2;
        const float* src = (d < 32)
            ? &g_qk[qkbase + (size_t)(h * 32 + d) * 1024 + mg + m4]
            : &g_pos[(size_t)(h * 32 + (d - 32)) * 1024 + mg + m4];
        float4 v = *(const float4*)src;
        sQ[(m4 + 0) * 68 + d] = v.x;
        sQ[(m4 + 1) * 68 + d] = v.y;
        sQ[(m4 + 2) * 68 + d] = v.z;
        sQ[(m4 + 3) * 68 + d] = v.w;
    }
    __syncthreads();

    uint32 Qb[32], Qs[32];
    #pragma unroll
    for (int ks = 0; ks < 8; ks++) {
        int c = 8 * ks + kk;
        float v0 = sQ[rl * 68 + c];
        float v1 = sQ[rh * 68 + c];
        float v2 = sQ[rl * 68 + c + 4];
        float v3 = sQ[rh * 68 + c + 4];
        Qb[4 * ks + 0] = f2tf(v0); Qs[4 * ks + 0] = f2tf(v0 - tf2f(Qb[4 * ks + 0]));
        Qb[4 * ks + 1] = f2tf(v1); Qs[4 * ks + 1] = f2tf(v1 - tf2f(Qb[4 * ks + 1]));
        Qb[4 * ks + 2] = f2tf(v2); Qs[4 * ks + 2] = f2tf(v2 - tf2f(Qb[4 * ks + 2]));
        Qb[4 * ks + 3] = f2tf(v3); Qs[4 * ks + 3] = f2tf(v3 - tf2f(Qb[4 * ks + 3]));
    }
    float m_l = -1e30f, m_h = -1e30f, l_l = 0.f, l_h = 0.f;
    float O[16][4];
    #pragma unroll
    for (int cf = 0; cf < 16; cf++)
        #pragma unroll
        for (int j = 0; j < 4; j++) O[cf][j] = 0.f;

    CP_WAIT0();
    __syncthreads();   // tile0 visible; Q extraction complete before P writes

    for (int nt = 0; nt < 16; nt++) {
        float* buf = sm + (nt & 1) * TILE_F;
        if (nt < 15) {
            cp_tile(sm + ((nt + 1) & 1) * TILE_F, tbase + (size_t)(nt + 1) * TILE_F, tid);
            CP_COMMIT();
        }
        const float4* cKf = (const float4*)buf;
        const float2* cVf = (const float2*)(buf + 8448);

        // ---- S = Q'^T K' (3xTF32) ----
        float S[8][4];
        #pragma unroll
        for (int f = 0; f < 8; f++)
            #pragma unroll
            for (int j = 0; j < 4; j++) S[f][j] = 0.f;
        #pragma unroll
        for (int ks = 0; ks < 8; ks++) {
            const float4* kr = cKf + (4 * ks + kk) * 66 + g;
            #pragma unroll
            for (int f = 0; f < 8; f++) {
                float4 kb = kr[8 * f];
                uint32 bb0 = __float_as_uint(kb.x);
                uint32 bb1 = __float_as_uint(kb.y);
                uint32 bs0 = __float_as_uint(kb.z);
                uint32 bs1 = __float_as_uint(kb.w);
                mma_tf32(S[f], &Qb[4 * ks], bb0, bb1);
                mma_tf32(S[f], &Qs[4 * ks], bb0, bb1);
                mma_tf32(S[f], &Qb[4 * ks], bs0, bs1);
            }
        }

        // ---- warp-local online softmax ----
        float mlo = -1e30f, mhi = -1e30f;
        #pragma unroll
        for (int f = 0; f < 8; f++) {
            mlo = fmaxf(mlo, fmaxf(S[f][0], S[f][1]));
            mhi = fmaxf(mhi, fmaxf(S[f][2], S[f][3]));
        }
        mlo = fmaxf(mlo, __shfl_xor_sync(0xffffffffu, mlo, 1));
        mlo = fmaxf(mlo, __shfl_xor_sync(0xffffffffu, mlo, 2));
        mhi = fmaxf(mhi, __shfl_xor_sync(0xffffffffu, mhi, 1));
        mhi = fmaxf(mhi, __shfl_xor_sync(0xffffffffu, mhi, 2));
        float mnl = fmaxf(m_l, mlo), mnh = fmaxf(m_h, mhi);
        float scl = __expf(m_l - mnl), sch = __expf(m_h - mnh);
        m_l = mnl; m_h = mnh;
        float slo = 0.f, shi = 0.f;
        #pragma unroll
        for (int f = 0; f < 8; f++) {
            float p0 = __expf(S[f][0] - mnl);
            float p1 = __expf(S[f][1] - mnl);
            float p2 = __expf(S[f][2] - mnh);
            float p3 = __expf(S[f][3] - mnh);
            slo += p0 + p1;
            shi += p2 + p3;
            int col = 8 * f + 2 * kk;
            *(float2*)&sP[g * 76 + col] = make_float2(tf2f(f2tf(p0)), tf2f(f2tf(p1)));
            *(float2*)&sP[(g + 8) * 76 + col] = make_float2(tf2f(f2tf(p2)), tf2f(f2tf(p3)));
        }
        slo += __shfl_xor_sync(0xffffffffu, slo, 1);
        slo += __shfl_xor_sync(0xffffffffu, slo, 2);
        shi += __shfl_xor_sync(0xffffffffu, shi, 1);
        shi += __shfl_xor_sync(0xffffffffu, shi, 2);
        l_l = l_l * scl + slo;
        l_h = l_h * sch + shi;
        __syncwarp();

        // ---- rescale O, then O += P * V ----
        #pragma unroll
        for (int cf = 0; cf < 16; cf++) {
            O[cf][0] *= scl; O[cf][1] *= scl;
            O[cf][2] *= sch; O[cf][3] *= sch;
        }
        #pragma unroll
        for (int ks = 0; ks < 8; ks++) {
            uint32 a[4];
            int col = 8 * ks + kk;
            a[0] = __float_as_uint(sP[g * 76 + col]);
            a[1] = __float_as_uint(sP[(g + 8) * 76 + col]);
            a[2] = __float_as_uint(sP[g * 76 + col + 4]);
            a[3] = __float_as_uint(sP[(g + 8) * 76 + col + 4]);
            const float2* vr = cVf + (4 * ks + kk) * 132 + g;
            #pragma unroll
            for (int cf = 0; cf < 16; cf++) {
                float2 v2 = vr[8 * cf];
                mma_tf32(O[cf], a, __float_as_uint(v2.x), __float_as_uint(v2.y));
            }
        }
        if (nt < 15) {
            CP_WAIT0();
            __syncthreads();
        }
    }

    // ---- normalize, stage [m][130] in buf0, coalesced out = O + x ----
    float il = 1.0f / l_l, ih = 1.0f / l_h;
    float* sO = sm;   // buf0: last compute tile was buf1; rows are warp-disjoint
    #pragma unroll
    for (int cf = 0; cf < 16; cf++) {
        int col = 8 * cf + 2 * kk;
        *(float2*)&sO[rl * 130 + col] = make_float2(O[cf][0] * il, O[cf][1] * il);
        *(float2*)&sO[rh * 130 + col] = make_float2(O[cf][2] * ih, O[cf][3] * ih);
    }
    __syncthreads();
    {
        int m = tid & 127;
        int c0 = (tid >> 7) * 64;
        #pragma unroll 4
        for (int k2 = 0; k2 < 64; k2++) {
            int c = c0 + k2;
            size_t a = ((size_t)b * 512 + h * 128 + c) * 1024 + mg + m;
            out[a] = sO[m * 130 + c] + x[a];
        }
    }
}

// ---------------- launch ----------------
extern "C" void kernel_launch(void* const* d_in, const int* in_sizes, int n_in,
                              void* d_out, int out_size)
{
    const float* x     = (const float*)d_in[0];
    const float* Wq    = (const float*)d_in[1];
    const float* bq    = (const float*)d_in[2];
    const float* qg    = (const float*)d_in[3];
    const float* qb    = (const float*)d_in[4];
    const float* qm    = (const float*)d_in[5];
    const float* qv    = (const float*)d_in[6];
    const float* Wk    = (const float*)d_in[7];
    const float* bk    = (const float*)d_in[8];
    const float* kg    = (const float*)d_in[9];
    const float* kb    = (const float*)d_in[10];
    const float* km    = (const float*)d_in[11];
    const float* kv    = (const float*)d_in[12];
    const float* Wv    = (const float*)d_in[13];
    const float* bv    = (const float*)d_in[14];
    const float* vg    = (const float*)d_in[15];
    const float* vb    = (const float*)d_in[16];
    const float* vm    = (const float*)d_in[17];
    const float* vvar  = (const float*)d_in[18];
    const float* rel_h = (const float*)d_in[19];
    const float* rel_w = (const float*)d_in[20];
    float* out = (float*)d_out;

    cudaFuncSetAttribute(attn_kernel, cudaFuncAttributeMaxDynamicSharedMemorySize,
                         ATTN_SMEM_FLOATS * (int)sizeof(float));
    cudaFuncSetAttribute(proj_kernel, cudaFuncAttributeMaxDynamicSharedMemorySize,
                         PROJ_SMEM_FLOATS * (int)sizeof(float));

    fold_kernel<<<768, 256>>>(Wq, bq, qg, qb, qm, qv,
                              Wk, bk, kg, kb, km, kv,
                              Wv, bv, vg, vb, vm, vvar);
    pos_kernel<<<512, 256>>>(rel_h, rel_w);
    proj_kernel<<<dim3(8, 6, 16), 256, PROJ_SMEM_FLOATS * sizeof(float)>>>(x);
    prep_kernel<<<dim3(16, 4, 16), 256>>>();
    attn_kernel<<<dim3(8, 4, 16), 256, ATTN_SMEM_FLOATS * sizeof(float)>>>(x, out);
}

// round 6
// speedup vs baseline: 2.3415x; 1.1020x over previous
#include <cuda_runtime.h>
#include <cuda_bf16.h>

typedef unsigned int uint32;

#define EPS 1e-5f
#define TILE_F 13312   // floats per tile image: K-bf16 4224 + V-f32 8448 + pad 640

// ---------------- scratch (device globals; no cudaMalloc allowed) ----------------
__device__ float g_Wall[768 * 512];     // folded weights: rows 0-127 q, 128-255 k, 256-767 v
__device__ float g_ball[768];           // folded biases
__device__ float g_pos[128 * 1024];     // pos[h*32+d][n]
__device__ float g_qk[16 * 256 * 1024]; // [b][o][n], o<128: q (h*32+d), o in [128,256): k
__device__ float g_vt[16 * 4 * 1024 * 128]; // [b][h][n][c]
__device__ __align__(16) float g_tile[16 * 4 * 16 * TILE_F]; // fragment-ready K'/V tiles

// ---------------- tf32 / bf16 helpers ----------------
__device__ __forceinline__ uint32 f2tf(float x) {
    uint32 r; asm("cvt.rna.tf32.f32 %0, %1;" : "=r"(r) : "f"(x)); return r;
}
__device__ __forceinline__ float tf2f(uint32 x) { return __uint_as_float(x); }

__device__ __forceinline__ void mma_tf32(float* c, const uint32* a, uint32 b0, uint32 b1) {
    asm volatile("mma.sync.aligned.m16n8k8.row.col.f32.tf32.tf32.f32 "
        "{%0,%1,%2,%3}, {%4,%5,%6,%7}, {%8,%9}, {%0,%1,%2,%3};"
        : "+f"(c[0]), "+f"(c[1]), "+f"(c[2]), "+f"(c[3])
        : "r"(a[0]), "r"(a[1]), "r"(a[2]), "r"(a[3]), "r"(b0), "r"(b1));
}

__device__ __forceinline__ void mma_bf16(float* c, const uint32* a, uint32 b0, uint32 b1) {
    asm volatile("mma.sync.aligned.m16n8k16.row.col.f32.bf16.bf16.f32 "
        "{%0,%1,%2,%3}, {%4,%5,%6,%7}, {%8,%9}, {%0,%1,%2,%3};"
        : "+f"(c[0]), "+f"(c[1]), "+f"(c[2]), "+f"(c[3])
        : "r"(a[0]), "r"(a[1]), "r"(a[2]), "r"(a[3]), "r"(b0), "r"(b1));
}

// split v0,v1 into bf16 big/small packed pairs (element0 in low 16 bits)
__device__ __forceinline__ void split2_bf(float v0, float v1, uint32& bb, uint32& ss) {
    float b0 = __bfloat162float(__float2bfloat16_rn(v0));
    float b1 = __bfloat162float(__float2bfloat16_rn(v1));
    __nv_bfloat162 tb = __floats2bfloat162_rn(b0, b1);
    __nv_bfloat162 ts = __floats2bfloat162_rn(v0 - b0, v1 - b1);
    bb = *reinterpret_cast<uint32*>(&tb);
    ss = *reinterpret_cast<uint32*>(&ts);
}

// ---------------- cp.async helpers ----------------
__device__ __forceinline__ void cp_tile(float* smem_dst, const float* gsrc, int tid) {
    uint32 s = (uint32)__cvta_generic_to_shared(smem_dst);
    #pragma unroll
    for (int it = 0; it < 13; it++) {
        int i = tid + it * 256;          // 3328 float4s = 13312 floats
        asm volatile("cp.async.cg.shared.global [%0], [%1], 16;\n"
                     :: "r"(s + i * 16), "l"(gsrc + i * 4));
    }
}
#define CP_COMMIT() asm volatile("cp.async.commit_group;\n" ::: "memory")
#define CP_WAIT0()  asm volatile("cp.async.wait_group 0;\n" ::: "memory")

// ---------------- 1) fold BN into conv weights ----------------
__global__ void fold_kernel(
    const float* __restrict__ Wq, const float* __restrict__ bq,
    const float* __restrict__ qg, const float* __restrict__ qb,
    const float* __restrict__ qm, const float* __restrict__ qvv,
    const float* __restrict__ Wk, const float* __restrict__ bk,
    const float* __restrict__ kg, const float* __restrict__ kb,
    const float* __restrict__ km, const float* __restrict__ kvv,
    const float* __restrict__ Wv, const float* __restrict__ bv,
    const float* __restrict__ vg, const float* __restrict__ vb,
    const float* __restrict__ vm, const float* __restrict__ vvv)
{
    int o = blockIdx.x;  // 0..767
    const float* src;
    float s, bias;
    if (o < 128) {
        s = qg[o] * rsqrtf(qvv[o] + EPS);
        bias = (bq[o] - qm[o]) * s + qb[o];
        src = Wq + o * 512;
    } else if (o < 256) {
        int oo = o - 128;
        s = kg[oo] * rsqrtf(kvv[oo] + EPS);
        bias = (bk[oo] - km[oo]) * s + kb[oo];
        src = Wk + oo * 512;
    } else {
        int oo = o - 256;
        s = vg[oo] * rsqrtf(vvv[oo] + EPS);
        bias = (bv[oo] - vm[oo]) * s + vb[oo];
        src = Wv + oo * 512;
    }
    for (int c = threadIdx.x; c < 512; c += blockDim.x)
        g_Wall[o * 512 + c] = src[c] * s;
    if (threadIdx.x == 0) g_ball[o] = bias;
}

// ---------------- 2) pos[h,d,n] = rel_h[h,d,hh] + rel_w[h,d,w] ----------------
__global__ void pos_kernel(const float* __restrict__ rel_h, const float* __restrict__ rel_w) {
    int idx = blockIdx.x * blockDim.x + threadIdx.x;
    if (idx >= 128 * 1024) return;
    int hd = idx >> 10;
    int n = idx & 1023;
    int w = n >> 5, hh = n & 31;
    g_pos[idx] = rel_h[hd * 32 + hh] + rel_w[hd * 32 + w];
}

// ---------------- 3) QKV projection via mma bf16 (3-term compensated) ----------------
// block tile 128(o) x 128(n), K=512 in slabs of 32 (2 k16 chunks each).
// smem: sW uint2[128][20]  (pair p: .x = big half2(k=2p,2p+1), .y = small)
//       sX uint2[16][132]  (kpair kp at col n: .x = big half2(rows 2kp,2kp+1), .y = small)
#define PROJ_SMEM_FLOATS 16896   // max(sW 5120 + sX 4224 = 9344, isV epilogue 128*132=16896)

__global__ __launch_bounds__(256) void proj_kernel(const float* __restrict__ x) {
    extern __shared__ float ps[];
    uint2* sW = (uint2*)ps;                 // [128][20]
    uint2* sX = (uint2*)(ps + 5120);        // [16][132]
    int b = blockIdx.z, row0 = blockIdx.y * 128, col0 = blockIdx.x * 128;
    bool isV = (row0 >= 256);
    int tid = threadIdx.x, w = tid >> 5, lane = tid & 31;
    int g = lane >> 2, kk = lane & 3;
    int wm = w >> 1, wn = w & 1;
    const float* xb = x + (size_t)b * 512 * 1024;

    float acc[2][8][4];
    #pragma unroll
    for (int mi = 0; mi < 2; mi++)
        #pragma unroll
        for (int nf = 0; nf < 8; nf++)
            #pragma unroll
            for (int j = 0; j < 4; j++) acc[mi][nf][j] = 0.f;

    float4 wreg[4], xr0[2], xr1[2];
    #pragma unroll
    for (int it = 0; it < 4; it++) {
        int i = tid + it * 256;
        wreg[it] = *(const float4*)&g_Wall[(size_t)(row0 + (i >> 3)) * 512 + ((i & 7) << 2)];
    }
    #pragma unroll
    for (int it = 0; it < 2; it++) {
        int i = tid + it * 256;
        int kp = i >> 5, n4 = (i & 31) << 2;
        xr0[it] = *(const float4*)&xb[(size_t)(2 * kp) * 1024 + col0 + n4];
        xr1[it] = *(const float4*)&xb[(size_t)(2 * kp + 1) * 1024 + col0 + n4];
    }

    for (int kt = 0; kt < 16; kt++) {
        __syncthreads();
        // W tile 128m x 32k -> [m][pair] (big,small)
        #pragma unroll
        for (int it = 0; it < 4; it++) {
            int i = tid + it * 256;
            int m = i >> 3, k4 = (i & 7) << 2;
            uint32 b01, s01, b23, s23;
            split2_bf(wreg[it].x, wreg[it].y, b01, s01);
            split2_bf(wreg[it].z, wreg[it].w, b23, s23);
            uint4 val; val.x = b01; val.y = s01; val.z = b23; val.w = s23;
            *(uint4*)&sW[m * 20 + (k4 >> 1)] = val;
        }
        // X tile 32k x 128n -> [kpair][n] (big,small), pairs along k
        #pragma unroll
        for (int it = 0; it < 2; it++) {
            int i = tid + it * 256;
            int kp = i >> 5, n4 = (i & 31) << 2;
            const float* e0 = (const float*)&xr0[it];
            const float* e1 = (const float*)&xr1[it];
            #pragma unroll
            for (int e = 0; e < 4; e++) {
                uint32 bb, ss;
                split2_bf(e0[e], e1[e], bb, ss);
                sX[kp * 132 + n4 + e] = make_uint2(bb, ss);
            }
        }
        __syncthreads();
        if (kt < 15) {
            #pragma unroll
            for (int it = 0; it < 4; it++) {
                int i = tid + it * 256;
                wreg[it] = *(const float4*)&g_Wall[(size_t)(row0 + (i >> 3)) * 512 + (kt + 1) * 32 + ((i & 7) << 2)];
            }
            #pragma unroll
            for (int it = 0; it < 2; it++) {
                int i = tid + it * 256;
                int kp = i >> 5, n4 = (i & 31) << 2;
                xr0[it] = *(const float4*)&xb[(size_t)((kt + 1) * 32 + 2 * kp) * 1024 + col0 + n4];
                xr1[it] = *(const float4*)&xb[(size_t)((kt + 1) * 32 + 2 * kp + 1) * 1024 + col0 + n4];
            }
        }

        #pragma unroll
        for (int kc = 0; kc < 2; kc++) {
            uint32 Ab[2][4], As[2][4];
            #pragma unroll
            for (int mi = 0; mi < 2; mi++) {
                int r = wm * 32 + mi * 16 + g;
                uint2 w0 = sW[r * 20 + kk + 8 * kc];
                uint2 w1 = sW[(r + 8) * 20 + kk + 8 * kc];
                uint2 w2 = sW[r * 20 + kk + 4 + 8 * kc];
                uint2 w3 = sW[(r + 8) * 20 + kk + 4 + 8 * kc];
                Ab[mi][0] = w0.x; Ab[mi][1] = w1.x; Ab[mi][2] = w2.x; Ab[mi][3] = w3.x;
                As[mi][0] = w0.y; As[mi][1] = w1.y; As[mi][2] = w2.y; As[mi][3] = w3.y;
            }
            #pragma unroll
            for (int nf = 0; nf < 8; nf++) {
                int nc = wn * 64 + 8 * nf + g;
                uint2 x0 = sX[(kk + 8 * kc) * 132 + nc];       // rows 2kk,2kk+1
                uint2 x1 = sX[(kk + 4 + 8 * kc) * 132 + nc];   // rows 2kk+8,2kk+9
                #pragma unroll
                for (int mi = 0; mi < 2; mi++) {
                    mma_bf16(acc[mi][nf], Ab[mi], x0.x, x1.x);
                    mma_bf16(acc[mi][nf], As[mi], x0.x, x1.x);
                    mma_bf16(acc[mi][nf], Ab[mi], x0.y, x1.y);
                }
            }
        }
    }

    if (!isV) {
        #pragma unroll
        for (int mi = 0; mi < 2; mi++) {
            int o0 = row0 + wm * 32 + mi * 16 + g;
            int o1 = o0 + 8;
            float b0v = g_ball[o0], b1v = g_ball[o1];
            #pragma unroll
            for (int nf = 0; nf < 8; nf++) {
                int n = col0 + wn * 64 + 8 * nf + 2 * kk;
                *(float2*)&g_qk[((size_t)b * 256 + o0) * 1024 + n] =
                    make_float2(acc[mi][nf][0] + b0v, acc[mi][nf][1] + b0v);
                *(float2*)&g_qk[((size_t)b * 256 + o1) * 1024 + n] =
                    make_float2(acc[mi][nf][2] + b1v, acc[mi][nf][3] + b1v);
            }
        }
    } else {
        // transpose through smem, coalesced stores to g_vt [n][c]
        __syncthreads();
        float* sOut = ps;   // 128 n x 132
        #pragma unroll
        for (int mi = 0; mi < 2; mi++) {
            int o0 = row0 + wm * 32 + mi * 16 + g;
            int ol = wm * 32 + mi * 16 + g;
            float b0v = g_ball[o0], b1v = g_ball[o0 + 8];
            #pragma unroll
            for (int nf = 0; nf < 8; nf++) {
                int n = wn * 64 + 8 * nf + 2 * kk;
                sOut[n * 132 + ol] = acc[mi][nf][0] + b0v;
                sOut[(n + 1) * 132 + ol] = acc[mi][nf][1] + b0v;
                sOut[n * 132 + ol + 8] = acc[mi][nf][2] + b1v;
                sOut[(n + 1) * 132 + ol + 8] = acc[mi][nf][3] + b1v;
            }
        }
        __syncthreads();
        int hh = (row0 - 256) >> 7;
        float* dst = g_vt + (size_t)(b * 4 + hh) * 131072;
        #pragma unroll
        for (int it = 0; it < 16; it++) {
            int i = tid + it * 256;
            int n = i >> 5, c4 = (i & 31) << 2;
            *(float4*)&dst[(size_t)(col0 + n) * 128 + c4] = *(float4*)&sOut[n * 132 + c4];
        }
    }
}

// ---------------- 3.5) prep: fragment-ready K'(bf16 split) / V(tf32) tile images ----------------
// K image: uint4 (Kb01, Kb89, Ks01, Ks89) at [dp][n], dp = 4*kc+kk, stride 66 uint4s.
//   Kb01 = half2(K'[16kc+2kk][n], K'[16kc+2kk+1][n]) big parts; Kb89 rows +8; Ks = smalls.
// V image (offset 4224 floats): float2 (V[r],V[r+4]) at [dp][c], dp=4ks+kk, stride 132 float2s.
__device__ __forceinline__ float kprime(size_t qkbase, int h, int ng, int d, int n) {
    return (d < 32) ? g_qk[qkbase + (size_t)(128 + h * 32 + d) * 1024 + ng + n]
                    : g_qk[qkbase + (size_t)(h * 32 + d - 32) * 1024 + ng + n];
}

__global__ __launch_bounds__(256) void prep_kernel() {
    int nt = blockIdx.x, h = blockIdx.y, b = blockIdx.z;
    int tid = threadIdx.x;
    int ng = nt * 64;
    size_t qkbase = (size_t)b * 256 * 1024;
    float* dst = g_tile + (size_t)((b * 4 + h) * 16 + nt) * TILE_F;

    #pragma unroll
    for (int it = 0; it < 4; it++) {
        int i = tid + it * 256;          // 1024 items: 16 dp x 64 n
        int dp = i >> 6, n = i & 63;
        int kc = dp >> 2, kk = dp & 3;
        int r0 = 16 * kc + 2 * kk;
        float v0 = kprime(qkbase, h, ng, r0, n);
        float v1 = kprime(qkbase, h, ng, r0 + 1, n);
        float v8 = kprime(qkbase, h, ng, r0 + 8, n);
        float v9 = kprime(qkbase, h, ng, r0 + 9, n);
        uint4 o;
        split2_bf(v0, v1, o.x, o.z);
        split2_bf(v8, v9, o.y, o.w);
        ((uint4*)dst)[dp * 66 + n] = o;
    }

    const float* vb = g_vt + (size_t)(b * 4 + h) * 131072;
    float* dv = dst + 4224;
    #pragma unroll
    for (int it = 0; it < 16; it++) {
        int i = tid + it * 256;
        int dp = i >> 7, c = i & 127;
        int r = ((dp >> 2) << 3) + (dp & 3);
        float v0 = tf2f(f2tf(vb[(size_t)(ng + r) * 128 + c]));
        float v1 = tf2f(f2tf(vb[(size_t)(ng + r + 4) * 128 + c]));
        ((float2*)dv)[dp * 132 + c] = make_float2(v0, v1);
    }
}

// ---------------- 4) flash attention: bf16x3 QK + tf32 PV, cp.async double buffer ----------------
#define AOFF_SP (2 * TILE_F)
#define ATTN_SMEM_FLOATS (2 * TILE_F + 8 * 16 * 76)   // 36352 floats = 145408 B

__global__ __launch_bounds__(256, 1) void attn_kernel(const float* __restrict__ x,
                                                      float* __restrict__ out)
{
    extern __shared__ float sm[];
    int mt = blockIdx.x, h = blockIdx.y, b = blockIdx.z;
    int tid = threadIdx.x, w = tid >> 5, lane = tid & 31;
    int g = lane >> 2, kk = lane & 3;
    int mg = mt * 128;
    int rl = 16 * w + g, rh = rl + 8;
    size_t qkbase = (size_t)b * 256 * 1024;
    const float* tbase = g_tile + (size_t)((b * 4 + h) * 16) * TILE_F;
    float* sP = sm + AOFF_SP + w * 1216;

    // prologue: start tile-0 copy, stage Q' (transposed) into the sP area
    cp_tile(sm, tbase, tid);
    CP_COMMIT();

    float* sQ = sm + AOFF_SP;
    #pragma unroll
    for (int it = 0; it < 8; it++) {
        int i = tid + it * 256;   // 2048 float4 units: 64 d x 32 m4
        int d = i >> 5, m4 = (i & 31) << 2;
        const float* src = (d < 32)
            ? &g_qk[qkbase + (size_t)(h * 32 + d) * 1024 + mg + m4]
            : &g_pos[(size_t)(h * 32 + (d - 32)) * 1024 + mg + m4];
        float4 v = *(const float4*)src;
        sQ[(m4 + 0) * 68 + d] = v.x;
        sQ[(m4 + 1) * 68 + d] = v.y;
        sQ[(m4 + 2) * 68 + d] = v.z;
        sQ[(m4 + 3) * 68 + d] = v.w;
    }
    __syncthreads();

    // Q' A-fragments for m16n8k16: Qb/Qs[kc][4]
    uint32 Qb[4][4], Qs[4][4];
    #pragma unroll
    for (int kc = 0; kc < 4; kc++) {
        int klo = 16 * kc + 2 * kk;
        int khi = klo + 8;
        split2_bf(sQ[rl * 68 + klo], sQ[rl * 68 + klo + 1], Qb[kc][0], Qs[kc][0]);
        split2_bf(sQ[rh * 68 + klo], sQ[rh * 68 + klo + 1], Qb[kc][1], Qs[kc][1]);
        split2_bf(sQ[rl * 68 + khi], sQ[rl * 68 + khi + 1], Qb[kc][2], Qs[kc][2]);
        split2_bf(sQ[rh * 68 + khi], sQ[rh * 68 + khi + 1], Qb[kc][3], Qs[kc][3]);
    }
    float m_l = -1e30f, m_h = -1e30f, l_l = 0.f, l_h = 0.f;
    float O[16][4];
    #pragma unroll
    for (int cf = 0; cf < 16; cf++)
        #pragma unroll
        for (int j = 0; j < 4; j++) O[cf][j] = 0.f;

    CP_WAIT0();
    __syncthreads();   // tile0 visible; Q extraction complete before P writes

    for (int nt = 0; nt < 16; nt++) {
        float* buf = sm + (nt & 1) * TILE_F;
        if (nt < 15) {
            cp_tile(sm + ((nt + 1) & 1) * TILE_F, tbase + (size_t)(nt + 1) * TILE_F, tid);
            CP_COMMIT();
        }
        const uint4* cK4 = (const uint4*)buf;
        const float2* cVf = (const float2*)(buf + 4224);

        // ---- S = Q'^T K' (3 x bf16 k16) ----
        float S[8][4];
        #pragma unroll
        for (int f = 0; f < 8; f++)
            #pragma unroll
            for (int j = 0; j < 4; j++) S[f][j] = 0.f;
        #pragma unroll
        for (int kc = 0; kc < 4; kc++) {
            const uint4* kr = cK4 + (4 * kc + kk) * 66 + g;
            #pragma unroll
            for (int f = 0; f < 8; f++) {
                uint4 kb = kr[8 * f];
                mma_bf16(S[f], Qb[kc], kb.x, kb.y);
                mma_bf16(S[f], Qs[kc], kb.x, kb.y);
                mma_bf16(S[f], Qb[kc], kb.z, kb.w);
            }
        }

        // ---- warp-local online softmax ----
        float mlo = -1e30f, mhi = -1e30f;
        #pragma unroll
        for (int f = 0; f < 8; f++) {
            mlo = fmaxf(mlo, fmaxf(S[f][0], S[f][1]));
            mhi = fmaxf(mhi, fmaxf(S[f][2], S[f][3]));
        }
        mlo = fmaxf(mlo, __shfl_xor_sync(0xffffffffu, mlo, 1));
        mlo = fmaxf(mlo, __shfl_xor_sync(0xffffffffu, mlo, 2));
        mhi = fmaxf(mhi, __shfl_xor_sync(0xffffffffu, mhi, 1));
        mhi = fmaxf(mhi, __shfl_xor_sync(0xffffffffu, mhi, 2));
        float mnl = fmaxf(m_l, mlo), mnh = fmaxf(m_h, mhi);
        float scl = __expf(m_l - mnl), sch = __expf(m_h - mnh);
        m_l = mnl; m_h = mnh;
        float slo = 0.f, shi = 0.f;
        #pragma unroll
        for (int f = 0; f < 8; f++) {
            float p0 = __expf(S[f][0] - mnl);
            float p1 = __expf(S[f][1] - mnl);
            float p2 = __expf(S[f][2] - mnh);
            float p3 = __expf(S[f][3] - mnh);
            slo += p0 + p1;
            shi += p2 + p3;
            int col = 8 * f + 2 * kk;
            *(float2*)&sP[g * 76 + col] = make_float2(tf2f(f2tf(p0)), tf2f(f2tf(p1)));
            *(float2*)&sP[(g + 8) * 76 + col] = make_float2(tf2f(f2tf(p2)), tf2f(f2tf(p3)));
        }
        slo += __shfl_xor_sync(0xffffffffu, slo, 1);
        slo += __shfl_xor_sync(0xffffffffu, slo, 2);
        shi += __shfl_xor_sync(0xffffffffu, shi, 1);
        shi += __shfl_xor_sync(0xffffffffu, shi, 2);
        l_l = l_l * scl + slo;
        l_h = l_h * sch + shi;
        __syncwarp();

        // ---- rescale O, then O += P * V (tf32 k8) ----
        #pragma unroll
        for (int cf = 0; cf < 16; cf++) {
            O[cf][0] *= scl; O[cf][1] *= scl;
            O[cf][2] *= sch; O[cf][3] *= sch;
        }
        #pragma unroll
        for (int ks = 0; ks < 8; ks++) {
            uint32 a[4];
            int col = 8 * ks + kk;
            a[0] = __float_as_uint(sP[g * 76 + col]);
            a[1] = __float_as_uint(sP[(g + 8) * 76 + col]);
            a[2] = __float_as_uint(sP[g * 76 + col + 4]);
            a[3] = __float_as_uint(sP[(g + 8) * 76 + col + 4]);
            const float2* vr = cVf + (4 * ks + kk) * 132 + g;
            #pragma unroll
            for (int cf = 0; cf < 16; cf++) {
                float2 v2 = vr[8 * cf];
                mma_tf32(O[cf], a, __float_as_uint(v2.x), __float_as_uint(v2.y));
            }
        }
        if (nt < 15) {
            CP_WAIT0();
            __syncthreads();
        }
    }

    // ---- normalize, stage [m][130] from smem start, coalesced out = O + x ----
    __syncthreads();   // all warps done reading last tile before sO overwrites bufs
    float il = 1.0f / l_l, ih = 1.0f / l_h;
    float* sO = sm;    // spans buf0+buf1 (both dead now)
    #pragma unroll
    for (int cf = 0; cf < 16; cf++) {
        int col = 8 * cf + 2 * kk;
        *(float2*)&sO[rl * 130 + col] = make_float2(O[cf][0] * il, O[cf][1] * il);
        *(float2*)&sO[rh * 130 + col] = make_float2(O[cf][2] * ih, O[cf][3] * ih);
    }
    __syncthreads();
    {
        int m = tid & 127;
        int c0 = (tid >> 7) * 64;
        #pragma unroll 4
        for (int k2 = 0; k2 < 64; k2++) {
            int c = c0 + k2;
            size_t a = ((size_t)b * 512 + h * 128 + c) * 1024 + mg + m;
            out[a] = sO[m * 130 + c] + x[a];
        }
    }
}

// ---------------- launch ----------------
extern "C" void kernel_launch(void* const* d_in, const int* in_sizes, int n_in,
                              void* d_out, int out_size)
{
    const float* x     = (const float*)d_in[0];
    const float* Wq    = (const float*)d_in[1];
    const float* bq    = (const float*)d_in[2];
    const float* qg    = (const float*)d_in[3];
    const float* qb    = (const float*)d_in[4];
    const float* qm    = (const float*)d_in[5];
    const float* qv    = (const float*)d_in[6];
    const float* Wk    = (const float*)d_in[7];
    const float* bk    = (const float*)d_in[8];
    const float* kg    = (const float*)d_in[9];
    const float* kb    = (const float*)d_in[10];
    const float* km    = (const float*)d_in[11];
    const float* kv    = (const float*)d_in[12];
    const float* Wv    = (const float*)d_in[13];
    const float* bv    = (const float*)d_in[14];
    const float* vg    = (const float*)d_in[15];
    const float* vb    = (const float*)d_in[16];
    const float* vm    = (const float*)d_in[17];
    const float* vvar  = (const float*)d_in[18];
    const float* rel_h = (const float*)d_in[19];
    const float* rel_w = (const float*)d_in[20];
    float* out = (float*)d_out;

    cudaFuncSetAttribute(attn_kernel, cudaFuncAttributeMaxDynamicSharedMemorySize,
                         ATTN_SMEM_FLOATS * (int)sizeof(float));
    cudaFuncSetAttribute(proj_kernel, cudaFuncAttributeMaxDynamicSharedMemorySize,
                         PROJ_SMEM_FLOATS * (int)sizeof(float));

    fold_kernel<<<768, 256>>>(Wq, bq, qg, qb, qm, qv,
                              Wk, bk, kg, kb, km, kv,
                              Wv, bv, vg, vb, vm, vvar);
    pos_kernel<<<512, 256>>>(rel_h, rel_w);
    proj_kernel<<<dim3(8, 6, 16), 256, PROJ_SMEM_FLOATS * sizeof(float)>>>(x);
    prep_kernel<<<dim3(16, 4, 16), 256>>>();
    attn_kernel<<<dim3(8, 4, 16), 256, ATTN_SMEM_FLOATS * sizeof(float)>>>(x, out);
}

// round 7
// speedup vs baseline: 3.1924x; 1.3634x over previous
#include <cuda_runtime.h>
#include <cuda_bf16.h>
#include <cuda_fp16.h>

typedef unsigned int uint32;

#define EPS 1e-5f
#define TILE_F 9216    // floats per tile image: K-bf16split 4224 + V-fp16 4224 + pad

// ---------------- scratch (device globals; no cudaMalloc allowed) ----------------
__device__ float g_ball[768];               // folded biases
__device__ float g_pos[128 * 1024];         // pos[h*32+d][n]
__device__ float g_qk[16 * 256 * 1024];     // [b][o][n], o<128: q, o in [128,256): k
__device__ float g_vt[16 * 4 * 1024 * 128]; // [b][h][n][c]
__device__ __align__(16) uint2 g_Wbs[768 * 256];        // W big/small bf16 pairs [o][kpair]
__device__ __align__(16) uint2 g_Xbs[16 * 256 * 1024];  // X big/small bf16 pairs [b][kpair][n]
__device__ __align__(16) float g_tile[16 * 4 * 16 * TILE_F]; // fragment-ready K'/V tiles

// ---------------- mma / pack helpers ----------------
__device__ __forceinline__ void mma_bf16(float* c, const uint32* a, uint32 b0, uint32 b1) {
    asm volatile("mma.sync.aligned.m16n8k16.row.col.f32.bf16.bf16.f32 "
        "{%0,%1,%2,%3}, {%4,%5,%6,%7}, {%8,%9}, {%0,%1,%2,%3};"
        : "+f"(c[0]), "+f"(c[1]), "+f"(c[2]), "+f"(c[3])
        : "r"(a[0]), "r"(a[1]), "r"(a[2]), "r"(a[3]), "r"(b0), "r"(b1));
}
__device__ __forceinline__ void mma_fp16(float* c, const uint32* a, uint32 b0, uint32 b1) {
    asm volatile("mma.sync.aligned.m16n8k16.row.col.f32.f16.f16.f32 "
        "{%0,%1,%2,%3}, {%4,%5,%6,%7}, {%8,%9}, {%0,%1,%2,%3};"
        : "+f"(c[0]), "+f"(c[1]), "+f"(c[2]), "+f"(c[3])
        : "r"(a[0]), "r"(a[1]), "r"(a[2]), "r"(a[3]), "r"(b0), "r"(b1));
}

// split v0,v1 into bf16 big/small packed pairs (element0 in low 16 bits)
__device__ __forceinline__ void split2_bf(float v0, float v1, uint32& bb, uint32& ss) {
    float b0 = __bfloat162float(__float2bfloat16_rn(v0));
    float b1 = __bfloat162float(__float2bfloat16_rn(v1));
    __nv_bfloat162 tb = __floats2bfloat162_rn(b0, b1);
    __nv_bfloat162 ts = __floats2bfloat162_rn(v0 - b0, v1 - b1);
    bb = *reinterpret_cast<uint32*>(&tb);
    ss = *reinterpret_cast<uint32*>(&ts);
}
__device__ __forceinline__ uint32 pack_h2(float v0, float v1) {
    __half2 h = __floats2half2_rn(v0, v1);
    return *reinterpret_cast<uint32*>(&h);
}
__device__ __forceinline__ float ex2f(float x) {
    float r; asm("ex2.approx.ftz.f32 %0, %1;" : "=f"(r) : "f"(x)); return r;
}

// ---------------- cp.async helpers ----------------
__device__ __forceinline__ void cp16(uint32 sdst, const void* gsrc) {
    asm volatile("cp.async.cg.shared.global [%0], [%1], 16;\n" :: "r"(sdst), "l"(gsrc));
}
#define CP_COMMIT() asm volatile("cp.async.commit_group;\n" ::: "memory")
#define CP_WAIT0()  asm volatile("cp.async.wait_group 0;\n" ::: "memory")

__device__ __forceinline__ void cp_tile(float* smem_dst, const float* gsrc, int tid) {
    uint32 s = (uint32)__cvta_generic_to_shared(smem_dst);
    #pragma unroll
    for (int it = 0; it < 9; it++) {
        int i = tid + it * 256;          // 2304 float4s = 9216 floats
        cp16(s + i * 16, gsrc + i * 4);
    }
}

// ---------------- 1) fold BN into conv weights; write pre-split bf16 image ----------------
__global__ void fold_kernel(
    const float* __restrict__ Wq, const float* __restrict__ bq,
    const float* __restrict__ qg, const float* __restrict__ qb,
    const float* __restrict__ qm, const float* __restrict__ qvv,
    const float* __restrict__ Wk, const float* __restrict__ bk,
    const float* __restrict__ kg, const float* __restrict__ kb,
    const float* __restrict__ km, const float* __restrict__ kvv,
    const float* __restrict__ Wv, const float* __restrict__ bv,
    const float* __restrict__ vg, const float* __restrict__ vb,
    const float* __restrict__ vm, const float* __restrict__ vvv)
{
    int o = blockIdx.x;  // 0..767
    const float* src;
    float s, bias;
    if (o < 128) {
        s = qg[o] * rsqrtf(qvv[o] + EPS);
        bias = (bq[o] - qm[o]) * s + qb[o];
        src = Wq + o * 512;
    } else if (o < 256) {
        int oo = o - 128;
        s = kg[oo] * rsqrtf(kvv[oo] + EPS);
        bias = (bk[oo] - km[oo]) * s + kb[oo];
        src = Wk + oo * 512;
    } else {
        int oo = o - 256;
        s = vg[oo] * rsqrtf(vvv[oo] + EPS);
        bias = (bv[oo] - vm[oo]) * s + vb[oo];
        src = Wv + oo * 512;
    }
    int p = threadIdx.x;           // pair 0..255
    float w0 = src[2 * p] * s;
    float w1 = src[2 * p + 1] * s;
    uint32 bb, ss;
    split2_bf(w0, w1, bb, ss);
    g_Wbs[o * 256 + p] = make_uint2(bb, ss);
    if (p == 0) g_ball[o] = bias;
}

// ---------------- 2) pos[h,d,n] = rel_h[h,d,hh] + rel_w[h,d,w] ----------------
__global__ void pos_kernel(const float* __restrict__ rel_h, const float* __restrict__ rel_w) {
    int idx = blockIdx.x * blockDim.x + threadIdx.x;
    if (idx >= 128 * 1024) return;
    int hd = idx >> 10;
    int n = idx & 1023;
    int w = n >> 5, hh = n & 31;
    g_pos[idx] = rel_h[hd * 32 + hh] + rel_w[hd * 32 + w];
}

// ---------------- 2.5) pre-split X into bf16 big/small pair image ----------------
// g_Xbs[b][kp][n]: .x = bf16x2(x[2kp][n], x[2kp+1][n]) big, .y = small
__global__ __launch_bounds__(256) void xsplit_kernel(const float* __restrict__ x) {
    int kp = blockIdx.x, b = blockIdx.y;
    int tid = threadIdx.x;
    const float* r0 = x + ((size_t)b * 512 + 2 * kp) * 1024;
    const float* r1 = r0 + 1024;
    uint2* dst = g_Xbs + ((size_t)b * 256 + kp) * 1024;
    int n4 = tid * 4;
    float4 a = *(const float4*)&r0[n4];
    float4 c = *(const float4*)&r1[n4];
    uint2 o0, o1, o2, o3;
    split2_bf(a.x, c.x, o0.x, o0.y);
    split2_bf(a.y, c.y, o1.x, o1.y);
    split2_bf(a.z, c.z, o2.x, o2.y);
    split2_bf(a.w, c.w, o3.x, o3.y);
    dst[n4] = o0; dst[n4 + 1] = o1; dst[n4 + 2] = o2; dst[n4 + 3] = o3;
}

// ---------------- 3) QKV projection: pure cp.async + bf16x3 mma ----------------
// smem per buffer (uint2): sW [128][20] (2560) + sX [16][132] (2112) = 4672
#define PB_U2 4672
#define PROJ_SMEM_FLOATS (2 * PB_U2 * 2)   // 18688 floats = 74752 B

__device__ __forceinline__ void cp_proj(uint2* buf, int b, int row0, int col0, int kt, int tid) {
    uint32 s = (uint32)__cvta_generic_to_shared(buf);
    #pragma unroll
    for (int it = 0; it < 4; it++) {          // W: 1024 16B-chunks
        int i = tid + it * 256;
        int m = i >> 3, c = i & 7;
        cp16(s + (m * 20 + 2 * c) * 8, g_Wbs + (size_t)(row0 + m) * 256 + kt * 16 + 2 * c);
    }
    #pragma unroll
    for (int it = 0; it < 4; it++) {          // X: 1024 16B-chunks
        int i = tid + it * 256;
        int kp = i >> 6, c = i & 63;
        cp16(s + (2560 + kp * 132 + 2 * c) * 8,
             g_Xbs + ((size_t)b * 256 + kt * 16 + kp) * 1024 + col0 + 2 * c);
    }
}

__global__ __launch_bounds__(256) void proj_kernel() {
    extern __shared__ float ps[];
    uint2* sbase = (uint2*)ps;
    int b = blockIdx.z, row0 = blockIdx.y * 128, col0 = blockIdx.x * 128;
    bool isV = (row0 >= 256);
    int tid = threadIdx.x, w = tid >> 5, lane = tid & 31;
    int g = lane >> 2, kk = lane & 3;
    int wm = w >> 1, wn = w & 1;

    float acc[2][8][4];
    #pragma unroll
    for (int mi = 0; mi < 2; mi++)
        #pragma unroll
        for (int nf = 0; nf < 8; nf++)
            #pragma unroll
            for (int j = 0; j < 4; j++) acc[mi][nf][j] = 0.f;

    cp_proj(sbase, b, row0, col0, 0, tid);
    CP_COMMIT();
    CP_WAIT0();
    __syncthreads();

    for (int kt = 0; kt < 16; kt++) {
        uint2* cur = sbase + (kt & 1) * PB_U2;
        if (kt < 15) {
            cp_proj(sbase + ((kt + 1) & 1) * PB_U2, b, row0, col0, kt + 1, tid);
            CP_COMMIT();
        }
        uint2* sW = cur;
        uint2* sX = cur + 2560;

        #pragma unroll
        for (int kc = 0; kc < 2; kc++) {
            uint32 Ab[2][4], As[2][4];
            #pragma unroll
            for (int mi = 0; mi < 2; mi++) {
                int r = wm * 32 + mi * 16 + g;
                uint2 w0 = sW[r * 20 + kk + 8 * kc];
                uint2 w1 = sW[(r + 8) * 20 + kk + 8 * kc];
                uint2 w2 = sW[r * 20 + kk + 4 + 8 * kc];
                uint2 w3 = sW[(r + 8) * 20 + kk + 4 + 8 * kc];
                Ab[mi][0] = w0.x; Ab[mi][1] = w1.x; Ab[mi][2] = w2.x; Ab[mi][3] = w3.x;
                As[mi][0] = w0.y; As[mi][1] = w1.y; As[mi][2] = w2.y; As[mi][3] = w3.y;
            }
            #pragma unroll
            for (int nf = 0; nf < 8; nf++) {
                int nc = wn * 64 + 8 * nf + g;
                uint2 x0 = sX[(kk + 8 * kc) * 132 + nc];       // k rows 2kk,2kk+1
                uint2 x1 = sX[(kk + 4 + 8 * kc) * 132 + nc];   // k rows 2kk+8,2kk+9
                #pragma unroll
                for (int mi = 0; mi < 2; mi++) {
                    mma_bf16(acc[mi][nf], Ab[mi], x0.x, x1.x);
                    mma_bf16(acc[mi][nf], As[mi], x0.x, x1.x);
                    mma_bf16(acc[mi][nf], Ab[mi], x0.y, x1.y);
                }
            }
        }
        if (kt < 15) {
            CP_WAIT0();
            __syncthreads();
        }
    }

    if (!isV) {
        #pragma unroll
        for (int mi = 0; mi < 2; mi++) {
            int o0 = row0 + wm * 32 + mi * 16 + g;
            int o1 = o0 + 8;
            float b0v = g_ball[o0], b1v = g_ball[o1];
            #pragma unroll
            for (int nf = 0; nf < 8; nf++) {
                int n = col0 + wn * 64 + 8 * nf + 2 * kk;
                *(float2*)&g_qk[((size_t)b * 256 + o0) * 1024 + n] =
                    make_float2(acc[mi][nf][0] + b0v, acc[mi][nf][1] + b0v);
                *(float2*)&g_qk[((size_t)b * 256 + o1) * 1024 + n] =
                    make_float2(acc[mi][nf][2] + b1v, acc[mi][nf][3] + b1v);
            }
        }
    } else {
        // transpose through smem, coalesced stores to g_vt [n][c]
        __syncthreads();
        float* sOut = ps;   // 128 n x 132
        #pragma unroll
        for (int mi = 0; mi < 2; mi++) {
            int o0 = row0 + wm * 32 + mi * 16 + g;
            int ol = wm * 32 + mi * 16 + g;
            float b0v = g_ball[o0], b1v = g_ball[o0 + 8];
            #pragma unroll
            for (int nf = 0; nf < 8; nf++) {
                int n = wn * 64 + 8 * nf + 2 * kk;
                sOut[n * 132 + ol] = acc[mi][nf][0] + b0v;
                sOut[(n + 1) * 132 + ol] = acc[mi][nf][1] + b0v;
                sOut[n * 132 + ol + 8] = acc[mi][nf][2] + b1v;
                sOut[(n + 1) * 132 + ol + 8] = acc[mi][nf][3] + b1v;
            }
        }
        __syncthreads();
        int hh = (row0 - 256) >> 7;
        float* dst = g_vt + (size_t)(b * 4 + hh) * 131072;
        #pragma unroll
        for (int it = 0; it < 16; it++) {
            int i = tid + it * 256;
            int n = i >> 5, c4 = (i & 31) << 2;
            *(float4*)&dst[(size_t)(col0 + n) * 128 + c4] = *(float4*)&sOut[n * 132 + c4];
        }
    }
}

// ---------------- 3.5) prep: fragment-ready K'(bf16 split) / V(fp16) tile images ----------------
// K image: uint4 (Kb01, Kb89, Ks01, Ks89) at [dp][n], dp=4kc+kk, stride 66 uint4s (4224 floats).
// V image at +4224 floats: uint2 (h2(v[16kc+2kk],v[+1]), h2(v[+8],v[+9])) at [dp][c], stride 132.
__device__ __forceinline__ float kprime(size_t qkbase, int h, int ng, int d, int n) {
    return (d < 32) ? g_qk[qkbase + (size_t)(128 + h * 32 + d) * 1024 + ng + n]
                    : g_qk[qkbase + (size_t)(h * 32 + d - 32) * 1024 + ng + n];
}

__global__ __launch_bounds__(256) void prep_kernel() {
    int nt = blockIdx.x, h = blockIdx.y, b = blockIdx.z;
    int tid = threadIdx.x;
    int ng = nt * 64;
    size_t qkbase = (size_t)b * 256 * 1024;
    float* dst = g_tile + (size_t)((b * 4 + h) * 16 + nt) * TILE_F;

    #pragma unroll
    for (int it = 0; it < 4; it++) {
        int i = tid + it * 256;          // 1024 items: 16 dp x 64 n
        int dp = i >> 6, n = i & 63;
        int kc = dp >> 2, kk = dp & 3;
        int r0 = 16 * kc + 2 * kk;
        float v0 = kprime(qkbase, h, ng, r0, n);
        float v1 = kprime(qkbase, h, ng, r0 + 1, n);
        float v8 = kprime(qkbase, h, ng, r0 + 8, n);
        float v9 = kprime(qkbase, h, ng, r0 + 9, n);
        uint4 o;
        split2_bf(v0, v1, o.x, o.z);
        split2_bf(v8, v9, o.y, o.w);
        ((uint4*)dst)[dp * 66 + n] = o;
    }

    const float* vb = g_vt + (size_t)(b * 4 + h) * 131072;
    uint2* dv = (uint2*)(dst + 4224);
    #pragma unroll
    for (int it = 0; it < 8; it++) {
        int i = tid + it * 256;          // 2048 items: 16 dp x 128 c
        int dp = i >> 7, c = i & 127;
        int kc = dp >> 2, kk = dp & 3;
        int r0 = 16 * kc + 2 * kk;
        float v00 = vb[(size_t)(ng + r0) * 128 + c];
        float v01 = vb[(size_t)(ng + r0 + 1) * 128 + c];
        float v10 = vb[(size_t)(ng + r0 + 8) * 128 + c];
        float v11 = vb[(size_t)(ng + r0 + 9) * 128 + c];
        dv[dp * 132 + c] = make_uint2(pack_h2(v00, v01), pack_h2(v10, v11));
    }
}

// ---------------- 4) flash attention: bf16x3 QK + fp16 PV (P in regs) ----------------
#define ATTN_SMEM_FLOATS (2 * TILE_F)   // 18432 floats = 73728 B

__global__ __launch_bounds__(256, 1) void attn_kernel(const float* __restrict__ x,
                                                      float* __restrict__ out)
{
    extern __shared__ float sm[];
    int mt = blockIdx.x, h = blockIdx.y, b = blockIdx.z;
    int tid = threadIdx.x, w = tid >> 5, lane = tid & 31;
    int g = lane >> 2, kk = lane & 3;
    int mg = mt * 128;
    int rl = 16 * w + g, rh = rl + 8;
    size_t qkbase = (size_t)b * 256 * 1024;
    const float* tbase = g_tile + (size_t)((b * 4 + h) * 16) * TILE_F;

    // prologue: start tile-0 copy into buf0; stage Q' (transposed, log2e-scaled) in buf1
    cp_tile(sm, tbase, tid);
    CP_COMMIT();

    float* sQ = sm + TILE_F;   // buf1, 8704 <= 9216 floats
    #pragma unroll
    for (int it = 0; it < 8; it++) {
        int i = tid + it * 256;   // 2048 float4 units: 64 d x 32 m4
        int d = i >> 5, m4 = (i & 31) << 2;
        const float* src = (d < 32)
            ? &g_qk[qkbase + (size_t)(h * 32 + d) * 1024 + mg + m4]
            : &g_pos[(size_t)(h * 32 + (d - 32)) * 1024 + mg + m4];
        float4 v = *(const float4*)src;
        sQ[(m4 + 0) * 68 + d] = v.x;
        sQ[(m4 + 1) * 68 + d] = v.y;
        sQ[(m4 + 2) * 68 + d] = v.z;
        sQ[(m4 + 3) * 68 + d] = v.w;
    }
    __syncthreads();

    // Q' A-fragments (log2e-scaled, bf16 big+small)
    const float LOG2E = 1.4426950408889634f;
    uint32 Qb[4][4], Qs[4][4];
    #pragma unroll
    for (int kc = 0; kc < 4; kc++) {
        int klo = 16 * kc + 2 * kk;
        int khi = klo + 8;
        split2_bf(LOG2E * sQ[rl * 68 + klo], LOG2E * sQ[rl * 68 + klo + 1], Qb[kc][0], Qs[kc][0]);
        split2_bf(LOG2E * sQ[rh * 68 + klo], LOG2E * sQ[rh * 68 + klo + 1], Qb[kc][1], Qs[kc][1]);
        split2_bf(LOG2E * sQ[rl * 68 + khi], LOG2E * sQ[rl * 68 + khi + 1], Qb[kc][2], Qs[kc][2]);
        split2_bf(LOG2E * sQ[rh * 68 + khi], LOG2E * sQ[rh * 68 + khi + 1], Qb[kc][3], Qs[kc][3]);
    }
    float m_l = -1e30f, m_h = -1e30f, l_l = 0.f, l_h = 0.f;
    float O[16][4];
    #pragma unroll
    for (int cf = 0; cf < 16; cf++)
        #pragma unroll
        for (int j = 0; j < 4; j++) O[cf][j] = 0.f;

    CP_WAIT0();
    __syncthreads();   // tile0 visible; all warps done with sQ (buf1)

    for (int nt = 0; nt < 16; nt++) {
        float* buf = sm + (nt & 1) * TILE_F;
        if (nt < 15) {
            cp_tile(sm + ((nt + 1) & 1) * TILE_F, tbase + (size_t)(nt + 1) * TILE_F, tid);
            CP_COMMIT();
        }
        const uint4* cK4 = (const uint4*)buf;
        const uint2* cV2 = (const uint2*)(buf + 4224);

        // ---- S = Q'^T K' (3 x bf16 k16), log2 domain ----
        float S[8][4];
        #pragma unroll
        for (int f = 0; f < 8; f++)
            #pragma unroll
            for (int j = 0; j < 4; j++) S[f][j] = 0.f;
        #pragma unroll
        for (int kc = 0; kc < 4; kc++) {
            const uint4* kr = cK4 + (4 * kc + kk) * 66 + g;
            #pragma unroll
            for (int f = 0; f < 8; f++) {
                uint4 kb = kr[8 * f];
                mma_bf16(S[f], Qb[kc], kb.x, kb.y);
                mma_bf16(S[f], Qs[kc], kb.x, kb.y);
                mma_bf16(S[f], Qb[kc], kb.z, kb.w);
            }
        }

        // ---- warp-local online softmax (exp2 domain) ----
        float mlo = -1e30f, mhi = -1e30f;
        #pragma unroll
        for (int f = 0; f < 8; f++) {
            mlo = fmaxf(mlo, fmaxf(S[f][0], S[f][1]));
            mhi = fmaxf(mhi, fmaxf(S[f][2], S[f][3]));
        }
        mlo = fmaxf(mlo, __shfl_xor_sync(0xffffffffu, mlo, 1));
        mlo = fmaxf(mlo, __shfl_xor_sync(0xffffffffu, mlo, 2));
        mhi = fmaxf(mhi, __shfl_xor_sync(0xffffffffu, mhi, 1));
        mhi = fmaxf(mhi, __shfl_xor_sync(0xffffffffu, mhi, 2));
        float mnl = fmaxf(m_l, mlo), mnh = fmaxf(m_h, mhi);
        float scl = ex2f(m_l - mnl), sch = ex2f(m_h - mnh);
        m_l = mnl; m_h = mnh;
        float slo = 0.f, shi = 0.f;
        #pragma unroll
        for (int f = 0; f < 8; f++) {
            float p0 = ex2f(S[f][0] - mnl);
            float p1 = ex2f(S[f][1] - mnl);
            float p2 = ex2f(S[f][2] - mnh);
            float p3 = ex2f(S[f][3] - mnh);
            slo += p0 + p1;
            shi += p2 + p3;
            S[f][0] = p0; S[f][1] = p1; S[f][2] = p2; S[f][3] = p3;
        }
        slo += __shfl_xor_sync(0xffffffffu, slo, 1);
        slo += __shfl_xor_sync(0xffffffffu, slo, 2);
        shi += __shfl_xor_sync(0xffffffffu, shi, 1);
        shi += __shfl_xor_sync(0xffffffffu, shi, 2);
        l_l = l_l * scl + slo;
        l_h = l_h * sch + shi;

        // ---- rescale O, then O += P * V (fp16 k16, P straight from regs) ----
        #pragma unroll
        for (int cf = 0; cf < 16; cf++) {
            O[cf][0] *= scl; O[cf][1] *= scl;
            O[cf][2] *= sch; O[cf][3] *= sch;
        }
        #pragma unroll
        for (int kc = 0; kc < 4; kc++) {
            uint32 a[4];
            a[0] = pack_h2(S[2 * kc][0],     S[2 * kc][1]);
            a[1] = pack_h2(S[2 * kc][2],     S[2 * kc][3]);
            a[2] = pack_h2(S[2 * kc + 1][0], S[2 * kc + 1][1]);
            a[3] = pack_h2(S[2 * kc + 1][2], S[2 * kc + 1][3]);
            const uint2* vr = cV2 + (4 * kc + kk) * 132 + g;
            #pragma unroll
            for (int cf = 0; cf < 16; cf++) {
                uint2 v2 = vr[8 * cf];
                mma_fp16(O[cf], a, v2.x, v2.y);
            }
        }
        if (nt < 15) {
            CP_WAIT0();
            __syncthreads();
        }
    }

    // ---- normalize, stage [m][130], coalesced out = O + x ----
    __syncthreads();   // all warps done reading last tile before sO overwrites bufs
    float il = 1.0f / l_l, ih = 1.0f / l_h;
    float* sO = sm;    // spans both buffers (dead now)
    #pragma unroll
    for (int cf = 0; cf < 16; cf++) {
        int col = 8 * cf + 2 * kk;
        *(float2*)&sO[rl * 130 + col] = make_float2(O[cf][0] * il, O[cf][1] * il);
        *(float2*)&sO[rh * 130 + col] = make_float2(O[cf][2] * ih, O[cf][3] * ih);
    }
    __syncthreads();
    {
        int m = tid & 127;
        int c0 = (tid >> 7) * 64;
        #pragma unroll 4
        for (int k2 = 0; k2 < 64; k2++) {
            int c = c0 + k2;
            size_t a = ((size_t)b * 512 + h * 128 + c) * 1024 + mg + m;
            out[a] = sO[m * 130 + c] + x[a];
        }
    }
}

// ---------------- launch ----------------
extern "C" void kernel_launch(void* const* d_in, const int* in_sizes, int n_in,
                              void* d_out, int out_size)
{
    const float* x     = (const float*)d_in[0];
    const float* Wq    = (const float*)d_in[1];
    const float* bq    = (const float*)d_in[2];
    const float* qg    = (const float*)d_in[3];
    const float* qb    = (const float*)d_in[4];
    const float* qm    = (const float*)d_in[5];
    const float* qv    = (const float*)d_in[6];
    const float* Wk    = (const float*)d_in[7];
    const float* bk    = (const float*)d_in[8];
    const float* kg    = (const float*)d_in[9];
    const float* kb    = (const float*)d_in[10];
    const float* km    = (const float*)d_in[11];
    const float* kv    = (const float*)d_in[12];
    const float* Wv    = (const float*)d_in[13];
    const float* bv    = (const float*)d_in[14];
    const float* vg    = (const float*)d_in[15];
    const float* vb    = (const float*)d_in[16];
    const float* vm    = (const float*)d_in[17];
    const float* vvar  = (const float*)d_in[18];
    const float* rel_h = (const float*)d_in[19];
    const float* rel_w = (const float*)d_in[20];
    float* out = (float*)d_out;

    cudaFuncSetAttribute(attn_kernel, cudaFuncAttributeMaxDynamicSharedMemorySize,
                         ATTN_SMEM_FLOATS * (int)sizeof(float));
    cudaFuncSetAttribute(proj_kernel, cudaFuncAttributeMaxDynamicSharedMemorySize,
                         PROJ_SMEM_FLOATS * (int)sizeof(float));

    fold_kernel<<<768, 256>>>(Wq, bq, qg, qb, qm, qv,
                              Wk, bk, kg, kb, km, kv,
                              Wv, bv, vg, vb, vm, vvar);
    pos_kernel<<<512, 256>>>(rel_h, rel_w);
    xsplit_kernel<<<dim3(256, 16), 256>>>(x);
    proj_kernel<<<dim3(8, 6, 16), 256, PROJ_SMEM_FLOATS * sizeof(float)>>>();
    prep_kernel<<<dim3(16, 4, 16), 256>>>();
    attn_kernel<<<dim3(8, 4, 16), 256, ATTN_SMEM_FLOATS * sizeof(float)>>>(x, out);
}

// round 9
// speedup vs baseline: 3.7548x; 1.1762x over previous
#include <cuda_runtime.h>
#include <cuda_bf16.h>
#include <cuda_fp16.h>

typedef unsigned int uint32;

#define EPS 1e-5f
#define TILE_F 9216    // floats per tile image: K-bf16split 4224 + V-fp16 4224 + pad

// ---------------- scratch (device globals; no cudaMalloc allowed) ----------------
__device__ float g_ball[768];               // folded biases
__device__ float g_pos[128 * 1024];         // pos[h*32+d][n]
__device__ float g_qk[16 * 256 * 1024];     // [b][o][n], o<128: q, o in [128,256): k
__device__ float g_vt[16 * 4 * 1024 * 128]; // [b][h][n][c]
__device__ __align__(16) uint2 g_Wbs[768 * 256];        // W big/small bf16 pairs [o][kpair]
__device__ __align__(16) uint2 g_Xbs[16 * 256 * 1024];  // X big/small bf16 pairs [b][kpair][n]
__device__ __align__(16) uint32 g_Wh[768 * 256];        // W fp16 pairs [o][kpair]
__device__ __align__(16) uint32 g_Xh[16 * 256 * 1024];  // X fp16 pairs [b][kpair][n]
__device__ __align__(16) float g_tile[16 * 4 * 16 * TILE_F]; // fragment-ready K'/V tiles

// ---------------- mma / pack helpers ----------------
__device__ __forceinline__ void mma_bf16(float* c, const uint32* a, uint32 b0, uint32 b1) {
    asm volatile("mma.sync.aligned.m16n8k16.row.col.f32.bf16.bf16.f32 "
        "{%0,%1,%2,%3}, {%4,%5,%6,%7}, {%8,%9}, {%0,%1,%2,%3};"
        : "+f"(c[0]), "+f"(c[1]), "+f"(c[2]), "+f"(c[3])
        : "r"(a[0]), "r"(a[1]), "r"(a[2]), "r"(a[3]), "r"(b0), "r"(b1));
}
__device__ __forceinline__ void mma_fp16(float* c, const uint32* a, uint32 b0, uint32 b1) {
    asm volatile("mma.sync.aligned.m16n8k16.row.col.f32.f16.f16.f32 "
        "{%0,%1,%2,%3}, {%4,%5,%6,%7}, {%8,%9}, {%0,%1,%2,%3};"
        : "+f"(c[0]), "+f"(c[1]), "+f"(c[2]), "+f"(c[3])
        : "r"(a[0]), "r"(a[1]), "r"(a[2]), "r"(a[3]), "r"(b0), "r"(b1));
}

// split v0,v1 into bf16 big/small packed pairs (element0 in low 16 bits)
__device__ __forceinline__ void split2_bf(float v0, float v1, uint32& bb, uint32& ss) {
    float b0 = __bfloat162float(__float2bfloat16_rn(v0));
    float b1 = __bfloat162float(__float2bfloat16_rn(v1));
    __nv_bfloat162 tb = __floats2bfloat162_rn(b0, b1);
    __nv_bfloat162 ts = __floats2bfloat162_rn(v0 - b0, v1 - b1);
    bb = *reinterpret_cast<uint32*>(&tb);
    ss = *reinterpret_cast<uint32*>(&ts);
}
__device__ __forceinline__ uint32 pack_h2(float v0, float v1) {
    __half2 h = __floats2half2_rn(v0, v1);
    return *reinterpret_cast<uint32*>(&h);
}
__device__ __forceinline__ float ex2f(float x) {
    float r; asm("ex2.approx.ftz.f32 %0, %1;" : "=f"(r) : "f"(x)); return r;
}

// ---------------- cp.async helpers ----------------
__device__ __forceinline__ void cp16(uint32 sdst, const void* gsrc) {
    asm volatile("cp.async.cg.shared.global [%0], [%1], 16;\n" :: "r"(sdst), "l"(gsrc));
}
#define CP_COMMIT() asm volatile("cp.async.commit_group;\n" ::: "memory")
#define CP_WAIT0()  asm volatile("cp.async.wait_group 0;\n" ::: "memory")

__device__ __forceinline__ void cp_tile(float* smem_dst, const float* gsrc, int tid) {
    uint32 s = (uint32)__cvta_generic_to_shared(smem_dst);
    #pragma unroll
    for (int it = 0; it < 9; it++) {
        int i = tid + it * 256;          // 2304 float4s = 9216 floats
        cp16(s + i * 16, gsrc + i * 4);
    }
}

// ---------------- 1) fold BN into conv weights; write bf16-split + fp16 images ----------------
__global__ void fold_kernel(
    const float* __restrict__ Wq, const float* __restrict__ bq,
    const float* __restrict__ qg, const float* __restrict__ qb,
    const float* __restrict__ qm, const float* __restrict__ qvv,
    const float* __restrict__ Wk, const float* __restrict__ bk,
    const float* __restrict__ kg, const float* __restrict__ kb,
    const float* __restrict__ km, const float* __restrict__ kvv,
    const float* __restrict__ Wv, const float* __restrict__ bv,
    const float* __restrict__ vg, const float* __restrict__ vb,
    const float* __restrict__ vm, const float* __restrict__ vvv)
{
    int o = blockIdx.x;  // 0..767
    const float* src;
    float s, bias;
    if (o < 128) {
        s = qg[o] * rsqrtf(qvv[o] + EPS);
        bias = (bq[o] - qm[o]) * s + qb[o];
        src = Wq + o * 512;
    } else if (o < 256) {
        int oo = o - 128;
        s = kg[oo] * rsqrtf(kvv[oo] + EPS);
        bias = (bk[oo] - km[oo]) * s + kb[oo];
        src = Wk + oo * 512;
    } else {
        int oo = o - 256;
        s = vg[oo] * rsqrtf(vvv[oo] + EPS);
        bias = (bv[oo] - vm[oo]) * s + vb[oo];
        src = Wv + oo * 512;
    }
    int p = threadIdx.x;           // pair 0..255
    float w0 = src[2 * p] * s;
    float w1 = src[2 * p + 1] * s;
    uint32 bb, ss;
    split2_bf(w0, w1, bb, ss);
    g_Wbs[o * 256 + p] = make_uint2(bb, ss);
    g_Wh[o * 256 + p] = pack_h2(w0, w1);
    if (p == 0) g_ball[o] = bias;
}

// ---------------- 2) pos[h,d,n] = rel_h[h,d,hh] + rel_w[h,d,w] ----------------
__global__ void pos_kernel(const float* __restrict__ rel_h, const float* __restrict__ rel_w) {
    int idx = blockIdx.x * blockDim.x + threadIdx.x;
    if (idx >= 128 * 1024) return;
    int hd = idx >> 10;
    int n = idx & 1023;
    int w = n >> 5, hh = n & 31;
    g_pos[idx] = rel_h[hd * 32 + hh] + rel_w[hd * 32 + w];
}

// ---------------- 2.5) pre-split X into bf16 big/small + fp16 pair images ----------------
__global__ __launch_bounds__(256) void xsplit_kernel(const float* __restrict__ x) {
    int kp = blockIdx.x, b = blockIdx.y;
    int tid = threadIdx.x;
    const float* r0 = x + ((size_t)b * 512 + 2 * kp) * 1024;
    const float* r1 = r0 + 1024;
    uint2* dst = g_Xbs + ((size_t)b * 256 + kp) * 1024;
    uint32* dsth = g_Xh + ((size_t)b * 256 + kp) * 1024;
    int n4 = tid * 4;
    float4 a = *(const float4*)&r0[n4];
    float4 c = *(const float4*)&r1[n4];
    uint2 o0, o1, o2, o3;
    split2_bf(a.x, c.x, o0.x, o0.y);
    split2_bf(a.y, c.y, o1.x, o1.y);
    split2_bf(a.z, c.z, o2.x, o2.y);
    split2_bf(a.w, c.w, o3.x, o3.y);
    dst[n4] = o0; dst[n4 + 1] = o1; dst[n4 + 2] = o2; dst[n4 + 3] = o3;
    uint4 hv;
    hv.x = pack_h2(a.x, c.x);
    hv.y = pack_h2(a.y, c.y);
    hv.z = pack_h2(a.z, c.z);
    hv.w = pack_h2(a.w, c.w);
    *(uint4*)&dsth[n4] = hv;
}

// ---------------- 3) QKV projection ----------------
// QK blocks (rb<2): bf16 3-term compensated. V blocks (rb>=2): fp16 single-term.
// QK smem per buffer (uint2): sW [128][20] (2560) + sX [16][132] (2112) = 4672
// V  smem per buffer (uint32): sW [128][20] (2560) + sX [16][136] (2176) = 4736
#define PBQK_U2 4672
#define PBV_U1 4736
#define PROJ_SMEM_BYTES 74752   // max(QK 2*4672*8, V 2*4736*4=37888, epilogue 128*132*4=67584)

__device__ __forceinline__ void cp_projqk(uint2* buf, int b, int row0, int col0, int kt, int tid) {
    uint32 s = (uint32)__cvta_generic_to_shared(buf);
    #pragma unroll
    for (int it = 0; it < 4; it++) {          // W: 1024 16B-chunks
        int i = tid + it * 256;
        int m = i >> 3, c = i & 7;
        cp16(s + (m * 20 + 2 * c) * 8, g_Wbs + (size_t)(row0 + m) * 256 + kt * 16 + 2 * c);
    }
    #pragma unroll
    for (int it = 0; it < 4; it++) {          // X: 1024 16B-chunks
        int i = tid + it * 256;
        int kp = i >> 6, c = i & 63;
        cp16(s + (2560 + kp * 132 + 2 * c) * 8,
             g_Xbs + ((size_t)b * 256 + kt * 16 + kp) * 1024 + col0 + 2 * c);
    }
}

__device__ __forceinline__ void cp_projv(uint32* buf, int b, int row0, int col0, int kt, int tid) {
    uint32 s = (uint32)__cvta_generic_to_shared(buf);
    #pragma unroll
    for (int it = 0; it < 2; it++) {          // W: 512 16B-chunks (128 m x 4 chunks)
        int i = tid + it * 256;
        int m = i >> 2, c = i & 3;
        cp16(s + (m * 20 + 4 * c) * 4, g_Wh + (size_t)(row0 + m) * 256 + kt * 16 + 4 * c);
    }
    #pragma unroll
    for (int it = 0; it < 2; it++) {          // X: 512 16B-chunks (16 kp x 32 chunks)
        int i = tid + it * 256;
        int kp = i >> 5, c = i & 31;
        cp16(s + (2560 + kp * 136 + 4 * c) * 4,
             g_Xh + ((size_t)b * 256 + kt * 16 + kp) * 1024 + col0 + 4 * c);
    }
}

__global__ __launch_bounds__(256) void proj_kernel() {
    extern __shared__ float ps[];
    int b = blockIdx.z, row0 = blockIdx.y * 128, col0 = blockIdx.x * 128;
    bool isV = (row0 >= 256);
    int tid = threadIdx.x, w = tid >> 5, lane = tid & 31;
    int g = lane >> 2, kk = lane & 3;
    int wm = w >> 1, wn = w & 1;

    float acc[2][8][4];
    #pragma unroll
    for (int mi = 0; mi < 2; mi++)
        #pragma unroll
        for (int nf = 0; nf < 8; nf++)
            #pragma unroll
            for (int j = 0; j < 4; j++) acc[mi][nf][j] = 0.f;

    if (!isV) {
        // ---------- bf16 3-term path (q/k) ----------
        uint2* sbase = (uint2*)ps;
        cp_projqk(sbase, b, row0, col0, 0, tid);
        CP_COMMIT();
        CP_WAIT0();
        __syncthreads();
        for (int kt = 0; kt < 16; kt++) {
            uint2* cur = sbase + (kt & 1) * PBQK_U2;
            if (kt < 15) {
                cp_projqk(sbase + ((kt + 1) & 1) * PBQK_U2, b, row0, col0, kt + 1, tid);
                CP_COMMIT();
            }
            uint2* sW = cur;
            uint2* sX = cur + 2560;
            #pragma unroll
            for (int kc = 0; kc < 2; kc++) {
                uint32 Ab[2][4], As[2][4];
                #pragma unroll
                for (int mi = 0; mi < 2; mi++) {
                    int r = wm * 32 + mi * 16 + g;
                    uint2 w0 = sW[r * 20 + kk + 8 * kc];
                    uint2 w1 = sW[(r + 8) * 20 + kk + 8 * kc];
                    uint2 w2 = sW[r * 20 + kk + 4 + 8 * kc];
                    uint2 w3 = sW[(r + 8) * 20 + kk + 4 + 8 * kc];
                    Ab[mi][0] = w0.x; Ab[mi][1] = w1.x; Ab[mi][2] = w2.x; Ab[mi][3] = w3.x;
                    As[mi][0] = w0.y; As[mi][1] = w1.y; As[mi][2] = w2.y; As[mi][3] = w3.y;
                }
                #pragma unroll
                for (int nf = 0; nf < 8; nf++) {
                    int nc = wn * 64 + 8 * nf + g;
                    uint2 x0 = sX[(kk + 8 * kc) * 132 + nc];
                    uint2 x1 = sX[(kk + 4 + 8 * kc) * 132 + nc];
                    #pragma unroll
                    for (int mi = 0; mi < 2; mi++) {
                        mma_bf16(acc[mi][nf], Ab[mi], x0.x, x1.x);
                        mma_bf16(acc[mi][nf], As[mi], x0.x, x1.x);
                        mma_bf16(acc[mi][nf], Ab[mi], x0.y, x1.y);
                    }
                }
            }
            if (kt < 15) {
                CP_WAIT0();
                __syncthreads();
            }
        }
        // epilogue: direct stores to g_qk
        #pragma unroll
        for (int mi = 0; mi < 2; mi++) {
            int o0 = row0 + wm * 32 + mi * 16 + g;
            int o1 = o0 + 8;
            float b0v = g_ball[o0], b1v = g_ball[o1];
            #pragma unroll
            for (int nf = 0; nf < 8; nf++) {
                int n = col0 + wn * 64 + 8 * nf + 2 * kk;
                *(float2*)&g_qk[((size_t)b * 256 + o0) * 1024 + n] =
                    make_float2(acc[mi][nf][0] + b0v, acc[mi][nf][1] + b0v);
                *(float2*)&g_qk[((size_t)b * 256 + o1) * 1024 + n] =
                    make_float2(acc[mi][nf][2] + b1v, acc[mi][nf][3] + b1v);
            }
        }
    } else {
        // ---------- fp16 single-term path (v) ----------
        uint32* sbase = (uint32*)ps;
        cp_projv(sbase, b, row0, col0, 0, tid);
        CP_COMMIT();
        CP_WAIT0();
        __syncthreads();
        for (int kt = 0; kt < 16; kt++) {
            uint32* cur = sbase + (kt & 1) * PBV_U1;
            if (kt < 15) {
                cp_projv(sbase + ((kt + 1) & 1) * PBV_U1, b, row0, col0, kt + 1, tid);
                CP_COMMIT();
            }
            uint32* sW = cur;
            uint32* sX = cur + 2560;
            #pragma unroll
            for (int kc = 0; kc < 2; kc++) {
                uint32 A[2][4];
                #pragma unroll
                for (int mi = 0; mi < 2; mi++) {
                    int r = wm * 32 + mi * 16 + g;
                    A[mi][0] = sW[r * 20 + kk + 8 * kc];
                    A[mi][1] = sW[(r + 8) * 20 + kk + 8 * kc];
                    A[mi][2] = sW[r * 20 + kk + 4 + 8 * kc];
                    A[mi][3] = sW[(r + 8) * 20 + kk + 4 + 8 * kc];
                }
                #pragma unroll
                for (int nf = 0; nf < 8; nf++) {
                    int nc = wn * 64 + 8 * nf + g;
                    uint32 x0 = sX[(kk + 8 * kc) * 136 + nc];
                    uint32 x1 = sX[(kk + 4 + 8 * kc) * 136 + nc];
                    #pragma unroll
                    for (int mi = 0; mi < 2; mi++)
                        mma_fp16(acc[mi][nf], A[mi], x0, x1);
                }
            }
            if (kt < 15) {
                CP_WAIT0();
                __syncthreads();
            }
        }
        // epilogue: transpose through smem, coalesced stores to g_vt [n][c]
        __syncthreads();
        float* sOut = ps;   // 128 n x 132
        #pragma unroll
        for (int mi = 0; mi < 2; mi++) {
            int o0 = row0 + wm * 32 + mi * 16 + g;
            int ol = wm * 32 + mi * 16 + g;
            float b0v = g_ball[o0], b1v = g_ball[o0 + 8];
            #pragma unroll
            for (int nf = 0; nf < 8; nf++) {
                int n = wn * 64 + 8 * nf + 2 * kk;
                sOut[n * 132 + ol] = acc[mi][nf][0] + b0v;
                sOut[(n + 1) * 132 + ol] = acc[mi][nf][1] + b0v;
                sOut[n * 132 + ol + 8] = acc[mi][nf][2] + b1v;
                sOut[(n + 1) * 132 + ol + 8] = acc[mi][nf][3] + b1v;
            }
        }
        __syncthreads();
        int hh = (row0 - 256) >> 7;
        float* dst = g_vt + (size_t)(b * 4 + hh) * 131072;
        #pragma unroll
        for (int it = 0; it < 16; it++) {
            int i = tid + it * 256;
            int n = i >> 5, c4 = (i & 31) << 2;
            *(float4*)&dst[(size_t)(col0 + n) * 128 + c4] = *(float4*)&sOut[n * 132 + c4];
        }
    }
}

// ---------------- 3.5) prep: fragment-ready K'(bf16 split) / V(fp16) tile images ----------------
__device__ __forceinline__ float kprime(size_t qkbase, int h, int ng, int d, int n) {
    return (d < 32) ? g_qk[qkbase + (size_t)(128 + h * 32 + d) * 1024 + ng + n]
                    : g_qk[qkbase + (size_t)(h * 32 + d - 32) * 1024 + ng + n];
}

__global__ __launch_bounds__(256) void prep_kernel() {
    int nt = blockIdx.x, h = blockIdx.y, b = blockIdx.z;
    int tid = threadIdx.x;
    int ng = nt * 64;
    size_t qkbase = (size_t)b * 256 * 1024;
    float* dst = g_tile + (size_t)((b * 4 + h) * 16 + nt) * TILE_F;

    #pragma unroll
    for (int it = 0; it < 4; it++) {
        int i = tid + it * 256;
        int dp = i >> 6, n = i & 63;
        int kc = dp >> 2, kk = dp & 3;
        int r0 = 16 * kc + 2 * kk;
        float v0 = kprime(qkbase, h, ng, r0, n);
        float v1 = kprime(qkbase, h, ng, r0 + 1, n);
        float v8 = kprime(qkbase, h, ng, r0 + 8, n);
        float v9 = kprime(qkbase, h, ng, r0 + 9, n);
        uint4 o;
        split2_bf(v0, v1, o.x, o.z);
        split2_bf(v8, v9, o.y, o.w);
        ((uint4*)dst)[dp * 66 + n] = o;
    }

    const float* vb = g_vt + (size_t)(b * 4 + h) * 131072;
    uint2* dv = (uint2*)(dst + 4224);
    #pragma unroll
    for (int it = 0; it < 8; it++) {
        int i = tid + it * 256;
        int dp = i >> 7, c = i & 127;
        int kc = dp >> 2, kk = dp & 3;
        int r0 = 16 * kc + 2 * kk;
        float v00 = vb[(size_t)(ng + r0) * 128 + c];
        float v01 = vb[(size_t)(ng + r0 + 1) * 128 + c];
        float v10 = vb[(size_t)(ng + r0 + 8) * 128 + c];
        float v11 = vb[(size_t)(ng + r0 + 9) * 128 + c];
        dv[dp * 132 + c] = make_uint2(pack_h2(v00, v01), pack_h2(v10, v11));
    }
}

// ---------------- 4) flash attention: bf16x3 QK + fp16 PV (P in regs) ----------------
#define ATTN_SMEM_FLOATS (2 * TILE_F)   // 18432 floats = 73728 B

__global__ __launch_bounds__(256, 1) void attn_kernel(const float* __restrict__ x,
                                                      float* __restrict__ out)
{
    extern __shared__ float sm[];
    int mt = blockIdx.x, h = blockIdx.y, b = blockIdx.z;
    int tid = threadIdx.x, w = tid >> 5, lane = tid & 31;
    int g = lane >> 2, kk = lane & 3;
    int mg = mt * 128;
    int rl = 16 * w + g, rh = rl + 8;
    size_t qkbase = (size_t)b * 256 * 1024;
    const float* tbase = g_tile + (size_t)((b * 4 + h) * 16) * TILE_F;

    cp_tile(sm, tbase, tid);
    CP_COMMIT();

    float* sQ = sm + TILE_F;
    #pragma unroll
    for (int it = 0; it < 8; it++) {
        int i = tid + it * 256;
        int d = i >> 5, m4 = (i & 31) << 2;
        const float* src = (d < 32)
            ? &g_qk[qkbase + (size_t)(h * 32 + d) * 1024 + mg + m4]
            : &g_pos[(size_t)(h * 32 + (d - 32)) * 1024 + mg + m4];
        float4 v = *(const float4*)src;
        sQ[(m4 + 0) * 68 + d] = v.x;
        sQ[(m4 + 1) * 68 + d] = v.y;
        sQ[(m4 + 2) * 68 + d] = v.z;
        sQ[(m4 + 3) * 68 + d] = v.w;
    }
    __syncthreads();

    const float LOG2E = 1.4426950408889634f;
    uint32 Qb[4][4], Qs[4][4];
    #pragma unroll
    for (int kc = 0; kc < 4; kc++) {
        int klo = 16 * kc + 2 * kk;
        int khi = klo + 8;
        split2_bf(LOG2E * sQ[rl * 68 + klo], LOG2E * sQ[rl * 68 + klo + 1], Qb[kc][0], Qs[kc][0]);
        split2_bf(LOG2E * sQ[rh * 68 + klo], LOG2E * sQ[rh * 68 + klo + 1], Qb[kc][1], Qs[kc][1]);
        split2_bf(LOG2E * sQ[rl * 68 + khi], LOG2E * sQ[rl * 68 + khi + 1], Qb[kc][2], Qs[kc][2]);
        split2_bf(LOG2E * sQ[rh * 68 + khi], LOG2E * sQ[rh * 68 + khi + 1], Qb[kc][3], Qs[kc][3]);
    }
    float m_l = -1e30f, m_h = -1e30f, l_l = 0.f, l_h = 0.f;
    float O[16][4];
    #pragma unroll
    for (int cf = 0; cf < 16; cf++)
        #pragma unroll
        for (int j = 0; j < 4; j++) O[cf][j] = 0.f;

    CP_WAIT0();
    __syncthreads();

    for (int nt = 0; nt < 16; nt++) {
        float* buf = sm + (nt & 1) * TILE_F;
        if (nt < 15) {
            cp_tile(sm + ((nt + 1) & 1) * TILE_F, tbase + (size_t)(nt + 1) * TILE_F, tid);
            CP_COMMIT();
        }
        const uint4* cK4 = (const uint4*)buf;
        const uint2* cV2 = (const uint2*)(buf + 4224);

        float S[8][4];
        #pragma unroll
        for (int f = 0; f < 8; f++)
            #pragma unroll
            for (int j = 0; j < 4; j++) S[f][j] = 0.f;
        #pragma unroll
        for (int kc = 0; kc < 4; kc++) {
            const uint4* kr = cK4 + (4 * kc + kk) * 66 + g;
            #pragma unroll
            for (int f = 0; f < 8; f++) {
                uint4 kb = kr[8 * f];
                mma_bf16(S[f], Qb[kc], kb.x, kb.y);
                mma_bf16(S[f], Qs[kc], kb.x, kb.y);
                mma_bf16(S[f], Qb[kc], kb.z, kb.w);
            }
        }

        float mlo = -1e30f, mhi = -1e30f;
        #pragma unroll
        for (int f = 0; f < 8; f++) {
            mlo = fmaxf(mlo, fmaxf(S[f][0], S[f][1]));
            mhi = fmaxf(mhi, fmaxf(S[f][2], S[f][3]));
        }
        mlo = fmaxf(mlo, __shfl_xor_sync(0xffffffffu, mlo, 1));
        mlo = fmaxf(mlo, __shfl_xor_sync(0xffffffffu, mlo, 2));
        mhi = fmaxf(mhi, __shfl_xor_sync(0xffffffffu, mhi, 1));
        mhi = fmaxf(mhi, __shfl_xor_sync(0xffffffffu, mhi, 2));
        float mnl = fmaxf(m_l, mlo), mnh = fmaxf(m_h, mhi);
        float scl = ex2f(m_l - mnl), sch = ex2f(m_h - mnh);
        m_l = mnl; m_h = mnh;
        float slo = 0.f, shi = 0.f;
        #pragma unroll
        for (int f = 0; f < 8; f++) {
            float p0 = ex2f(S[f][0] - mnl);
            float p1 = ex2f(S[f][1] - mnl);
            float p2 = ex2f(S[f][2] - mnh);
            float p3 = ex2f(S[f][3] - mnh);
            slo += p0 + p1;
            shi += p2 + p3;
            S[f][0] = p0; S[f][1] = p1; S[f][2] = p2; S[f][3] = p3;
        }
        slo += __shfl_xor_sync(0xffffffffu, slo, 1);
        slo += __shfl_xor_sync(0xffffffffu, slo, 2);
        shi += __shfl_xor_sync(0xffffffffu, shi, 1);
        shi += __shfl_xor_sync(0xffffffffu, shi, 2);
        l_l = l_l * scl + slo;
        l_h = l_h * sch + shi;

        #pragma unroll
        for (int cf = 0; cf < 16; cf++) {
            O[cf][0] *= scl; O[cf][1] *= scl;
            O[cf][2] *= sch; O[cf][3] *= sch;
        }
        #pragma unroll
        for (int kc = 0; kc < 4; kc++) {
            uint32 a[4];
            a[0] = pack_h2(S[2 * kc][0],     S[2 * kc][1]);
            a[1] = pack_h2(S[2 * kc][2],     S[2 * kc][3]);
            a[2] = pack_h2(S[2 * kc + 1][0], S[2 * kc + 1][1]);
            a[3] = pack_h2(S[2 * kc + 1][2], S[2 * kc + 1][3]);
            const uint2* vr = cV2 + (4 * kc + kk) * 132 + g;
            #pragma unroll
            for (int cf = 0; cf < 16; cf++) {
                uint2 v2 = vr[8 * cf];
                mma_fp16(O[cf], a, v2.x, v2.y);
            }
        }
        if (nt < 15) {
            CP_WAIT0();
            __syncthreads();
        }
    }

    __syncthreads();
    float il = 1.0f / l_l, ih = 1.0f / l_h;
    float* sO = sm;
    #pragma unroll
    for (int cf = 0; cf < 16; cf++) {
        int col = 8 * cf + 2 * kk;
        *(float2*)&sO[rl * 130 + col] = make_float2(O[cf][0] * il, O[cf][1] * il);
        *(float2*)&sO[rh * 130 + col] = make_float2(O[cf][2] * ih, O[cf][3] * ih);
    }
    __syncthreads();
    {
        int m = tid & 127;
        int c0 = (tid >> 7) * 64;
        #pragma unroll 4
        for (int k2 = 0; k2 < 64; k2++) {
            int c = c0 + k2;
            size_t a = ((size_t)b * 512 + h * 128 + c) * 1024 + mg + m;
            out[a] = sO[m * 130 + c] + x[a];
        }
    }
}

// ---------------- launch ----------------
extern "C" void kernel_launch(void* const* d_in, const int* in_sizes, int n_in,
                              void* d_out, int out_size)
{
    const float* x     = (const float*)d_in[0];
    const float* Wq    = (const float*)d_in[1];
    const float* bq    = (const float*)d_in[2];
    const float* qg    = (const float*)d_in[3];
    const float* qb    = (const float*)d_in[4];
    const float* qm    = (const float*)d_in[5];
    const float* qv    = (const float*)d_in[6];
    const float* Wk    = (const float*)d_in[7];
    const float* bk    = (const float*)d_in[8];
    const float* kg    = (const float*)d_in[9];
    const float* kb    = (const float*)d_in[10];
    const float* km    = (const float*)d_in[11];
    const float* kv    = (const float*)d_in[12];
    const float* Wv    = (const float*)d_in[13];
    const float* bv    = (const float*)d_in[14];
    const float* vg    = (const float*)d_in[15];
    const float* vb    = (const float*)d_in[16];
    const float* vm    = (const float*)d_in[17];
    const float* vvar  = (const float*)d_in[18];
    const float* rel_h = (const float*)d_in[19];
    const float* rel_w = (const float*)d_in[20];
    float* out = (float*)d_out;

    cudaFuncSetAttribute(attn_kernel, cudaFuncAttributeMaxDynamicSharedMemorySize,
                         ATTN_SMEM_FLOATS * (int)sizeof(float));
    cudaFuncSetAttribute(proj_kernel, cudaFuncAttributeMaxDynamicSharedMemorySize,
                         PROJ_SMEM_BYTES);

    fold_kernel<<<768, 256>>>(Wq, bq, qg, qb, qm, qv,
                              Wk, bk, kg, kb, km, kv,
                              Wv, bv, vg, vb, vm, vvar);
    pos_kernel<<<512, 256>>>(rel_h, rel_w);
    xsplit_kernel<<<dim3(256, 16), 256>>>(x);
    proj_kernel<<<dim3(8, 6, 16), 256, PROJ_SMEM_BYTES>>>();
    prep_kernel<<<dim3(16, 4, 16), 256>>>();
    attn_kernel<<<dim3(8, 4, 16), 256, ATTN_SMEM_FLOATS * sizeof(float)>>>(x, out);
}

// round 10
// speedup vs baseline: 3.7552x; 1.0001x over previous
#include <cuda_runtime.h>
#include <cuda_bf16.h>
#include <cuda_fp16.h>

typedef unsigned int uint32;

#define EPS 1e-5f
#define TILE_F 9216    // floats per tile image: K-bf16split 4224 + V-fp16 4224 + pad

// ---------------- scratch (device globals; no cudaMalloc allowed) ----------------
__device__ float g_ball[768];               // folded biases
__device__ float g_qk[16 * 256 * 1024];     // [b][o][n], o<128: q, o in [128,256): k
__device__ __align__(16) uint2 g_Wbs[768 * 256];        // W big/small bf16 pairs [o][kpair]
__device__ __align__(16) uint2 g_Xbs[16 * 256 * 1024];  // X big/small bf16 pairs [b][kpair][n]
__device__ __align__(16) uint32 g_Wh[768 * 256];        // W fp16 pairs [o][kpair]
__device__ __align__(16) uint32 g_Xh[16 * 256 * 1024];  // X fp16 pairs [b][kpair][n]
__device__ __align__(16) float g_tile[16 * 4 * 16 * TILE_F]; // fragment-ready K'/V tiles

// ---------------- mma / pack helpers ----------------
__device__ __forceinline__ void mma_bf16(float* c, const uint32* a, uint32 b0, uint32 b1) {
    asm volatile("mma.sync.aligned.m16n8k16.row.col.f32.bf16.bf16.f32 "
        "{%0,%1,%2,%3}, {%4,%5,%6,%7}, {%8,%9}, {%0,%1,%2,%3};"
        : "+f"(c[0]), "+f"(c[1]), "+f"(c[2]), "+f"(c[3])
        : "r"(a[0]), "r"(a[1]), "r"(a[2]), "r"(a[3]), "r"(b0), "r"(b1));
}
__device__ __forceinline__ void mma_fp16(float* c, const uint32* a, uint32 b0, uint32 b1) {
    asm volatile("mma.sync.aligned.m16n8k16.row.col.f32.f16.f16.f32 "
        "{%0,%1,%2,%3}, {%4,%5,%6,%7}, {%8,%9}, {%0,%1,%2,%3};"
        : "+f"(c[0]), "+f"(c[1]), "+f"(c[2]), "+f"(c[3])
        : "r"(a[0]), "r"(a[1]), "r"(a[2]), "r"(a[3]), "r"(b0), "r"(b1));
}

// split v0,v1 into bf16 big/small packed pairs (element0 in low 16 bits)
__device__ __forceinline__ void split2_bf(float v0, float v1, uint32& bb, uint32& ss) {
    float b0 = __bfloat162float(__float2bfloat16_rn(v0));
    float b1 = __bfloat162float(__float2bfloat16_rn(v1));
    __nv_bfloat162 tb = __floats2bfloat162_rn(b0, b1);
    __nv_bfloat162 ts = __floats2bfloat162_rn(v0 - b0, v1 - b1);
    bb = *reinterpret_cast<uint32*>(&tb);
    ss = *reinterpret_cast<uint32*>(&ts);
}
__device__ __forceinline__ uint32 pack_h2(float v0, float v1) {
    __half2 h = __floats2half2_rn(v0, v1);
    return *reinterpret_cast<uint32*>(&h);
}
__device__ __forceinline__ float ex2f(float x) {
    float r; asm("ex2.approx.ftz.f32 %0, %1;" : "=f"(r) : "f"(x)); return r;
}

// ---------------- cp.async helpers ----------------
__device__ __forceinline__ void cp16(uint32 sdst, const void* gsrc) {
    asm volatile("cp.async.cg.shared.global [%0], [%1], 16;\n" :: "r"(sdst), "l"(gsrc));
}
#define CP_COMMIT() asm volatile("cp.async.commit_group;\n" ::: "memory")
#define CP_WAIT0()  asm volatile("cp.async.wait_group 0;\n" ::: "memory")

__device__ __forceinline__ void cp_tile(float* smem_dst, const float* gsrc, int tid) {
    uint32 s = (uint32)__cvta_generic_to_shared(smem_dst);
    #pragma unroll
    for (int it = 0; it < 9; it++) {
        int i = tid + it * 256;          // 2304 float4s = 9216 floats
        cp16(s + i * 16, gsrc + i * 4);
    }
}

// ---------------- 1) fold BN into conv weights; write bf16-split + fp16 images ----------------
__global__ void fold_kernel(
    const float* __restrict__ Wq, const float* __restrict__ bq,
    const float* __restrict__ qg, const float* __restrict__ qb,
    const float* __restrict__ qm, const float* __restrict__ qvv,
    const float* __restrict__ Wk, const float* __restrict__ bk,
    const float* __restrict__ kg, const float* __restrict__ kb,
    const float* __restrict__ km, const float* __restrict__ kvv,
    const float* __restrict__ Wv, const float* __restrict__ bv,
    const float* __restrict__ vg, const float* __restrict__ vb,
    const float* __restrict__ vm, const float* __restrict__ vvv)
{
    int o = blockIdx.x;  // 0..767
    const float* src;
    float s, bias;
    if (o < 128) {
        s = qg[o] * rsqrtf(qvv[o] + EPS);
        bias = (bq[o] - qm[o]) * s + qb[o];
        src = Wq + o * 512;
    } else if (o < 256) {
        int oo = o - 128;
        s = kg[oo] * rsqrtf(kvv[oo] + EPS);
        bias = (bk[oo] - km[oo]) * s + kb[oo];
        src = Wk + oo * 512;
    } else {
        int oo = o - 256;
        s = vg[oo] * rsqrtf(vvv[oo] + EPS);
        bias = (bv[oo] - vm[oo]) * s + vb[oo];
        src = Wv + oo * 512;
    }
    int p = threadIdx.x;           // pair 0..255
    float w0 = src[2 * p] * s;
    float w1 = src[2 * p + 1] * s;
    uint32 bb, ss;
    split2_bf(w0, w1, bb, ss);
    g_Wbs[o * 256 + p] = make_uint2(bb, ss);
    g_Wh[o * 256 + p] = pack_h2(w0, w1);
    if (p == 0) g_ball[o] = bias;
}

// ---------------- 2) pre-split X into bf16 big/small + fp16 pair images ----------------
__global__ __launch_bounds__(256) void xsplit_kernel(const float* __restrict__ x) {
    int kp = blockIdx.x, b = blockIdx.y;
    int tid = threadIdx.x;
    const float* r0 = x + ((size_t)b * 512 + 2 * kp) * 1024;
    const float* r1 = r0 + 1024;
    uint2* dst = g_Xbs + ((size_t)b * 256 + kp) * 1024;
    uint32* dsth = g_Xh + ((size_t)b * 256 + kp) * 1024;
    int n4 = tid * 4;
    float4 a = *(const float4*)&r0[n4];
    float4 c = *(const float4*)&r1[n4];
    uint2 o0, o1, o2, o3;
    split2_bf(a.x, c.x, o0.x, o0.y);
    split2_bf(a.y, c.y, o1.x, o1.y);
    split2_bf(a.z, c.z, o2.x, o2.y);
    split2_bf(a.w, c.w, o3.x, o3.y);
    dst[n4] = o0; dst[n4 + 1] = o1; dst[n4 + 2] = o2; dst[n4 + 3] = o3;
    uint4 hv;
    hv.x = pack_h2(a.x, c.x);
    hv.y = pack_h2(a.y, c.y);
    hv.z = pack_h2(a.z, c.z);
    hv.w = pack_h2(a.w, c.w);
    *(uint4*)&dsth[n4] = hv;
}

// ---------------- 3) QKV projection ----------------
// QK blocks (rb<2): bf16 3-term compensated -> g_qk.
// V blocks (rb>=2): fp16 single-term -> fp16 V tile image in g_tile (direct).
#define PBQK_U2 4672
#define PBV_U1 4736
#define PROJ_SMEM_BYTES 74752

__device__ __forceinline__ void cp_projqk(uint2* buf, int b, int row0, int col0, int kt, int tid) {
    uint32 s = (uint32)__cvta_generic_to_shared(buf);
    #pragma unroll
    for (int it = 0; it < 4; it++) {
        int i = tid + it * 256;
        int m = i >> 3, c = i & 7;
        cp16(s + (m * 20 + 2 * c) * 8, g_Wbs + (size_t)(row0 + m) * 256 + kt * 16 + 2 * c);
    }
    #pragma unroll
    for (int it = 0; it < 4; it++) {
        int i = tid + it * 256;
        int kp = i >> 6, c = i & 63;
        cp16(s + (2560 + kp * 132 + 2 * c) * 8,
             g_Xbs + ((size_t)b * 256 + kt * 16 + kp) * 1024 + col0 + 2 * c);
    }
}

__device__ __forceinline__ void cp_projv(uint32* buf, int b, int row0, int col0, int kt, int tid) {
    uint32 s = (uint32)__cvta_generic_to_shared(buf);
    #pragma unroll
    for (int it = 0; it < 2; it++) {
        int i = tid + it * 256;
        int m = i >> 2, c = i & 3;
        cp16(s + (m * 20 + 4 * c) * 4, g_Wh + (size_t)(row0 + m) * 256 + kt * 16 + 4 * c);
    }
    #pragma unroll
    for (int it = 0; it < 2; it++) {
        int i = tid + it * 256;
        int kp = i >> 5, c = i & 31;
        cp16(s + (2560 + kp * 136 + 4 * c) * 4,
             g_Xh + ((size_t)b * 256 + kt * 16 + kp) * 1024 + col0 + 4 * c);
    }
}

__global__ __launch_bounds__(256) void proj_kernel() {
    extern __shared__ float ps[];
    int b = blockIdx.z, row0 = blockIdx.y * 128, col0 = blockIdx.x * 128;
    bool isV = (row0 >= 256);
    int tid = threadIdx.x, w = tid >> 5, lane = tid & 31;
    int g = lane >> 2, kk = lane & 3;
    int wm = w >> 1, wn = w & 1;

    float acc[2][8][4];
    #pragma unroll
    for (int mi = 0; mi < 2; mi++)
        #pragma unroll
        for (int nf = 0; nf < 8; nf++)
            #pragma unroll
            for (int j = 0; j < 4; j++) acc[mi][nf][j] = 0.f;

    if (!isV) {
        // ---------- bf16 3-term path (q/k) ----------
        uint2* sbase = (uint2*)ps;
        cp_projqk(sbase, b, row0, col0, 0, tid);
        CP_COMMIT();
        CP_WAIT0();
        __syncthreads();
        for (int kt = 0; kt < 16; kt++) {
            uint2* cur = sbase + (kt & 1) * PBQK_U2;
            if (kt < 15) {
                cp_projqk(sbase + ((kt + 1) & 1) * PBQK_U2, b, row0, col0, kt + 1, tid);
                CP_COMMIT();
            }
            uint2* sW = cur;
            uint2* sX = cur + 2560;
            #pragma unroll
            for (int kc = 0; kc < 2; kc++) {
                uint32 Ab[2][4], As[2][4];
                #pragma unroll
                for (int mi = 0; mi < 2; mi++) {
                    int r = wm * 32 + mi * 16 + g;
                    uint2 w0 = sW[r * 20 + kk + 8 * kc];
                    uint2 w1 = sW[(r + 8) * 20 + kk + 8 * kc];
                    uint2 w2 = sW[r * 20 + kk + 4 + 8 * kc];
                    uint2 w3 = sW[(r + 8) * 20 + kk + 4 + 8 * kc];
                    Ab[mi][0] = w0.x; Ab[mi][1] = w1.x; Ab[mi][2] = w2.x; Ab[mi][3] = w3.x;
                    As[mi][0] = w0.y; As[mi][1] = w1.y; As[mi][2] = w2.y; As[mi][3] = w3.y;
                }
                #pragma unroll
                for (int nf = 0; nf < 8; nf++) {
                    int nc = wn * 64 + 8 * nf + g;
                    uint2 x0 = sX[(kk + 8 * kc) * 132 + nc];
                    uint2 x1 = sX[(kk + 4 + 8 * kc) * 132 + nc];
                    #pragma unroll
                    for (int mi = 0; mi < 2; mi++) {
                        mma_bf16(acc[mi][nf], Ab[mi], x0.x, x1.x);
                        mma_bf16(acc[mi][nf], As[mi], x0.x, x1.x);
                        mma_bf16(acc[mi][nf], Ab[mi], x0.y, x1.y);
                    }
                }
            }
            if (kt < 15) {
                CP_WAIT0();
                __syncthreads();
            }
        }
        #pragma unroll
        for (int mi = 0; mi < 2; mi++) {
            int o0 = row0 + wm * 32 + mi * 16 + g;
            int o1 = o0 + 8;
            float b0v = g_ball[o0], b1v = g_ball[o1];
            #pragma unroll
            for (int nf = 0; nf < 8; nf++) {
                int n = col0 + wn * 64 + 8 * nf + 2 * kk;
                *(float2*)&g_qk[((size_t)b * 256 + o0) * 1024 + n] =
                    make_float2(acc[mi][nf][0] + b0v, acc[mi][nf][1] + b0v);
                *(float2*)&g_qk[((size_t)b * 256 + o1) * 1024 + n] =
                    make_float2(acc[mi][nf][2] + b1v, acc[mi][nf][3] + b1v);
            }
        }
    } else {
        // ---------- fp16 single-term path (v) ----------
        uint32* sbase = (uint32*)ps;
        cp_projv(sbase, b, row0, col0, 0, tid);
        CP_COMMIT();
        CP_WAIT0();
        __syncthreads();
        for (int kt = 0; kt < 16; kt++) {
            uint32* cur = sbase + (kt & 1) * PBV_U1;
            if (kt < 15) {
                cp_projv(sbase + ((kt + 1) & 1) * PBV_U1, b, row0, col0, kt + 1, tid);
                CP_COMMIT();
            }
            uint32* sW = cur;
            uint32* sX = cur + 2560;
            #pragma unroll
            for (int kc = 0; kc < 2; kc++) {
                uint32 A[2][4];
                #pragma unroll
                for (int mi = 0; mi < 2; mi++) {
                    int r = wm * 32 + mi * 16 + g;
                    A[mi][0] = sW[r * 20 + kk + 8 * kc];
                    A[mi][1] = sW[(r + 8) * 20 + kk + 8 * kc];
                    A[mi][2] = sW[r * 20 + kk + 4 + 8 * kc];
                    A[mi][3] = sW[(r + 8) * 20 + kk + 4 + 8 * kc];
                }
                #pragma unroll
                for (int nf = 0; nf < 8; nf++) {
                    int nc = wn * 64 + 8 * nf + g;
                    uint32 x0 = sX[(kk + 8 * kc) * 136 + nc];
                    uint32 x1 = sX[(kk + 4 + 8 * kc) * 136 + nc];
                    #pragma unroll
                    for (int mi = 0; mi < 2; mi++)
                        mma_fp16(acc[mi][nf], A[mi], x0, x1);
                }
            }
            if (kt < 15) {
                CP_WAIT0();
                __syncthreads();
            }
        }
        // epilogue: transpose to sOut[n][c], then write fp16 V tile image directly
        __syncthreads();
        float* sOut = ps;   // 128 n x 132
        #pragma unroll
        for (int mi = 0; mi < 2; mi++) {
            int o0 = row0 + wm * 32 + mi * 16 + g;
            int ol = wm * 32 + mi * 16 + g;
            float b0v = g_ball[o0], b1v = g_ball[o0 + 8];
            #pragma unroll
            for (int nf = 0; nf < 8; nf++) {
                int n = wn * 64 + 8 * nf + 2 * kk;
                sOut[n * 132 + ol] = acc[mi][nf][0] + b0v;
                sOut[(n + 1) * 132 + ol] = acc[mi][nf][1] + b0v;
                sOut[n * 132 + ol + 8] = acc[mi][nf][2] + b1v;
                sOut[(n + 1) * 132 + ol + 8] = acc[mi][nf][3] + b1v;
            }
        }
        __syncthreads();
        int h = (row0 - 256) >> 7;
        float* tb0 = g_tile + ((size_t)((b * 4 + h) * 16) + (col0 >> 6)) * TILE_F + 4224;
        #pragma unroll
        for (int it = 0; it < 16; it++) {
            int idx = tid + it * 256;     // 4096: c 0..127, dp 0..15, ntl 0..1
            int c = idx & 127, dp = (idx >> 7) & 15, ntl = idx >> 11;
            int r0 = 16 * (dp >> 2) + 2 * (dp & 3) + ntl * 64;
            uint2 val = make_uint2(
                pack_h2(sOut[r0 * 132 + c],       sOut[(r0 + 1) * 132 + c]),
                pack_h2(sOut[(r0 + 8) * 132 + c], sOut[(r0 + 9) * 132 + c]));
            ((uint2*)(tb0 + (size_t)ntl * TILE_F))[dp * 132 + c] = val;
        }
    }
}

// ---------------- 3.5) prep: fragment-ready K' (bf16 split) image only ----------------
__device__ __forceinline__ float kprime(size_t qkbase, int h, int ng, int d, int n) {
    return (d < 32) ? g_qk[qkbase + (size_t)(128 + h * 32 + d) * 1024 + ng + n]
                    : g_qk[qkbase + (size_t)(h * 32 + d - 32) * 1024 + ng + n];
}

__global__ __launch_bounds__(256) void prep_kernel() {
    int nt = blockIdx.x, h = blockIdx.y, b = blockIdx.z;
    int tid = threadIdx.x;
    int ng = nt * 64;
    size_t qkbase = (size_t)b * 256 * 1024;
    float* dst = g_tile + (size_t)((b * 4 + h) * 16 + nt) * TILE_F;

    #pragma unroll
    for (int it = 0; it < 4; it++) {
        int i = tid + it * 256;
        int dp = i >> 6, n = i & 63;
        int kc = dp >> 2, kk = dp & 3;
        int r0 = 16 * kc + 2 * kk;
        float v0 = kprime(qkbase, h, ng, r0, n);
        float v1 = kprime(qkbase, h, ng, r0 + 1, n);
        float v8 = kprime(qkbase, h, ng, r0 + 8, n);
        float v9 = kprime(qkbase, h, ng, r0 + 9, n);
        uint4 o;
        split2_bf(v0, v1, o.x, o.z);
        split2_bf(v8, v9, o.y, o.w);
        ((uint4*)dst)[dp * 66 + n] = o;
    }
}

// ---------------- 4) flash attention: bf16x3 QK + fp16 PV (P in regs) ----------------
#define ATTN_SMEM_FLOATS (2 * TILE_F)   // 18432 floats = 73728 B

__global__ __launch_bounds__(256, 1) void attn_kernel(const float* __restrict__ x,
                                                      const float* __restrict__ rel_h,
                                                      const float* __restrict__ rel_w,
                                                      float* __restrict__ out)
{
    extern __shared__ float sm[];
    int mt = blockIdx.x, h = blockIdx.y, b = blockIdx.z;
    int tid = threadIdx.x, w = tid >> 5, lane = tid & 31;
    int g = lane >> 2, kk = lane & 3;
    int mg = mt * 128;
    int rl = 16 * w + g, rh = rl + 8;
    size_t qkbase = (size_t)b * 256 * 1024;
    const float* tbase = g_tile + (size_t)((b * 4 + h) * 16) * TILE_F;

    cp_tile(sm, tbase, tid);
    CP_COMMIT();

    float* sQ = sm + TILE_F;
    #pragma unroll
    for (int it = 0; it < 8; it++) {
        int i = tid + it * 256;
        int d = i >> 5, m4 = (i & 31) << 2;
        float4 v;
        if (d < 32) {
            v = *(const float4*)&g_qk[qkbase + (size_t)(h * 32 + d) * 1024 + mg + m4];
        } else {
            int hd = h * 32 + (d - 32);
            int n0 = mg + m4;
            float ww = rel_w[hd * 32 + (n0 >> 5)];
            float4 rh4 = *(const float4*)&rel_h[hd * 32 + (n0 & 31)];
            v = make_float4(rh4.x + ww, rh4.y + ww, rh4.z + ww, rh4.w + ww);
        }
        sQ[(m4 + 0) * 68 + d] = v.x;
        sQ[(m4 + 1) * 68 + d] = v.y;
        sQ[(m4 + 2) * 68 + d] = v.z;
        sQ[(m4 + 3) * 68 + d] = v.w;
    }
    __syncthreads();

    const float LOG2E = 1.4426950408889634f;
    uint32 Qb[4][4], Qs[4][4];
    #pragma unroll
    for (int kc = 0; kc < 4; kc++) {
        int klo = 16 * kc + 2 * kk;
        int khi = klo + 8;
        split2_bf(LOG2E * sQ[rl * 68 + klo], LOG2E * sQ[rl * 68 + klo + 1], Qb[kc][0], Qs[kc][0]);
        split2_bf(LOG2E * sQ[rh * 68 + klo], LOG2E * sQ[rh * 68 + klo + 1], Qb[kc][1], Qs[kc][1]);
        split2_bf(LOG2E * sQ[rl * 68 + khi], LOG2E * sQ[rl * 68 + khi + 1], Qb[kc][2], Qs[kc][2]);
        split2_bf(LOG2E * sQ[rh * 68 + khi], LOG2E * sQ[rh * 68 + khi + 1], Qb[kc][3], Qs[kc][3]);
    }
    float m_l = -1e30f, m_h = -1e30f, l_l = 0.f, l_h = 0.f;
    float O[16][4];
    #pragma unroll
    for (int cf = 0; cf < 16; cf++)
        #pragma unroll
        for (int j = 0; j < 4; j++) O[cf][j] = 0.f;

    CP_WAIT0();
    __syncthreads();

    for (int nt = 0; nt < 16; nt++) {
        float* buf = sm + (nt & 1) * TILE_F;
        if (nt < 15) {
            cp_tile(sm + ((nt + 1) & 1) * TILE_F, tbase + (size_t)(nt + 1) * TILE_F, tid);
            CP_COMMIT();
        }
        const uint4* cK4 = (const uint4*)buf;
        const uint2* cV2 = (const uint2*)(buf + 4224);

        float S[8][4];
        #pragma unroll
        for (int f = 0; f < 8; f++)
            #pragma unroll
            for (int j = 0; j < 4; j++) S[f][j] = 0.f;
        #pragma unroll
        for (int kc = 0; kc < 4; kc++) {
            const uint4* kr = cK4 + (4 * kc + kk) * 66 + g;
            #pragma unroll
            for (int f = 0; f < 8; f++) {
                uint4 kb = kr[8 * f];
                mma_bf16(S[f], Qb[kc], kb.x, kb.y);
                mma_bf16(S[f], Qs[kc], kb.x, kb.y);
                mma_bf16(S[f], Qb[kc], kb.z, kb.w);
            }
        }

        float mlo = -1e30f, mhi = -1e30f;
        #pragma unroll
        for (int f = 0; f < 8; f++) {
            mlo = fmaxf(mlo, fmaxf(S[f][0], S[f][1]));
            mhi = fmaxf(mhi, fmaxf(S[f][2], S[f][3]));
        }
        mlo = fmaxf(mlo, __shfl_xor_sync(0xffffffffu, mlo, 1));
        mlo = fmaxf(mlo, __shfl_xor_sync(0xffffffffu, mlo, 2));
        mhi = fmaxf(mhi, __shfl_xor_sync(0xffffffffu, mhi, 1));
        mhi = fmaxf(mhi, __shfl_xor_sync(0xffffffffu, mhi, 2));
        float mnl = fmaxf(m_l, mlo), mnh = fmaxf(m_h, mhi);
        float scl = ex2f(m_l - mnl), sch = ex2f(m_h - mnh);
        m_l = mnl; m_h = mnh;
        float slo = 0.f, shi = 0.f;
        #pragma unroll
        for (int f = 0; f < 8; f++) {
            float p0 = ex2f(S[f][0] - mnl);
            float p1 = ex2f(S[f][1] - mnl);
            float p2 = ex2f(S[f][2] - mnh);
            float p3 = ex2f(S[f][3] - mnh);
            slo += p0 + p1;
            shi += p2 + p3;
            S[f][0] = p0; S[f][1] = p1; S[f][2] = p2; S[f][3] = p3;
        }
        slo += __shfl_xor_sync(0xffffffffu, slo, 1);
        slo += __shfl_xor_sync(0xffffffffu, slo, 2);
        shi += __shfl_xor_sync(0xffffffffu, shi, 1);
        shi += __shfl_xor_sync(0xffffffffu, shi, 2);
        l_l = l_l * scl + slo;
        l_h = l_h * sch + shi;

        // deferred rescale: skip when the whole warp's scales are exactly 1
        if (!__all_sync(0xffffffffu, (scl == 1.f) && (sch == 1.f))) {
            #pragma unroll
            for (int cf = 0; cf < 16; cf++) {
                O[cf][0] *= scl; O[cf][1] *= scl;
                O[cf][2] *= sch; O[cf][3] *= sch;
            }
        }
        #pragma unroll
        for (int kc = 0; kc < 4; kc++) {
            uint32 a[4];
            a[0] = pack_h2(S[2 * kc][0],     S[2 * kc][1]);
            a[1] = pack_h2(S[2 * kc][2],     S[2 * kc][3]);
            a[2] = pack_h2(S[2 * kc + 1][0], S[2 * kc + 1][1]);
            a[3] = pack_h2(S[2 * kc + 1][2], S[2 * kc + 1][3]);
            const uint2* vr = cV2 + (4 * kc + kk) * 132 + g;
            #pragma unroll
            for (int cf = 0; cf < 16; cf++) {
                uint2 v2 = vr[8 * cf];
                mma_fp16(O[cf], a, v2.x, v2.y);
            }
        }
        if (nt < 15) {
            CP_WAIT0();
            __syncthreads();
        }
    }

    __syncthreads();
    float il = 1.0f / l_l, ih = 1.0f / l_h;
    float* sO = sm;
    #pragma unroll
    for (int cf = 0; cf < 16; cf++) {
        int col = 8 * cf + 2 * kk;
        *(float2*)&sO[rl * 130 + col] = make_float2(O[cf][0] * il, O[cf][1] * il);
        *(float2*)&sO[rh * 130 + col] = make_float2(O[cf][2] * ih, O[cf][3] * ih);
    }
    __syncthreads();
    {
        int m = tid & 127;
        int c0 = (tid >> 7) * 64;
        #pragma unroll 4
        for (int k2 = 0; k2 < 64; k2++) {
            int c = c0 + k2;
            size_t a = ((size_t)b * 512 + h * 128 + c) * 1024 + mg + m;
            out[a] = sO[m * 130 + c] + x[a];
        }
    }
}

// ---------------- launch ----------------
extern "C" void kernel_launch(void* const* d_in, const int* in_sizes, int n_in,
                              void* d_out, int out_size)
{
    const float* x     = (const float*)d_in[0];
    const float* Wq    = (const float*)d_in[1];
    const float* bq    = (const float*)d_in[2];
    const float* qg    = (const float*)d_in[3];
    const float* qb    = (const float*)d_in[4];
    const float* qm    = (const float*)d_in[5];
    const float* qv    = (const float*)d_in[6];
    const float* Wk    = (const float*)d_in[7];
    const float* bk    = (const float*)d_in[8];
    const float* kg    = (const float*)d_in[9];
    const float* kb    = (const float*)d_in[10];
    const float* km    = (const float*)d_in[11];
    const float* kv    = (const float*)d_in[12];
    const float* Wv    = (const float*)d_in[13];
    const float* bv    = (const float*)d_in[14];
    const float* vg    = (const float*)d_in[15];
    const float* vb    = (const float*)d_in[16];
    const float* vm    = (const float*)d_in[17];
    const float* vvar  = (const float*)d_in[18];
    const float* rel_h = (const float*)d_in[19];
    const float* rel_w = (const float*)d_in[20];
    float* out = (float*)d_out;

    cudaFuncSetAttribute(attn_kernel, cudaFuncAttributeMaxDynamicSharedMemorySize,
                         ATTN_SMEM_FLOATS * (int)sizeof(float));
    cudaFuncSetAttribute(proj_kernel, cudaFuncAttributeMaxDynamicSharedMemorySize,
                         PROJ_SMEM_BYTES);

    fold_kernel<<<768, 256>>>(Wq, bq, qg, qb, qm, qv,
                              Wk, bk, kg, kb, km, kv,
                              Wv, bv, vg, vb, vm, vvar);
    xsplit_kernel<<<dim3(256, 16), 256>>>(x);
    proj_kernel<<<dim3(8, 6, 16), 256, PROJ_SMEM_BYTES>>>();
    prep_kernel<<<dim3(16, 4, 16), 256>>>();
    attn_kernel<<<dim3(8, 4, 16), 256, ATTN_SMEM_FLOATS * sizeof(float)>>>(x, rel_h, rel_w, out);
}

// round 12
// speedup vs baseline: 4.6630x; 1.2417x over previous
#include <cuda_runtime.h>
#include <cuda_bf16.h>
#include <cuda_fp16.h>

typedef unsigned int uint32;

#define EPS 1e-5f
#define TILE_F 9216    // floats per tile image: K-bf16split 4224 + V-fp16 4224 + pad

// ---------------- scratch (device globals; no cudaMalloc allowed) ----------------
__device__ float g_ball[768];               // folded biases
__device__ float g_qk[16 * 256 * 1024];     // [b][o][n], o<128: q, o in [128,256): k
__device__ __align__(16) uint2 g_Wbs[768 * 256];        // W big/small bf16 pairs [o][kpair]
__device__ __align__(16) uint2 g_Xbs[16 * 256 * 1024];  // X big/small bf16 pairs [b][kpair][n]
__device__ __align__(16) uint32 g_Wh[768 * 256];        // W fp16 pairs [o][kpair]
__device__ __align__(16) uint32 g_Xh[16 * 256 * 1024];  // X fp16 pairs [b][kpair][n]
__device__ __align__(16) float g_tile[16 * 4 * 16 * TILE_F]; // fragment-ready K'/V tiles

// ---------------- mma / pack helpers ----------------
__device__ __forceinline__ void mma_bf16(float* c, const uint32* a, uint32 b0, uint32 b1) {
    asm volatile("mma.sync.aligned.m16n8k16.row.col.f32.bf16.bf16.f32 "
        "{%0,%1,%2,%3}, {%4,%5,%6,%7}, {%8,%9}, {%0,%1,%2,%3};"
        : "+f"(c[0]), "+f"(c[1]), "+f"(c[2]), "+f"(c[3])
        : "r"(a[0]), "r"(a[1]), "r"(a[2]), "r"(a[3]), "r"(b0), "r"(b1));
}
__device__ __forceinline__ void mma_fp16(float* c, const uint32* a, uint32 b0, uint32 b1) {
    asm volatile("mma.sync.aligned.m16n8k16.row.col.f32.f16.f16.f32 "
        "{%0,%1,%2,%3}, {%4,%5,%6,%7}, {%8,%9}, {%0,%1,%2,%3};"
        : "+f"(c[0]), "+f"(c[1]), "+f"(c[2]), "+f"(c[3])
        : "r"(a[0]), "r"(a[1]), "r"(a[2]), "r"(a[3]), "r"(b0), "r"(b1));
}

// split v0,v1 into bf16 big/small packed pairs (element0 in low 16 bits)
__device__ __forceinline__ void split2_bf(float v0, float v1, uint32& bb, uint32& ss) {
    float b0 = __bfloat162float(__float2bfloat16_rn(v0));
    float b1 = __bfloat162float(__float2bfloat16_rn(v1));
    __nv_bfloat162 tb = __floats2bfloat162_rn(b0, b1);
    __nv_bfloat162 ts = __floats2bfloat162_rn(v0 - b0, v1 - b1);
    bb = *reinterpret_cast<uint32*>(&tb);
    ss = *reinterpret_cast<uint32*>(&ts);
}
__device__ __forceinline__ uint32 pack_h2(float v0, float v1) {
    __half2 h = __floats2half2_rn(v0, v1);
    return *reinterpret_cast<uint32*>(&h);
}
__device__ __forceinline__ float ex2f(float x) {
    float r; asm("ex2.approx.ftz.f32 %0, %1;" : "=f"(r) : "f"(x)); return r;
}

// ---------------- cp.async helpers ----------------
__device__ __forceinline__ void cp16(uint32 sdst, const void* gsrc) {
    asm volatile("cp.async.cg.shared.global [%0], [%1], 16;\n" :: "r"(sdst), "l"(gsrc));
}
#define CP_COMMIT() asm volatile("cp.async.commit_group;\n" ::: "memory")
#define CP_WAIT0()  asm volatile("cp.async.wait_group 0;\n" ::: "memory")
#define CP_WAIT1()  asm volatile("cp.async.wait_group 1;\n" ::: "memory")

// 128-thread tile copy for attn
__device__ __forceinline__ void cp_tile(float* smem_dst, const float* gsrc, int tid) {
    uint32 s = (uint32)__cvta_generic_to_shared(smem_dst);
    #pragma unroll
    for (int it = 0; it < 18; it++) {
        int i = tid + it * 128;          // 2304 float4s = 9216 floats
        cp16(s + i * 16, gsrc + i * 4);
    }
}

// ---------------- 1) fold BN into conv weights; write bf16-split + fp16 images ----------------
__global__ void fold_kernel(
    const float* __restrict__ Wq, const float* __restrict__ bq,
    const float* __restrict__ qg, const float* __restrict__ qb,
    const float* __restrict__ qm, const float* __restrict__ qvv,
    const float* __restrict__ Wk, const float* __restrict__ bk,
    const float* __restrict__ kg, const float* __restrict__ kb,
    const float* __restrict__ km, const float* __restrict__ kvv,
    const float* __restrict__ Wv, const float* __restrict__ bv,
    const float* __restrict__ vg, const float* __restrict__ vb,
    const float* __restrict__ vm, const float* __restrict__ vvv)
{
    int o = blockIdx.x;  // 0..767
    const float* src;
    float s, bias;
    if (o < 128) {
        s = qg[o] * rsqrtf(qvv[o] + EPS);
        bias = (bq[o] - qm[o]) * s + qb[o];
        src = Wq + o * 512;
    } else if (o < 256) {
        int oo = o - 128;
        s = kg[oo] * rsqrtf(kvv[oo] + EPS);
        bias = (bk[oo] - km[oo]) * s + kb[oo];
        src = Wk + oo * 512;
    } else {
        int oo = o - 256;
        s = vg[oo] * rsqrtf(vvv[oo] + EPS);
        bias = (bv[oo] - vm[oo]) * s + vb[oo];
        src = Wv + oo * 512;
    }
    int p = threadIdx.x;           // pair 0..255
    float w0 = src[2 * p] * s;
    float w1 = src[2 * p + 1] * s;
    uint32 bb, ss;
    split2_bf(w0, w1, bb, ss);
    g_Wbs[o * 256 + p] = make_uint2(bb, ss);
    g_Wh[o * 256 + p] = pack_h2(w0, w1);
    if (p == 0) g_ball[o] = bias;
}

// ---------------- 2) pre-split X into bf16 big/small + fp16 pair images ----------------
__global__ __launch_bounds__(256) void xsplit_kernel(const float* __restrict__ x) {
    int kp = blockIdx.x, b = blockIdx.y;
    int tid = threadIdx.x;
    const float* r0 = x + ((size_t)b * 512 + 2 * kp) * 1024;
    const float* r1 = r0 + 1024;
    uint2* dst = g_Xbs + ((size_t)b * 256 + kp) * 1024;
    uint32* dsth = g_Xh + ((size_t)b * 256 + kp) * 1024;
    int n4 = tid * 4;
    float4 a = *(const float4*)&r0[n4];
    float4 c = *(const float4*)&r1[n4];
    uint2 o0, o1, o2, o3;
    split2_bf(a.x, c.x, o0.x, o0.y);
    split2_bf(a.y, c.y, o1.x, o1.y);
    split2_bf(a.z, c.z, o2.x, o2.y);
    split2_bf(a.w, c.w, o3.x, o3.y);
    dst[n4] = o0; dst[n4 + 1] = o1; dst[n4 + 2] = o2; dst[n4 + 3] = o3;
    uint4 hv;
    hv.x = pack_h2(a.x, c.x);
    hv.y = pack_h2(a.y, c.y);
    hv.z = pack_h2(a.z, c.z);
    hv.w = pack_h2(a.w, c.w);
    *(uint4*)&dsth[n4] = hv;
}

// ---------------- 3) QKV projection (3-stage cp.async pipeline) ----------------
// QK blocks (rb<2): bf16 3-term compensated -> g_qk.
// V blocks (rb>=2): fp16 single-term -> fp16 V tile image in g_tile (direct).
#define PBQK_U2 4672
#define PBV_U1 4736
#define PROJ_SMEM_BYTES 112128   // 3 * PBQK_U2 * 8; covers V (3*18944) and epilogue (67584)

__device__ __forceinline__ void cp_projqk(uint2* buf, int b, int row0, int col0, int kt, int tid) {
    uint32 s = (uint32)__cvta_generic_to_shared(buf);
    #pragma unroll
    for (int it = 0; it < 4; it++) {
        int i = tid + it * 256;
        int m = i >> 3, c = i & 7;
        cp16(s + (m * 20 + 2 * c) * 8, g_Wbs + (size_t)(row0 + m) * 256 + kt * 16 + 2 * c);
    }
    #pragma unroll
    for (int it = 0; it < 4; it++) {
        int i = tid + it * 256;
        int kp = i >> 6, c = i & 63;
        cp16(s + (2560 + kp * 132 + 2 * c) * 8,
             g_Xbs + ((size_t)b * 256 + kt * 16 + kp) * 1024 + col0 + 2 * c);
    }
}

__device__ __forceinline__ void cp_projv(uint32* buf, int b, int row0, int col0, int kt, int tid) {
    uint32 s = (uint32)__cvta_generic_to_shared(buf);
    #pragma unroll
    for (int it = 0; it < 2; it++) {
        int i = tid + it * 256;
        int m = i >> 2, c = i & 3;
        cp16(s + (m * 20 + 4 * c) * 4, g_Wh + (size_t)(row0 + m) * 256 + kt * 16 + 4 * c);
    }
    #pragma unroll
    for (int it = 0; it < 2; it++) {
        int i = tid + it * 256;
        int kp = i >> 5, c = i & 31;
        cp16(s + (2560 + kp * 136 + 4 * c) * 4,
             g_Xh + ((size_t)b * 256 + kt * 16 + kp) * 1024 + col0 + 4 * c);
    }
}

__global__ __launch_bounds__(256) void proj_kernel() {
    extern __shared__ float ps[];
    int b = blockIdx.z, row0 = blockIdx.y * 128, col0 = blockIdx.x * 128;
    bool isV = (row0 >= 256);
    int tid = threadIdx.x, w = tid >> 5, lane = tid & 31;
    int g = lane >> 2, kk = lane & 3;
    int wm = w >> 1, wn = w & 1;

    float acc[2][8][4];
    #pragma unroll
    for (int mi = 0; mi < 2; mi++)
        #pragma unroll
        for (int nf = 0; nf < 8; nf++)
            #pragma unroll
            for (int j = 0; j < 4; j++) acc[mi][nf][j] = 0.f;

    if (!isV) {
        // ---------- bf16 3-term path (q/k), 3-stage pipeline ----------
        uint2* sbase = (uint2*)ps;
        cp_projqk(sbase, b, row0, col0, 0, tid);
        CP_COMMIT();
        cp_projqk(sbase + PBQK_U2, b, row0, col0, 1, tid);
        CP_COMMIT();
        int bufidx = 0;
        for (int kt = 0; kt < 16; kt++) {
            CP_WAIT1();          // slab kt complete (kt+1 may be in flight)
            __syncthreads();     // all warps done with slab kt-1's buffer
            if (kt < 14) {
                int nb = bufidx + 2; if (nb >= 3) nb -= 3;
                cp_projqk(sbase + nb * PBQK_U2, b, row0, col0, kt + 2, tid);
                CP_COMMIT();
            }
            uint2* cur = sbase + bufidx * PBQK_U2;
            uint2* sW = cur;
            uint2* sX = cur + 2560;
            #pragma unroll
            for (int kc = 0; kc < 2; kc++) {
                uint32 Ab[2][4], As[2][4];
                #pragma unroll
                for (int mi = 0; mi < 2; mi++) {
                    int r = wm * 32 + mi * 16 + g;
                    uint2 w0 = sW[r * 20 + kk + 8 * kc];
                    uint2 w1 = sW[(r + 8) * 20 + kk + 8 * kc];
                    uint2 w2 = sW[r * 20 + kk + 4 + 8 * kc];
                    uint2 w3 = sW[(r + 8) * 20 + kk + 4 + 8 * kc];
                    Ab[mi][0] = w0.x; Ab[mi][1] = w1.x; Ab[mi][2] = w2.x; Ab[mi][3] = w3.x;
                    As[mi][0] = w0.y; As[mi][1] = w1.y; As[mi][2] = w2.y; As[mi][3] = w3.y;
                }
                #pragma unroll
                for (int nf = 0; nf < 8; nf++) {
                    int nc = wn * 64 + 8 * nf + g;
                    uint2 x0 = sX[(kk + 8 * kc) * 132 + nc];
                    uint2 x1 = sX[(kk + 4 + 8 * kc) * 132 + nc];
                    #pragma unroll
                    for (int mi = 0; mi < 2; mi++) {
                        mma_bf16(acc[mi][nf], Ab[mi], x0.x, x1.x);
                        mma_bf16(acc[mi][nf], As[mi], x0.x, x1.x);
                        mma_bf16(acc[mi][nf], Ab[mi], x0.y, x1.y);
                    }
                }
            }
            if (++bufidx == 3) bufidx = 0;
        }
        #pragma unroll
        for (int mi = 0; mi < 2; mi++) {
            int o0 = row0 + wm * 32 + mi * 16 + g;
            int o1 = o0 + 8;
            float b0v = g_ball[o0], b1v = g_ball[o1];
            #pragma unroll
            for (int nf = 0; nf < 8; nf++) {
                int n = col0 + wn * 64 + 8 * nf + 2 * kk;
                *(float2*)&g_qk[((size_t)b * 256 + o0) * 1024 + n] =
                    make_float2(acc[mi][nf][0] + b0v, acc[mi][nf][1] + b0v);
                *(float2*)&g_qk[((size_t)b * 256 + o1) * 1024 + n] =
                    make_float2(acc[mi][nf][2] + b1v, acc[mi][nf][3] + b1v);
            }
        }
    } else {
        // ---------- fp16 single-term path (v), 3-stage pipeline ----------
        uint32* sbase = (uint32*)ps;
        cp_projv(sbase, b, row0, col0, 0, tid);
        CP_COMMIT();
        cp_projv(sbase + PBV_U1, b, row0, col0, 1, tid);
        CP_COMMIT();
        int bufidx = 0;
        for (int kt = 0; kt < 16; kt++) {
            CP_WAIT1();
            __syncthreads();
            if (kt < 14) {
                int nb = bufidx + 2; if (nb >= 3) nb -= 3;
                cp_projv(sbase + nb * PBV_U1, b, row0, col0, kt + 2, tid);
                CP_COMMIT();
            }
            uint32* cur = sbase + bufidx * PBV_U1;
            uint32* sW = cur;
            uint32* sX = cur + 2560;
            #pragma unroll
            for (int kc = 0; kc < 2; kc++) {
                uint32 A[2][4];
                #pragma unroll
                for (int mi = 0; mi < 2; mi++) {
                    int r = wm * 32 + mi * 16 + g;
                    A[mi][0] = sW[r * 20 + kk + 8 * kc];
                    A[mi][1] = sW[(r + 8) * 20 + kk + 8 * kc];
                    A[mi][2] = sW[r * 20 + kk + 4 + 8 * kc];
                    A[mi][3] = sW[(r + 8) * 20 + kk + 4 + 8 * kc];
                }
                #pragma unroll
                for (int nf = 0; nf < 8; nf++) {
                    int nc = wn * 64 + 8 * nf + g;
                    uint32 x0 = sX[(kk + 8 * kc) * 136 + nc];
                    uint32 x1 = sX[(kk + 4 + 8 * kc) * 136 + nc];
                    #pragma unroll
                    for (int mi = 0; mi < 2; mi++)
                        mma_fp16(acc[mi][nf], A[mi], x0, x1);
                }
            }
            if (++bufidx == 3) bufidx = 0;
        }
        // epilogue: transpose to sOut[n][c], then write fp16 V tile image directly
        CP_WAIT0();
        __syncthreads();
        float* sOut = ps;   // 128 n x 132
        #pragma unroll
        for (int mi = 0; mi < 2; mi++) {
            int o0 = row0 + wm * 32 + mi * 16 + g;
            int ol = wm * 32 + mi * 16 + g;
            float b0v = g_ball[o0], b1v = g_ball[o0 + 8];
            #pragma unroll
            for (int nf = 0; nf < 8; nf++) {
                int n = wn * 64 + 8 * nf + 2 * kk;
                sOut[n * 132 + ol] = acc[mi][nf][0] + b0v;
                sOut[(n + 1) * 132 + ol] = acc[mi][nf][1] + b0v;
                sOut[n * 132 + ol + 8] = acc[mi][nf][2] + b1v;
                sOut[(n + 1) * 132 + ol + 8] = acc[mi][nf][3] + b1v;
            }
        }
        __syncthreads();
        int h = (row0 - 256) >> 7;
        float* tb0 = g_tile + ((size_t)((b * 4 + h) * 16) + (col0 >> 6)) * TILE_F + 4224;
        #pragma unroll
        for (int it = 0; it < 16; it++) {
            int idx = tid + it * 256;     // 4096: c 0..127, dp 0..15, ntl 0..1
            int c = idx & 127, dp = (idx >> 7) & 15, ntl = idx >> 11;
            int r0 = 16 * (dp >> 2) + 2 * (dp & 3) + ntl * 64;
            uint2 val = make_uint2(
                pack_h2(sOut[r0 * 132 + c],       sOut[(r0 + 1) * 132 + c]),
                pack_h2(sOut[(r0 + 8) * 132 + c], sOut[(r0 + 9) * 132 + c]));
            ((uint2*)(tb0 + (size_t)ntl * TILE_F))[dp * 132 + c] = val;
        }
    }
}

// ---------------- 3.5) prep: fragment-ready K' (bf16 split) image only ----------------
__device__ __forceinline__ float kprime(size_t qkbase, int h, int ng, int d, int n) {
    return (d < 32) ? g_qk[qkbase + (size_t)(128 + h * 32 + d) * 1024 + ng + n]
                    : g_qk[qkbase + (size_t)(h * 32 + d - 32) * 1024 + ng + n];
}

__global__ __launch_bounds__(256) void prep_kernel() {
    int nt = blockIdx.x, h = blockIdx.y, b = blockIdx.z;
    int tid = threadIdx.x;
    int ng = nt * 64;
    size_t qkbase = (size_t)b * 256 * 1024;
    float* dst = g_tile + (size_t)((b * 4 + h) * 16 + nt) * TILE_F;

    #pragma unroll
    for (int it = 0; it < 4; it++) {
        int i = tid + it * 256;
        int dp = i >> 6, n = i & 63;
        int kc = dp >> 2, kk = dp & 3;
        int r0 = 16 * kc + 2 * kk;
        float v0 = kprime(qkbase, h, ng, r0, n);
        float v1 = kprime(qkbase, h, ng, r0 + 1, n);
        float v8 = kprime(qkbase, h, ng, r0 + 8, n);
        float v9 = kprime(qkbase, h, ng, r0 + 9, n);
        uint4 o;
        split2_bf(v0, v1, o.x, o.z);
        split2_bf(v8, v9, o.y, o.w);
        ((uint4*)dst)[dp * 66 + n] = o;
    }
}

// ---------------- 4) flash attention: 64-query tiles, 128 threads, 3 CTAs/SM ----------------
#define ATTN_SMEM_FLOATS (2 * TILE_F)   // 18432 floats = 73728 B

__global__ __launch_bounds__(128, 3) void attn_kernel(const float* __restrict__ x,
                                                      const float* __restrict__ rel_h,
                                                      const float* __restrict__ rel_w,
                                                      float* __restrict__ out)
{
    extern __shared__ float sm[];
    int mt = blockIdx.x, h = blockIdx.y, b = blockIdx.z;
    int tid = threadIdx.x, w = tid >> 5, lane = tid & 31;
    int g = lane >> 2, kk = lane & 3;
    int mg = mt * 64;
    int rl = 16 * w + g, rh = rl + 8;
    size_t qkbase = (size_t)b * 256 * 1024;
    const float* tbase = g_tile + (size_t)((b * 4 + h) * 16) * TILE_F;

    cp_tile(sm, tbase, tid);
    CP_COMMIT();

    // stage Q' [64 m][68] (d-major transpose + pos inline)
    float* sQ = sm + TILE_F;
    #pragma unroll
    for (int it = 0; it < 8; it++) {
        int i = tid + it * 128;   // 1024 float4 units: 64 d x 16 m4
        int d = i >> 4, m4 = (i & 15) << 2;
        float4 v;
        if (d < 32) {
            v = *(const float4*)&g_qk[qkbase + (size_t)(h * 32 + d) * 1024 + mg + m4];
        } else {
            int hd = h * 32 + (d - 32);
            int n0 = mg + m4;
            float ww = rel_w[hd * 32 + (n0 >> 5)];
            float4 rh4 = *(const float4*)&rel_h[hd * 32 + (n0 & 31)];
            v = make_float4(rh4.x + ww, rh4.y + ww, rh4.z + ww, rh4.w + ww);
        }
        sQ[(m4 + 0) * 68 + d] = v.x;
        sQ[(m4 + 1) * 68 + d] = v.y;
        sQ[(m4 + 2) * 68 + d] = v.z;
        sQ[(m4 + 3) * 68 + d] = v.w;
    }
    __syncthreads();

    const float LOG2E = 1.4426950408889634f;
    uint32 Qb[4][4], Qs[4][4];
    #pragma unroll
    for (int kc = 0; kc < 4; kc++) {
        int klo = 16 * kc + 2 * kk;
        int khi = klo + 8;
        split2_bf(LOG2E * sQ[rl * 68 + klo], LOG2E * sQ[rl * 68 + klo + 1], Qb[kc][0], Qs[kc][0]);
        split2_bf(LOG2E * sQ[rh * 68 + klo], LOG2E * sQ[rh * 68 + klo + 1], Qb[kc][1], Qs[kc][1]);
        split2_bf(LOG2E * sQ[rl * 68 + khi], LOG2E * sQ[rl * 68 + khi + 1], Qb[kc][2], Qs[kc][2]);
        split2_bf(LOG2E * sQ[rh * 68 + khi], LOG2E * sQ[rh * 68 + khi + 1], Qb[kc][3], Qs[kc][3]);
    }
    float m_l = -1e30f, m_h = -1e30f, l_l = 0.f, l_h = 0.f;
    float O[16][4];
    #pragma unroll
    for (int cf = 0; cf < 16; cf++)
        #pragma unroll
        for (int j = 0; j < 4; j++) O[cf][j] = 0.f;

    CP_WAIT0();
    __syncthreads();

    for (int nt = 0; nt < 16; nt++) {
        float* buf = sm + (nt & 1) * TILE_F;
        if (nt < 15) {
            cp_tile(sm + ((nt + 1) & 1) * TILE_F, tbase + (size_t)(nt + 1) * TILE_F, tid);
            CP_COMMIT();
        }
        const uint4* cK4 = (const uint4*)buf;
        const uint2* cV2 = (const uint2*)(buf + 4224);

        float S[8][4];
        #pragma unroll
        for (int f = 0; f < 8; f++)
            #pragma unroll
            for (int j = 0; j < 4; j++) S[f][j] = 0.f;
        #pragma unroll
        for (int kc = 0; kc < 4; kc++) {
            const uint4* kr = cK4 + (4 * kc + kk) * 66 + g;
            #pragma unroll
            for (int f = 0; f < 8; f++) {
                uint4 kb = kr[8 * f];
                mma_bf16(S[f], Qb[kc], kb.x, kb.y);
                mma_bf16(S[f], Qs[kc], kb.x, kb.y);
                mma_bf16(S[f], Qb[kc], kb.z, kb.w);
            }
        }

        float mlo = -1e30f, mhi = -1e30f;
        #pragma unroll
        for (int f = 0; f < 8; f++) {
            mlo = fmaxf(mlo, fmaxf(S[f][0], S[f][1]));
            mhi = fmaxf(mhi, fmaxf(S[f][2], S[f][3]));
        }
        mlo = fmaxf(mlo, __shfl_xor_sync(0xffffffffu, mlo, 1));
        mlo = fmaxf(mlo, __shfl_xor_sync(0xffffffffu, mlo, 2));
        mhi = fmaxf(mhi, __shfl_xor_sync(0xffffffffu, mhi, 1));
        mhi = fmaxf(mhi, __shfl_xor_sync(0xffffffffu, mhi, 2));
        float mnl = fmaxf(m_l, mlo), mnh = fmaxf(m_h, mhi);
        float scl = ex2f(m_l - mnl), sch = ex2f(m_h - mnh);
        m_l = mnl; m_h = mnh;
        float slo = 0.f, shi = 0.f;
        #pragma unroll
        for (int f = 0; f < 8; f++) {
            float p0 = ex2f(S[f][0] - mnl);
            float p1 = ex2f(S[f][1] - mnl);
            float p2 = ex2f(S[f][2] - mnh);
            float p3 = ex2f(S[f][3] - mnh);
            slo += p0 + p1;
            shi += p2 + p3;
            S[f][0] = p0; S[f][1] = p1; S[f][2] = p2; S[f][3] = p3;
        }
        slo += __shfl_xor_sync(0xffffffffu, slo, 1);
        slo += __shfl_xor_sync(0xffffffffu, slo, 2);
        shi += __shfl_xor_sync(0xffffffffu, shi, 1);
        shi += __shfl_xor_sync(0xffffffffu, shi, 2);
        l_l = l_l * scl + slo;
        l_h = l_h * sch + shi;

        if (!__all_sync(0xffffffffu, (scl == 1.f) && (sch == 1.f))) {
            #pragma unroll
            for (int cf = 0; cf < 16; cf++) {
                O[cf][0] *= scl; O[cf][1] *= scl;
                O[cf][2] *= sch; O[cf][3] *= sch;
            }
        }
        #pragma unroll
        for (int kc = 0; kc < 4; kc++) {
            uint32 a[4];
            a[0] = pack_h2(S[2 * kc][0],     S[2 * kc][1]);
            a[1] = pack_h2(S[2 * kc][2],     S[2 * kc][3]);
            a[2] = pack_h2(S[2 * kc + 1][0], S[2 * kc + 1][1]);
            a[3] = pack_h2(S[2 * kc + 1][2], S[2 * kc + 1][3]);
            const uint2* vr = cV2 + (4 * kc + kk) * 132 + g;
            #pragma unroll
            for (int cf = 0; cf < 16; cf++) {
                uint2 v2 = vr[8 * cf];
                mma_fp16(O[cf], a, v2.x, v2.y);
            }
        }
        if (nt < 15) {
            CP_WAIT0();
            __syncthreads();
        }
    }

    __syncthreads();
    float il = 1.0f / l_l, ih = 1.0f / l_h;
    float* sO = sm;
    #pragma unroll
    for (int cf = 0; cf < 16; cf++) {
        int col = 8 * cf + 2 * kk;
        *(float2*)&sO[rl * 130 + col] = make_float2(O[cf][0] * il, O[cf][1] * il);
        *(float2*)&sO[rh * 130 + col] = make_float2(O[cf][2] * ih, O[cf][3] * ih);
    }
    __syncthreads();
    {
        int m = tid & 63;
        int c0 = (tid >> 6) * 64;
        #pragma unroll 4
        for (int k2 = 0; k2 < 64; k2++) {
            int c = c0 + k2;
            size_t a = ((size_t)b * 512 + h * 128 + c) * 1024 + mg + m;
            out[a] = sO[m * 130 + c] + x[a];
        }
    }
}

// ---------------- launch ----------------
extern "C" void kernel_launch(void* const* d_in, const int* in_sizes, int n_in,
                              void* d_out, int out_size)
{
    const float* x     = (const float*)d_in[0];
    const float* Wq    = (const float*)d_in[1];
    const float* bq    = (const float*)d_in[2];
    const float* qg    = (const float*)d_in[3];
    const float* qb    = (const float*)d_in[4];
    const float* qm    = (const float*)d_in[5];
    const float* qv    = (const float*)d_in[6];
    const float* Wk    = (const float*)d_in[7];
    const float* bk    = (const float*)d_in[8];
    const float* kg    = (const float*)d_in[9];
    const float* kb    = (const float*)d_in[10];
    const float* km    = (const float*)d_in[11];
    const float* kv    = (const float*)d_in[12];
    const float* Wv    = (const float*)d_in[13];
    const float* bv    = (const float*)d_in[14];
    const float* vg    = (const float*)d_in[15];
    const float* vb    = (const float*)d_in[16];
    const float* vm    = (const float*)d_in[17];
    const float* vvar  = (const float*)d_in[18];
    const float* rel_h = (const float*)d_in[19];
    const float* rel_w = (const float*)d_in[20];
    float* out = (float*)d_out;

    cudaFuncSetAttribute(attn_kernel, cudaFuncAttributeMaxDynamicSharedMemorySize,
                         ATTN_SMEM_FLOATS * (int)sizeof(float));
    cudaFuncSetAttribute(proj_kernel, cudaFuncAttributeMaxDynamicSharedMemorySize,
                         PROJ_SMEM_BYTES);

    fold_kernel<<<768, 256>>>(Wq, bq, qg, qb, qm, qv,
                              Wk, bk, kg, kb, km, kv,
                              Wv, bv, vg, vb, vm, vvar);
    xsplit_kernel<<<dim3(256, 16), 256>>>(x);
    proj_kernel<<<dim3(8, 6, 16), 256, PROJ_SMEM_BYTES>>>();
    prep_kernel<<<dim3(16, 4, 16), 256>>>();
    attn_kernel<<<dim3(16, 4, 16), 128, ATTN_SMEM_FLOATS * sizeof(float)>>>(x, rel_h, rel_w, out);
}